// round 8
// baseline (speedup 1.0000x reference)
#include <cuda_runtime.h>
#include <cuda_bf16.h>
#include <math.h>
#include <stdint.h>

#define B_    128
#define T_    64
#define V_    10000
#define NI_   512
#define ENH   640
#define DNH   1024
#define NZ_   128
#define ND_   8
#define K_    1024
#define D_    160
#define LOGITS_ELEMS (B_ * T_ * V_)

// ---------------- scratch ----------------
__device__ __align__(256) float g_we   [B_ * T_ * NI_];
__device__ __align__(256) float g_xgf  [B_ * T_ * 4 * ENH];
__device__ __align__(256) float g_xgb  [B_ * T_ * 4 * ENH];
__device__ __align__(256) float g_encA [4 * B_ * ENH];   // hfA, cf, hbA, cb
__device__ __align__(256) float g_hfB  [B_ * ENH];
__device__ __align__(256) float g_hbB  [B_ * ENH];
__device__ __align__(256) float g_fhs  [B_ * 2 * ENH];
__device__ __align__(256) float g_muvar[B_ * 2 * NZ_];
__device__ __align__(256) float g_root [B_ * DNH];
__device__ __align__(256) int   g_inds [B_ * ND_];
__device__ __align__(256) float g_q    [B_ * ND_ * D_];
__device__ __align__(256) float g_vqp  [B_ * ND_];
__device__ __align__(256) float g_suffix[B_ * NI_];
__device__ __align__(256) float g_demb [B_ * T_ * NI_];
__device__ __align__(256) float g_xgd  [B_ * T_ * 4 * DNH];
__device__ __align__(256) float g_hd0  [B_ * DNH];
__device__ __align__(256) float g_cd   [B_ * DNH];
__device__ __align__(256) float g_decout[B_ * T_ * DNH];

// ---------------- fp32 SGEMM (encoder path; exact numerics kept) ----------------
template<int BM, int BN, int BK, int TM, int TN>
__global__ __launch_bounds__((BM/TM)*(BN/TN))
void gemm_k(const float* __restrict__ A, int lda,
            const float* __restrict__ W, int ldw,
            const float* __restrict__ bias,
            const float* __restrict__ Cadd, int ldca,
            float* __restrict__ C, int ldc,
            int N, int K)
{
    constexpr int NT = (BM/TM)*(BN/TN);
    __shared__ __align__(16) float As[BK][BM + 4];
    __shared__ __align__(16) float Ws[BK][BN + 4];
    const int tid  = threadIdx.x;
    const int row0 = blockIdx.y * BM;
    const int col0 = blockIdx.x * BN;
    const int tr   = tid / (BN / TN);
    const int tc   = tid % (BN / TN);
    float acc[TM][TN];
#pragma unroll
    for (int i = 0; i < TM; i++)
#pragma unroll
        for (int j = 0; j < TN; j++) acc[i][j] = 0.f;
    for (int k0 = 0; k0 < K; k0 += BK) {
#pragma unroll
        for (int idx = tid * 4; idx < BM * BK; idx += NT * 4) {
            int m = idx / BK, kk = idx % BK;
            float4 v = *reinterpret_cast<const float4*>(A + (size_t)(row0 + m) * lda + (k0 + kk));
            As[kk+0][m]=v.x; As[kk+1][m]=v.y; As[kk+2][m]=v.z; As[kk+3][m]=v.w;
        }
#pragma unroll
        for (int idx = tid * 4; idx < BN * BK; idx += NT * 4) {
            int n = idx / BK, kk = idx % BK;
            float4 v = make_float4(0.f,0.f,0.f,0.f);
            if (col0 + n < N)
                v = *reinterpret_cast<const float4*>(W + (size_t)(col0 + n) * ldw + (k0 + kk));
            Ws[kk+0][n]=v.x; Ws[kk+1][n]=v.y; Ws[kk+2][n]=v.z; Ws[kk+3][n]=v.w;
        }
        __syncthreads();
#pragma unroll
        for (int kk = 0; kk < BK; kk++) {
            float ra[TM], rb[TN];
#pragma unroll
            for (int i = 0; i < TM; i += 4) {
                float4 v = *reinterpret_cast<const float4*>(&As[kk][tr*TM+i]);
                ra[i]=v.x; ra[i+1]=v.y; ra[i+2]=v.z; ra[i+3]=v.w;
            }
#pragma unroll
            for (int j = 0; j < TN; j += 4) {
                float4 v = *reinterpret_cast<const float4*>(&Ws[kk][tc*TN+j]);
                rb[j]=v.x; rb[j+1]=v.y; rb[j+2]=v.z; rb[j+3]=v.w;
            }
#pragma unroll
            for (int i = 0; i < TM; i++)
#pragma unroll
                for (int j = 0; j < TN; j++)
                    acc[i][j] = fmaf(ra[i], rb[j], acc[i][j]);
        }
        __syncthreads();
    }
#pragma unroll
    for (int i = 0; i < TM; i++) {
        int m = row0 + tr*TM + i;
#pragma unroll
        for (int j = 0; j < TN; j++) {
            int n = col0 + tc*TN + j;
            if (n < N) {
                float v = acc[i][j];
                if (bias) v += bias[n];
                if (Cadd) v += Cadd[(size_t)m * ldca + n];
                C[(size_t)m * ldc + n] = v;
            }
        }
    }
}

// ---------------- split-bf16 tensor-core GEMM: C = A @ W^T (+bias) ----------------
// A [M,K] f32 row-major, W [N,K] f32 row-major. M%128==0, K%32==0, N guarded.
#define MMA_BF16(CC, AA, BB)                                                     \
    asm volatile("mma.sync.aligned.m16n8k16.row.col.f32.bf16.bf16.f32 "          \
        "{%0,%1,%2,%3}, {%4,%5,%6,%7}, {%8,%9}, {%0,%1,%2,%3};"                  \
        : "+f"(CC[0]), "+f"(CC[1]), "+f"(CC[2]), "+f"(CC[3])                     \
        : "r"(AA[0]), "r"(AA[1]), "r"(AA[2]), "r"(AA[3]), "r"(BB[0]), "r"(BB[1]))

__global__ __launch_bounds__(256)
void hgemm_split(const float* __restrict__ A, int lda,
                 const float* __restrict__ W, int ldw,
                 const float* __restrict__ bias,
                 float* __restrict__ C, int ldc, int N, int K)
{
    __shared__ __align__(16) __nv_bfloat16 Ah[128][40];
    __shared__ __align__(16) __nv_bfloat16 Al[128][40];
    __shared__ __align__(16) __nv_bfloat16 Wh[128][40];
    __shared__ __align__(16) __nv_bfloat16 Wl[128][40];
    const int tid  = threadIdx.x;
    const int warp = tid >> 5, lane = tid & 31;
    const int wm = warp >> 2, wn = warp & 3;      // 2 x 4 warp grid; warp tile 64x32
    const int row0 = blockIdx.y * 128, col0 = blockIdx.x * 128;
    const int g = lane >> 2, q = lane & 3;

    float acc[4][4][4];
#pragma unroll
    for (int a = 0; a < 4; a++)
#pragma unroll
        for (int b = 0; b < 4; b++)
#pragma unroll
            for (int c = 0; c < 4; c++) acc[a][b][c] = 0.f;

    for (int k0 = 0; k0 < K; k0 += 32) {
        __syncthreads();
        for (int i = tid; i < 128 * 8; i += 256) {
            int r = i >> 3, c4 = (i & 7) << 2;
            float4 va = *reinterpret_cast<const float4*>(&A[(size_t)(row0 + r) * lda + k0 + c4]);
            float xa[4] = {va.x, va.y, va.z, va.w};
#pragma unroll
            for (int e = 0; e < 4; e++) {
                __nv_bfloat16 h = __float2bfloat16_rn(xa[e]);
                Ah[r][c4+e] = h;
                Al[r][c4+e] = __float2bfloat16_rn(xa[e] - __bfloat162float(h));
            }
            float4 vw = make_float4(0.f,0.f,0.f,0.f);
            if (col0 + r < N)
                vw = *reinterpret_cast<const float4*>(&W[(size_t)(col0 + r) * ldw + k0 + c4]);
            float xw[4] = {vw.x, vw.y, vw.z, vw.w};
#pragma unroll
            for (int e = 0; e < 4; e++) {
                __nv_bfloat16 h = __float2bfloat16_rn(xw[e]);
                Wh[r][c4+e] = h;
                Wl[r][c4+e] = __float2bfloat16_rn(xw[e] - __bfloat162float(h));
            }
        }
        __syncthreads();
#pragma unroll
        for (int ks = 0; ks < 32; ks += 16) {
            uint32_t ah[4][4], al[4][4], bh[4][2], bl[4][2];
#pragma unroll
            for (int mi = 0; mi < 4; mi++) {
                int r = wm*64 + mi*16 + g;
                ah[mi][0] = *reinterpret_cast<const uint32_t*>(&Ah[r  ][ks + 2*q    ]);
                ah[mi][1] = *reinterpret_cast<const uint32_t*>(&Ah[r+8][ks + 2*q    ]);
                ah[mi][2] = *reinterpret_cast<const uint32_t*>(&Ah[r  ][ks + 2*q + 8]);
                ah[mi][3] = *reinterpret_cast<const uint32_t*>(&Ah[r+8][ks + 2*q + 8]);
                al[mi][0] = *reinterpret_cast<const uint32_t*>(&Al[r  ][ks + 2*q    ]);
                al[mi][1] = *reinterpret_cast<const uint32_t*>(&Al[r+8][ks + 2*q    ]);
                al[mi][2] = *reinterpret_cast<const uint32_t*>(&Al[r  ][ks + 2*q + 8]);
                al[mi][3] = *reinterpret_cast<const uint32_t*>(&Al[r+8][ks + 2*q + 8]);
            }
#pragma unroll
            for (int ni = 0; ni < 4; ni++) {
                int c = wn*32 + ni*8 + g;
                bh[ni][0] = *reinterpret_cast<const uint32_t*>(&Wh[c][ks + 2*q    ]);
                bh[ni][1] = *reinterpret_cast<const uint32_t*>(&Wh[c][ks + 2*q + 8]);
                bl[ni][0] = *reinterpret_cast<const uint32_t*>(&Wl[c][ks + 2*q    ]);
                bl[ni][1] = *reinterpret_cast<const uint32_t*>(&Wl[c][ks + 2*q + 8]);
            }
#pragma unroll
            for (int mi = 0; mi < 4; mi++)
#pragma unroll
                for (int ni = 0; ni < 4; ni++) {
                    MMA_BF16(acc[mi][ni], ah[mi], bh[ni]);
                    MMA_BF16(acc[mi][ni], ah[mi], bl[ni]);
                    MMA_BF16(acc[mi][ni], al[mi], bh[ni]);
                }
        }
    }
#pragma unroll
    for (int mi = 0; mi < 4; mi++) {
        int r = row0 + wm*64 + mi*16 + g;
#pragma unroll
        for (int ni = 0; ni < 4; ni++) {
            int c = col0 + wn*32 + ni*8 + 2*q;
            float b0 = 0.f, b1 = 0.f;
            if (bias) {
                if (c < N)     b0 = bias[c];
                if (c + 1 < N) b1 = bias[c+1];
            }
            if (c < N) {
                C[(size_t)r * ldc + c]     = acc[mi][ni][0] + b0;
                C[(size_t)(r+8) * ldc + c] = acc[mi][ni][2] + b0;
            }
            if (c + 1 < N) {
                C[(size_t)r * ldc + c + 1]     = acc[mi][ni][1] + b1;
                C[(size_t)(r+8) * ldc + c + 1] = acc[mi][ni][3] + b1;
            }
        }
    }
}

// ---------------- fused LSTM step ----------------
// Block: 256 threads = 8 warps = 4 j-columns x 2 gate-pairs; lane owns 4 batch rows.
// grid.x = H/4 j-blocks; grid.y = 1 (dec) or 2 (enc fwd+bwd).
__device__ __forceinline__ float sigf(float x) { return 1.f / (1.f + expf(-x)); }

template<int H>
__global__ __launch_bounds__(256)
void lstm_step(const float* __restrict__ xg0, const float* __restrict__ xg1, int rsXG,
               const float* __restrict__ W0,  const float* __restrict__ W1,
               const float* __restrict__ h0in, const float* __restrict__ h1in, int rsHin,
               float* __restrict__ c0p, float* __restrict__ c1p,
               float* __restrict__ h0out, float* __restrict__ h1out, int rsHout)
{
    const float* xg;  const float* Whh; const float* hin; float* cp; float* hout;
    if (blockIdx.y == 0) { xg = xg0; Whh = W0; hin = h0in; cp = c0p; hout = h0out; }
    else                 { xg = xg1; Whh = W1; hin = h1in; cp = c1p; hout = h1out; }

    __shared__ __align__(16) float hs[32][132];      // [k][b]
    __shared__ __align__(16) float ws[4][4][32];     // [gate][j][k]
    __shared__ float sg[4][4][128];                  // [gate][j][b]

    const int tid  = threadIdx.x;
    const int lane = tid & 31, w = tid >> 5;
    const int jw = w >> 1, gp = w & 1;               // j within block, gate pair
    const int g0 = 2 * gp, g1 = 2 * gp + 1;
    const int jb0 = blockIdx.x * 4;

    float a0[4] = {0.f,0.f,0.f,0.f};
    float a1[4] = {0.f,0.f,0.f,0.f};

    for (int k0 = 0; k0 < H; k0 += 32) {
        __syncthreads();
        for (int i = tid; i < 128 * 8; i += 256) {
            int b = i >> 3, c4 = (i & 7) << 2;
            float4 v = *reinterpret_cast<const float4*>(&hin[(size_t)b * rsHin + k0 + c4]);
            hs[c4+0][b]=v.x; hs[c4+1][b]=v.y; hs[c4+2][b]=v.z; hs[c4+3][b]=v.w;
        }
        for (int i = tid; i < 4 * 4 * 8; i += 256) {
            int gg = i >> 5, rem = i & 31;
            int jj = rem >> 3, c4 = (rem & 7) << 2;
            float4 v = *reinterpret_cast<const float4*>(
                &Whh[(size_t)(gg * H + jb0 + jj) * H + k0 + c4]);
            ws[gg][jj][c4+0]=v.x; ws[gg][jj][c4+1]=v.y; ws[gg][jj][c4+2]=v.z; ws[gg][jj][c4+3]=v.w;
        }
        __syncthreads();
#pragma unroll
        for (int kk = 0; kk < 32; kk++) {
            float4 hv = *reinterpret_cast<const float4*>(&hs[kk][lane * 4]);
            float w0v = ws[g0][jw][kk], w1v = ws[g1][jw][kk];
            a0[0] = fmaf(hv.x, w0v, a0[0]); a1[0] = fmaf(hv.x, w1v, a1[0]);
            a0[1] = fmaf(hv.y, w0v, a0[1]); a1[1] = fmaf(hv.y, w1v, a1[1]);
            a0[2] = fmaf(hv.z, w0v, a0[2]); a1[2] = fmaf(hv.z, w1v, a1[2]);
            a0[3] = fmaf(hv.w, w0v, a0[3]); a1[3] = fmaf(hv.w, w1v, a1[3]);
        }
    }
#pragma unroll
    for (int e = 0; e < 4; e++) {
        sg[g0][jw][lane*4 + e] = a0[e];
        sg[g1][jw][lane*4 + e] = a1[e];
    }
    __syncthreads();
    for (int p = tid; p < 4 * 128; p += 256) {
        int j = p >> 7, b = p & 127;
        int jg = jb0 + j;
        const float* xr = xg + (size_t)b * rsXG;
        float gi = sg[0][j][b] + xr[0*H + jg];
        float gf = sg[1][j][b] + xr[1*H + jg];
        float gc = sg[2][j][b] + xr[2*H + jg];
        float go = sg[3][j][b] + xr[3*H + jg];
        size_t ci = (size_t)b * H + jg;
        float cc = sigf(gf) * cp[ci] + sigf(gi) * tanhf(gc);
        cp[ci] = cc;
        hout[(size_t)b * rsHout + jg] = sigf(go) * tanhf(cc);
    }
}

// ---------------- elementwise / small kernels ----------------
__global__ void embed_kernel(const int* __restrict__ x, const float* __restrict__ emb,
                             float* __restrict__ out)
{
    size_t idx = (size_t)blockIdx.x * blockDim.x + threadIdx.x;
    if (idx >= (size_t)B_ * T_ * NI_) return;
    int i = (int)(idx % NI_), bt = (int)(idx / NI_);
    out[idx] = emb[(size_t)x[bt] * NI_ + i];
}

__global__ void demb_kernel(const int* __restrict__ x, const float* __restrict__ emb,
                            const float* __restrict__ suffix, float* __restrict__ out)
{
    size_t idx = (size_t)blockIdx.x * blockDim.x + threadIdx.x;
    if (idx >= (size_t)B_ * T_ * NI_) return;
    int i = (int)(idx % NI_), bt = (int)(idx / NI_);
    int b = bt / T_;
    out[idx] = emb[(size_t)x[bt] * NI_ + i] + suffix[(size_t)b * NI_ + i];
}

__global__ void concat_fhs(const float* __restrict__ hf, const float* __restrict__ hb,
                           float* __restrict__ fhs)
{
    int idx = blockIdx.x * blockDim.x + threadIdx.x;
    if (idx >= B_ * 2 * ENH) return;
    int b = idx / (2 * ENH), j = idx % (2 * ENH);
    fhs[idx] = (j < ENH) ? hf[(size_t)b * ENH + j] : hb[(size_t)b * ENH + (j - ENH)];
}

__global__ void kl_kernel(const float* __restrict__ muvar, float* __restrict__ out_kl)
{
    int b = threadIdx.x;
    if (b >= B_) return;
    float s = 0.f;
    const float* row = muvar + (size_t)b * 2 * NZ_;
    for (int j = 0; j < NZ_; j++) {
        float mu = row[j], lv = row[NZ_ + j];
        s += mu * mu + expf(lv) - lv - 1.f;
    }
    out_kl[b] = 0.5f * s;
}

__global__ void dec_init(const float* __restrict__ root, float* __restrict__ h0,
                         float* __restrict__ c0)
{
    int idx = blockIdx.x * blockDim.x + threadIdx.x;
    if (idx >= B_ * DNH) return;
    float r = root[idx];
    h0[idx] = tanhf(r);
    c0[idx] = r;
}

__global__ void vq_kernel(const float* __restrict__ fhs, const float* __restrict__ cb,
                          int* __restrict__ inds, float* __restrict__ q,
                          float* __restrict__ vqp)
{
    const int bn = blockIdx.x;
    const int b = bn / ND_, n = bn % ND_;
    __shared__ __align__(16) float lat[D_];
    __shared__ float svals[256];
    __shared__ int   sidx[256];
    const float* latg = fhs + (size_t)b * (ND_ * D_) + (size_t)n * D_;
    for (int d = threadIdx.x; d < D_; d += 256) lat[d] = latg[d];
    __syncthreads();
    float best = INFINITY; int bidx = K_;
    const float* cbn = cb + (size_t)n * K_ * D_;
    for (int k = threadIdx.x; k < K_; k += 256) {
        const float4* ck = reinterpret_cast<const float4*>(cbn + (size_t)k * D_);
        float t1 = 0.f, t2 = 0.f;
#pragma unroll
        for (int d4 = 0; d4 < D_ / 4; d4++) {
            float4 cv = ck[d4];
            const float4 lv = *reinterpret_cast<const float4*>(&lat[d4 * 4]);
            t1 = fmaf(cv.x, cv.x, t1); t2 = fmaf(cv.x, lv.x, t2);
            t1 = fmaf(cv.y, cv.y, t1); t2 = fmaf(cv.y, lv.y, t2);
            t1 = fmaf(cv.z, cv.z, t1); t2 = fmaf(cv.z, lv.z, t2);
            t1 = fmaf(cv.w, cv.w, t1); t2 = fmaf(cv.w, lv.w, t2);
        }
        float dist = t1 - 2.f * t2;
        if (dist < best || (dist == best && k < bidx)) { best = dist; bidx = k; }
    }
    svals[threadIdx.x] = best; sidx[threadIdx.x] = bidx;
    __syncthreads();
    for (int off = 128; off > 0; off >>= 1) {
        if (threadIdx.x < off) {
            float v = svals[threadIdx.x + off]; int i2 = sidx[threadIdx.x + off];
            if (v < svals[threadIdx.x] || (v == svals[threadIdx.x] && i2 < sidx[threadIdx.x])) {
                svals[threadIdx.x] = v; sidx[threadIdx.x] = i2;
            }
        }
        __syncthreads();
    }
    const int kmin = sidx[0];
    if (threadIdx.x == 0) inds[bn] = kmin;
    __syncthreads();
    const float* ck = cbn + (size_t)kmin * D_;
    float part = 0.f;
    for (int d = threadIdx.x; d < D_; d += 256) {
        float qv = ck[d], lv = lat[d];
        float diff = qv - lv;
        q[(size_t)bn * D_ + d] = lv + diff;
        part += diff * diff;
    }
    svals[threadIdx.x] = part;
    __syncthreads();
    for (int off = 128; off > 0; off >>= 1) {
        if (threadIdx.x < off) svals[threadIdx.x] += svals[threadIdx.x + off];
        __syncthreads();
    }
    if (threadIdx.x == 0) vqp[bn] = svals[0] / (float)D_;
}

__global__ void vq_finish(const float* __restrict__ vqp, const int* __restrict__ inds,
                          float* __restrict__ out_vq, float* __restrict__ out_inds)
{
    int b = threadIdx.x;
    if (b >= B_) return;
    float s = 0.f;
#pragma unroll
    for (int n = 0; n < ND_; n++) s += vqp[b * ND_ + n];
    out_vq[b] = 1.25f * s;
#pragma unroll
    for (int n = 0; n < ND_; n++)
        out_inds[b * ND_ + n] = (float)inds[b * ND_ + n];
}

// ---------------- launch helpers ----------------
static inline void gemm_big(const float* A, int lda, const float* W, int ldw,
                            const float* bias, float* C, int ldc, int M, int N, int K)
{
    dim3 grid((N + 127) / 128, M / 128);
    gemm_k<128, 128, 16, 8, 8><<<grid, 256>>>(A, lda, W, ldw, bias, nullptr, 0, C, ldc, N, K);
}
static inline void gemm_small(const float* A, int lda, const float* W, int ldw,
                              const float* bias, float* C, int ldc, int M, int N, int K)
{
    dim3 grid((N + 63) / 64, M / 32);
    gemm_k<32, 64, 16, 4, 4><<<grid, 128>>>(A, lda, W, ldw, bias, nullptr, 0, C, ldc, N, K);
}
static inline void gemm_tc(const float* A, int lda, const float* W, int ldw,
                           const float* bias, float* C, int ldc, int M, int N, int K)
{
    dim3 grid((N + 127) / 128, M / 128);
    hgemm_split<<<grid, 256>>>(A, lda, W, ldw, bias, C, ldc, N, K);
}

extern "C" void kernel_launch(void* const* d_in, const int* in_sizes, int n_in,
                              void* d_out, int out_size)
{
    (void)in_sizes; (void)n_in; (void)out_size;
    const int*   x         = (const int*)  d_in[0];
    const float* enc_embed = (const float*)d_in[1];
    const float* enc_Wih_f = (const float*)d_in[2];
    const float* enc_Whh_f = (const float*)d_in[3];
    const float* enc_b_f   = (const float*)d_in[4];
    const float* enc_Wih_b = (const float*)d_in[5];
    const float* enc_Whh_b = (const float*)d_in[6];
    const float* enc_b_b   = (const float*)d_in[7];
    const float* enc_lin   = (const float*)d_in[8];
    const float* z2dec_W   = (const float*)d_in[9];
    const float* z2dec_b   = (const float*)d_in[10];
    const float* codebooks = (const float*)d_in[11];
    const float* suffix_W  = (const float*)d_in[12];
    const float* dec_embed = (const float*)d_in[13];
    const float* dec_Wih   = (const float*)d_in[14];
    const float* dec_Whh   = (const float*)d_in[15];
    const float* dec_b     = (const float*)d_in[16];
    const float* pred_W    = (const float*)d_in[17];

    float* out      = (float*)d_out;
    float* out_log  = out;
    float* out_vq   = out + (size_t)LOGITS_ELEMS;
    float* out_kl   = out_vq + B_;
    float* out_inds = out_kl + B_;

    float *we,*xgf,*xgb,*encA,*hfB,*hbB,*fhs,*muvar,*root,*q,*vqp,*suffix;
    float *demb,*xgd,*hd0,*cd,*decout;
    int* inds;
    cudaGetSymbolAddress((void**)&we,    g_we);
    cudaGetSymbolAddress((void**)&xgf,   g_xgf);
    cudaGetSymbolAddress((void**)&xgb,   g_xgb);
    cudaGetSymbolAddress((void**)&encA,  g_encA);
    cudaGetSymbolAddress((void**)&hfB,   g_hfB);
    cudaGetSymbolAddress((void**)&hbB,   g_hbB);
    cudaGetSymbolAddress((void**)&fhs,   g_fhs);
    cudaGetSymbolAddress((void**)&muvar, g_muvar);
    cudaGetSymbolAddress((void**)&root,  g_root);
    cudaGetSymbolAddress((void**)&inds,  g_inds);
    cudaGetSymbolAddress((void**)&q,     g_q);
    cudaGetSymbolAddress((void**)&vqp,   g_vqp);
    cudaGetSymbolAddress((void**)&suffix,g_suffix);
    cudaGetSymbolAddress((void**)&demb,  g_demb);
    cudaGetSymbolAddress((void**)&xgd,   g_xgd);
    cudaGetSymbolAddress((void**)&hd0,   g_hd0);
    cudaGetSymbolAddress((void**)&cd,    g_cd);
    cudaGetSymbolAddress((void**)&decout,g_decout);

    float* hfA = encA;
    float* cf  = encA + (size_t)B_ * ENH;
    float* hbA = encA + (size_t)2 * B_ * ENH;
    float* cb  = encA + (size_t)3 * B_ * ENH;

    const int EW = 256;

    // encoder embedding + input-gate GEMMs (fp32 exact)
    embed_kernel<<<(B_ * T_ * NI_ + EW - 1) / EW, EW>>>(x, enc_embed, we);
    gemm_big(we, NI_, enc_Wih_f, NI_, enc_b_f, xgf, 4 * ENH, B_ * T_, 4 * ENH, NI_);
    gemm_big(we, NI_, enc_Wih_b, NI_, enc_b_b, xgb, 4 * ENH, B_ * T_, 4 * ENH, NI_);
    cudaMemsetAsync(encA, 0, sizeof(float) * 4 * B_ * ENH, 0);

    // encoder recurrence: fwd + bwd fused, h double-buffered
    {
        dim3 grid(ENH / 4, 2);
        for (int s = 0; s < T_; s++) {
            const float* hf_in = (s & 1) ? hfB : hfA;
            float*       hf_out= (s & 1) ? hfA : hfB;
            const float* hb_in = (s & 1) ? hbB : hbA;
            float*       hb_out= (s & 1) ? hbA : hbB;
            lstm_step<ENH><<<grid, 256>>>(
                xgf + (size_t)s * 4 * ENH, xgb + (size_t)(T_ - 1 - s) * 4 * ENH, T_ * 4 * ENH,
                enc_Whh_f, enc_Whh_b,
                hf_in, hb_in, ENH,
                cf, cb,
                hf_out, hb_out, ENH);
        }
    }
    // after 64 steps (even count), final h is in the A buffers
    concat_fhs<<<(B_ * 2 * ENH + EW - 1) / EW, EW>>>(hfA, hbA, fhs);

    gemm_small(fhs, 2 * ENH, enc_lin, 2 * ENH, nullptr, muvar, 2 * NZ_, B_, 2 * NZ_, 2 * ENH);
    kl_kernel<<<1, B_>>>(muvar, out_kl);
    gemm_small(muvar, 2 * NZ_, z2dec_W, NZ_, z2dec_b, root, DNH, B_, DNH, NZ_);

    vq_kernel<<<B_ * ND_, 256>>>(fhs, codebooks, inds, q, vqp);
    vq_finish<<<1, B_>>>(vqp, inds, out_vq, out_inds);

    gemm_small(q, ND_ * D_, suffix_W, ND_ * D_, nullptr, suffix, NI_, B_, NI_, ND_ * D_);
    demb_kernel<<<(B_ * T_ * NI_ + EW - 1) / EW, EW>>>(x, dec_embed, suffix, demb);

    // decoder input gates: tensor-core split-bf16
    gemm_tc(demb, NI_, dec_Wih, NI_, dec_b, xgd, 4 * DNH, B_ * T_, 4 * DNH, NI_);

    dec_init<<<(B_ * DNH + EW - 1) / EW, EW>>>(root, hd0, cd);

    // decoder recurrence: fused step, h written straight into decout slices
    {
        dim3 grid(DNH / 4, 1);
        for (int s = 0; s < T_; s++) {
            const float* hin = (s == 0) ? hd0 : (decout + (size_t)(s - 1) * DNH);
            int rsHin        = (s == 0) ? DNH : (T_ * DNH);
            const float* xgs = xgd + (size_t)s * 4 * DNH;
            lstm_step<DNH><<<grid, 256>>>(
                xgs, xgs, T_ * 4 * DNH,
                dec_Whh, dec_Whh,
                hin, hin, rsHin,
                cd, cd,
                decout + (size_t)s * DNH, decout + (size_t)s * DNH, T_ * DNH);
        }
    }

    // logits: tensor-core split-bf16
    gemm_tc(decout, DNH, pred_W, DNH, nullptr, out_log, V_, B_ * T_, V_, DNH);
}

// round 12
// speedup vs baseline: 1.4296x; 1.4296x over previous
#include <cuda_runtime.h>
#include <cuda_bf16.h>
#include <math.h>
#include <stdint.h>

#define B_    128
#define T_    64
#define V_    10000
#define NI_   512
#define ENH   640
#define DNH   1024
#define NZ_   128
#define ND_   8
#define K_    1024
#define D_    160
#define LOGITS_ELEMS (B_ * T_ * V_)

// ---------------- scratch ----------------
__device__ __align__(256) float g_we   [B_ * T_ * NI_];
__device__ __align__(256) float g_xgf  [B_ * T_ * 4 * ENH];
__device__ __align__(256) float g_xgb  [B_ * T_ * 4 * ENH];
__device__ __align__(256) float g_encA [4 * B_ * ENH];   // hfA, cf, hbA, cb
__device__ __align__(256) float g_hfB  [B_ * ENH];
__device__ __align__(256) float g_hbB  [B_ * ENH];
__device__ __align__(256) float g_fhs  [B_ * 2 * ENH];
__device__ __align__(256) float g_muvar[B_ * 2 * NZ_];
__device__ __align__(256) float g_root [B_ * DNH];
__device__ __align__(256) int   g_inds [B_ * ND_];
__device__ __align__(256) float g_q    [B_ * ND_ * D_];
__device__ __align__(256) float g_vqp  [B_ * ND_];
__device__ __align__(256) float g_suffix[B_ * NI_];
__device__ __align__(256) float g_demb [B_ * T_ * NI_];
__device__ __align__(256) float g_xgd  [B_ * T_ * 4 * DNH];
__device__ __align__(256) float g_hd0  [B_ * DNH];
__device__ __align__(256) float g_cd   [B_ * DNH];
__device__ __align__(256) float g_decout[B_ * T_ * DNH];
// permuted (gate-interleaved) weights/biases
__device__ __align__(256) float g_WfP  [4 * ENH * NI_];
__device__ __align__(256) float g_WbP  [4 * ENH * NI_];
__device__ __align__(256) float g_WhfP [4 * ENH * ENH];
__device__ __align__(256) float g_WhbP [4 * ENH * ENH];
__device__ __align__(256) float g_WdP  [4 * DNH * NI_];
__device__ __align__(256) float g_WhdP [4 * DNH * DNH];
__device__ __align__(256) float g_bfP  [4 * ENH];
__device__ __align__(256) float g_bbP  [4 * ENH];
__device__ __align__(256) float g_bdP  [4 * DNH];

// ---------------- weight permute: row g*H+j -> j*4+g ----------------
__global__ void perm_w(const float* __restrict__ W, float* __restrict__ Wp, int H, int K)
{
    size_t idx = (size_t)blockIdx.x * blockDim.x + threadIdx.x;
    if (idx >= (size_t)4 * H * K) return;
    int k = (int)(idx % K);
    int r = (int)(idx / K);
    int g = r / H, j = r % H;
    Wp[((size_t)j * 4 + g) * K + k] = W[idx];
}
__global__ void perm_b(const float* __restrict__ b, float* __restrict__ bp, int H)
{
    int idx = blockIdx.x * blockDim.x + threadIdx.x;
    if (idx >= 4 * H) return;
    int g = idx / H, j = idx % H;
    bp[j * 4 + g] = b[idx];
}

// ---------------- fp32 SGEMM ----------------
template<int BM, int BN, int BK, int TM, int TN>
__global__ __launch_bounds__((BM/TM)*(BN/TN))
void gemm_k(const float* __restrict__ A, int lda,
            const float* __restrict__ W, int ldw,
            const float* __restrict__ bias,
            float* __restrict__ C, int ldc,
            int N, int K)
{
    constexpr int NT = (BM/TM)*(BN/TN);
    __shared__ __align__(16) float As[BK][BM + 4];
    __shared__ __align__(16) float Ws[BK][BN + 4];
    const int tid  = threadIdx.x;
    const int row0 = blockIdx.y * BM;
    const int col0 = blockIdx.x * BN;
    const int tr   = tid / (BN / TN);
    const int tc   = tid % (BN / TN);
    float acc[TM][TN];
#pragma unroll
    for (int i = 0; i < TM; i++)
#pragma unroll
        for (int j = 0; j < TN; j++) acc[i][j] = 0.f;
    for (int k0 = 0; k0 < K; k0 += BK) {
#pragma unroll
        for (int idx = tid * 4; idx < BM * BK; idx += NT * 4) {
            int m = idx / BK, kk = idx % BK;
            float4 v = *reinterpret_cast<const float4*>(A + (size_t)(row0 + m) * lda + (k0 + kk));
            As[kk+0][m]=v.x; As[kk+1][m]=v.y; As[kk+2][m]=v.z; As[kk+3][m]=v.w;
        }
#pragma unroll
        for (int idx = tid * 4; idx < BN * BK; idx += NT * 4) {
            int n = idx / BK, kk = idx % BK;
            float4 v = make_float4(0.f,0.f,0.f,0.f);
            if (col0 + n < N)
                v = *reinterpret_cast<const float4*>(W + (size_t)(col0 + n) * ldw + (k0 + kk));
            Ws[kk+0][n]=v.x; Ws[kk+1][n]=v.y; Ws[kk+2][n]=v.z; Ws[kk+3][n]=v.w;
        }
        __syncthreads();
#pragma unroll
        for (int kk = 0; kk < BK; kk++) {
            float ra[TM], rb[TN];
#pragma unroll
            for (int i = 0; i < TM; i += 4) {
                float4 v = *reinterpret_cast<const float4*>(&As[kk][tr*TM+i]);
                ra[i]=v.x; ra[i+1]=v.y; ra[i+2]=v.z; ra[i+3]=v.w;
            }
#pragma unroll
            for (int j = 0; j < TN; j += 4) {
                float4 v = *reinterpret_cast<const float4*>(&Ws[kk][tc*TN+j]);
                rb[j]=v.x; rb[j+1]=v.y; rb[j+2]=v.z; rb[j+3]=v.w;
            }
#pragma unroll
            for (int i = 0; i < TM; i++)
#pragma unroll
                for (int j = 0; j < TN; j++)
                    acc[i][j] = fmaf(ra[i], rb[j], acc[i][j]);
        }
        __syncthreads();
    }
#pragma unroll
    for (int i = 0; i < TM; i++) {
        int m = row0 + tr*TM + i;
#pragma unroll
        for (int j = 0; j < TN; j++) {
            int n = col0 + tc*TN + j;
            if (n < N) {
                float v = acc[i][j];
                if (bias) v += bias[n];
                C[(size_t)m * ldc + n] = v;
            }
        }
    }
}

// ---------------- split-bf16 tensor-core GEMM (decoder-side only) ----------------
#define MMA_BF16(CC, AA, BB)                                                     \
    asm volatile("mma.sync.aligned.m16n8k16.row.col.f32.bf16.bf16.f32 "          \
        "{%0,%1,%2,%3}, {%4,%5,%6,%7}, {%8,%9}, {%0,%1,%2,%3};"                  \
        : "+f"(CC[0]), "+f"(CC[1]), "+f"(CC[2]), "+f"(CC[3])                     \
        : "r"(AA[0]), "r"(AA[1]), "r"(AA[2]), "r"(AA[3]), "r"(BB[0]), "r"(BB[1]))

__global__ __launch_bounds__(256)
void hgemm_split(const float* __restrict__ A, int lda,
                 const float* __restrict__ W, int ldw,
                 const float* __restrict__ bias,
                 float* __restrict__ C, int ldc, int N, int K)
{
    __shared__ __align__(16) __nv_bfloat16 Ah[128][40];
    __shared__ __align__(16) __nv_bfloat16 Al[128][40];
    __shared__ __align__(16) __nv_bfloat16 Wh[128][40];
    __shared__ __align__(16) __nv_bfloat16 Wl[128][40];
    const int tid  = threadIdx.x;
    const int warp = tid >> 5, lane = tid & 31;
    const int wm = warp >> 2, wn = warp & 3;
    const int row0 = blockIdx.y * 128, col0 = blockIdx.x * 128;
    const int g = lane >> 2, q = lane & 3;
    float acc[4][4][4];
#pragma unroll
    for (int a = 0; a < 4; a++)
#pragma unroll
        for (int b = 0; b < 4; b++)
#pragma unroll
            for (int c = 0; c < 4; c++) acc[a][b][c] = 0.f;
    for (int k0 = 0; k0 < K; k0 += 32) {
        __syncthreads();
        for (int i = tid; i < 128 * 8; i += 256) {
            int r = i >> 3, c4 = (i & 7) << 2;
            float4 va = *reinterpret_cast<const float4*>(&A[(size_t)(row0 + r) * lda + k0 + c4]);
            float xa[4] = {va.x, va.y, va.z, va.w};
#pragma unroll
            for (int e = 0; e < 4; e++) {
                __nv_bfloat16 h = __float2bfloat16_rn(xa[e]);
                Ah[r][c4+e] = h;
                Al[r][c4+e] = __float2bfloat16_rn(xa[e] - __bfloat162float(h));
            }
            float4 vw = make_float4(0.f,0.f,0.f,0.f);
            if (col0 + r < N)
                vw = *reinterpret_cast<const float4*>(&W[(size_t)(col0 + r) * ldw + k0 + c4]);
            float xw[4] = {vw.x, vw.y, vw.z, vw.w};
#pragma unroll
            for (int e = 0; e < 4; e++) {
                __nv_bfloat16 h = __float2bfloat16_rn(xw[e]);
                Wh[r][c4+e] = h;
                Wl[r][c4+e] = __float2bfloat16_rn(xw[e] - __bfloat162float(h));
            }
        }
        __syncthreads();
#pragma unroll
        for (int ks = 0; ks < 32; ks += 16) {
            uint32_t ah[4][4], al[4][4], bh[4][2], bl[4][2];
#pragma unroll
            for (int mi = 0; mi < 4; mi++) {
                int r = wm*64 + mi*16 + g;
                ah[mi][0] = *reinterpret_cast<const uint32_t*>(&Ah[r  ][ks + 2*q    ]);
                ah[mi][1] = *reinterpret_cast<const uint32_t*>(&Ah[r+8][ks + 2*q    ]);
                ah[mi][2] = *reinterpret_cast<const uint32_t*>(&Ah[r  ][ks + 2*q + 8]);
                ah[mi][3] = *reinterpret_cast<const uint32_t*>(&Ah[r+8][ks + 2*q + 8]);
                al[mi][0] = *reinterpret_cast<const uint32_t*>(&Al[r  ][ks + 2*q    ]);
                al[mi][1] = *reinterpret_cast<const uint32_t*>(&Al[r+8][ks + 2*q    ]);
                al[mi][2] = *reinterpret_cast<const uint32_t*>(&Al[r  ][ks + 2*q + 8]);
                al[mi][3] = *reinterpret_cast<const uint32_t*>(&Al[r+8][ks + 2*q + 8]);
            }
#pragma unroll
            for (int ni = 0; ni < 4; ni++) {
                int c = wn*32 + ni*8 + g;
                bh[ni][0] = *reinterpret_cast<const uint32_t*>(&Wh[c][ks + 2*q    ]);
                bh[ni][1] = *reinterpret_cast<const uint32_t*>(&Wh[c][ks + 2*q + 8]);
                bl[ni][0] = *reinterpret_cast<const uint32_t*>(&Wl[c][ks + 2*q    ]);
                bl[ni][1] = *reinterpret_cast<const uint32_t*>(&Wl[c][ks + 2*q + 8]);
            }
#pragma unroll
            for (int mi = 0; mi < 4; mi++)
#pragma unroll
                for (int ni = 0; ni < 4; ni++) {
                    MMA_BF16(acc[mi][ni], ah[mi], bh[ni]);
                    MMA_BF16(acc[mi][ni], ah[mi], bl[ni]);
                    MMA_BF16(acc[mi][ni], al[mi], bh[ni]);
                }
        }
    }
#pragma unroll
    for (int mi = 0; mi < 4; mi++) {
        int r = row0 + wm*64 + mi*16 + g;
#pragma unroll
        for (int ni = 0; ni < 4; ni++) {
            int c = col0 + wn*32 + ni*8 + 2*q;
            float b0 = 0.f, b1 = 0.f;
            if (bias) {
                if (c < N)     b0 = bias[c];
                if (c + 1 < N) b1 = bias[c+1];
            }
            if (c < N) {
                C[(size_t)r * ldc + c]     = acc[mi][ni][0] + b0;
                C[(size_t)(r+8) * ldc + c] = acc[mi][ni][2] + b0;
            }
            if (c + 1 < N) {
                C[(size_t)r * ldc + c + 1]     = acc[mi][ni][1] + b1;
                C[(size_t)(r+8) * ldc + c + 1] = acc[mi][ni][3] + b1;
            }
        }
    }
}

// ---------------- fused LSTM step, gate-interleaved ----------------
// xg and W are gate-interleaved: column index = j*4 + gate(i,f,g,o).
// Block: 128 threads (16x8), output tile 64(batch) x 32(cols) = 64b x 8j x 4g.
// Each thread: 4 batch rows x (1 j x 4 gates) -> full LSTM cell update in registers.
__device__ __forceinline__ float sigf(float x) { return 1.f / (1.f + expf(-x)); }

template<int H>
__global__ __launch_bounds__(128)
void lstm_step2(const float* __restrict__ xgA, const float* __restrict__ xgB, int rsXG,
                const float* __restrict__ WA,  const float* __restrict__ WB,
                const float* __restrict__ hinA, const float* __restrict__ hinB, int rsHin,
                float* __restrict__ cA, float* __restrict__ cB,
                float* __restrict__ houtA, float* __restrict__ houtB, int rsHout)
{
    const float* xg  = blockIdx.z ? xgB  : xgA;
    const float* W   = blockIdx.z ? WB   : WA;
    const float* hin = blockIdx.z ? hinB : hinA;
    float* cp   = blockIdx.z ? cB : cA;
    float* hout = blockIdx.z ? houtB : houtA;

    __shared__ __align__(16) float As[16][68];   // [k][batch]
    __shared__ __align__(16) float Ws[16][36];   // [k][col]
    const int tid = threadIdx.x;
    const int tr = tid >> 3, tc = tid & 7;
    const int row0 = blockIdx.y * 64;
    const int col0 = blockIdx.x * 32;

    float acc[4][4];
#pragma unroll
    for (int i = 0; i < 4; i++)
#pragma unroll
        for (int j = 0; j < 4; j++) acc[i][j] = 0.f;

    for (int k0 = 0; k0 < H; k0 += 16) {
        __syncthreads();
#pragma unroll
        for (int i = tid * 4; i < 64 * 16; i += 128 * 4) {
            int r = i >> 4, kk = i & 15;
            float4 v = *reinterpret_cast<const float4*>(&hin[(size_t)(row0 + r) * rsHin + k0 + kk]);
            As[kk+0][r]=v.x; As[kk+1][r]=v.y; As[kk+2][r]=v.z; As[kk+3][r]=v.w;
        }
        {
            int i = tid * 4;   // 32*16 = 512 = 128*4: one vec per thread
            int r = i >> 4, kk = i & 15;
            float4 v = *reinterpret_cast<const float4*>(&W[(size_t)(col0 + r) * H + k0 + kk]);
            Ws[kk+0][r]=v.x; Ws[kk+1][r]=v.y; Ws[kk+2][r]=v.z; Ws[kk+3][r]=v.w;
        }
        __syncthreads();
#pragma unroll
        for (int kk = 0; kk < 16; kk++) {
            float4 ra = *reinterpret_cast<const float4*>(&As[kk][tr * 4]);
            float4 rb = *reinterpret_cast<const float4*>(&Ws[kk][tc * 4]);
            acc[0][0]=fmaf(ra.x,rb.x,acc[0][0]); acc[0][1]=fmaf(ra.x,rb.y,acc[0][1]);
            acc[0][2]=fmaf(ra.x,rb.z,acc[0][2]); acc[0][3]=fmaf(ra.x,rb.w,acc[0][3]);
            acc[1][0]=fmaf(ra.y,rb.x,acc[1][0]); acc[1][1]=fmaf(ra.y,rb.y,acc[1][1]);
            acc[1][2]=fmaf(ra.y,rb.z,acc[1][2]); acc[1][3]=fmaf(ra.y,rb.w,acc[1][3]);
            acc[2][0]=fmaf(ra.z,rb.x,acc[2][0]); acc[2][1]=fmaf(ra.z,rb.y,acc[2][1]);
            acc[2][2]=fmaf(ra.z,rb.z,acc[2][2]); acc[2][3]=fmaf(ra.z,rb.w,acc[2][3]);
            acc[3][0]=fmaf(ra.w,rb.x,acc[3][0]); acc[3][1]=fmaf(ra.w,rb.y,acc[3][1]);
            acc[3][2]=fmaf(ra.w,rb.z,acc[3][2]); acc[3][3]=fmaf(ra.w,rb.w,acc[3][3]);
        }
    }

    const int col = col0 + tc * 4;
    const int j   = col >> 2;
#pragma unroll
    for (int i = 0; i < 4; i++) {
        int b = row0 + tr * 4 + i;
        float4 xv = *reinterpret_cast<const float4*>(&xg[(size_t)b * rsXG + col]);
        float gi = acc[i][0] + xv.x;
        float gf = acc[i][1] + xv.y;
        float gg = acc[i][2] + xv.z;
        float go = acc[i][3] + xv.w;
        size_t ci = (size_t)b * H + j;
        float cc = sigf(gf) * cp[ci] + sigf(gi) * tanhf(gg);
        cp[ci] = cc;
        hout[(size_t)b * rsHout + j] = sigf(go) * tanhf(cc);
    }
}

// ---------------- elementwise / small kernels ----------------
__global__ void embed_kernel(const int* __restrict__ x, const float* __restrict__ emb,
                             float* __restrict__ out)
{
    size_t idx = (size_t)blockIdx.x * blockDim.x + threadIdx.x;
    if (idx >= (size_t)B_ * T_ * NI_) return;
    int i = (int)(idx % NI_), bt = (int)(idx / NI_);
    out[idx] = emb[(size_t)x[bt] * NI_ + i];
}

__global__ void demb_kernel(const int* __restrict__ x, const float* __restrict__ emb,
                            const float* __restrict__ suffix, float* __restrict__ out)
{
    size_t idx = (size_t)blockIdx.x * blockDim.x + threadIdx.x;
    if (idx >= (size_t)B_ * T_ * NI_) return;
    int i = (int)(idx % NI_), bt = (int)(idx / NI_);
    int b = bt / T_;
    out[idx] = emb[(size_t)x[bt] * NI_ + i] + suffix[(size_t)b * NI_ + i];
}

__global__ void concat_fhs(const float* __restrict__ hf, const float* __restrict__ hb,
                           float* __restrict__ fhs)
{
    int idx = blockIdx.x * blockDim.x + threadIdx.x;
    if (idx >= B_ * 2 * ENH) return;
    int b = idx / (2 * ENH), j = idx % (2 * ENH);
    fhs[idx] = (j < ENH) ? hf[(size_t)b * ENH + j] : hb[(size_t)b * ENH + (j - ENH)];
}

__global__ void kl_kernel(const float* __restrict__ muvar, float* __restrict__ out_kl)
{
    int b = threadIdx.x;
    if (b >= B_) return;
    float s = 0.f;
    const float* row = muvar + (size_t)b * 2 * NZ_;
    for (int j = 0; j < NZ_; j++) {
        float mu = row[j], lv = row[NZ_ + j];
        s += mu * mu + expf(lv) - lv - 1.f;
    }
    out_kl[b] = 0.5f * s;
}

__global__ void dec_init(const float* __restrict__ root, float* __restrict__ h0,
                         float* __restrict__ c0)
{
    int idx = blockIdx.x * blockDim.x + threadIdx.x;
    if (idx >= B_ * DNH) return;
    float r = root[idx];
    h0[idx] = tanhf(r);
    c0[idx] = r;
}

__global__ void vq_kernel(const float* __restrict__ fhs, const float* __restrict__ cb,
                          int* __restrict__ inds, float* __restrict__ q,
                          float* __restrict__ vqp)
{
    const int bn = blockIdx.x;
    const int b = bn / ND_, n = bn % ND_;
    __shared__ __align__(16) float lat[D_];
    __shared__ float svals[256];
    __shared__ int   sidx[256];
    const float* latg = fhs + (size_t)b * (ND_ * D_) + (size_t)n * D_;
    for (int d = threadIdx.x; d < D_; d += 256) lat[d] = latg[d];
    __syncthreads();
    float best = INFINITY; int bidx = K_;
    const float* cbn = cb + (size_t)n * K_ * D_;
    for (int k = threadIdx.x; k < K_; k += 256) {
        const float4* ck = reinterpret_cast<const float4*>(cbn + (size_t)k * D_);
        float t1 = 0.f, t2 = 0.f;
#pragma unroll
        for (int d4 = 0; d4 < D_ / 4; d4++) {
            float4 cv = ck[d4];
            const float4 lv = *reinterpret_cast<const float4*>(&lat[d4 * 4]);
            t1 = fmaf(cv.x, cv.x, t1); t2 = fmaf(cv.x, lv.x, t2);
            t1 = fmaf(cv.y, cv.y, t1); t2 = fmaf(cv.y, lv.y, t2);
            t1 = fmaf(cv.z, cv.z, t1); t2 = fmaf(cv.z, lv.z, t2);
            t1 = fmaf(cv.w, cv.w, t1); t2 = fmaf(cv.w, lv.w, t2);
        }
        float dist = t1 - 2.f * t2;
        if (dist < best || (dist == best && k < bidx)) { best = dist; bidx = k; }
    }
    svals[threadIdx.x] = best; sidx[threadIdx.x] = bidx;
    __syncthreads();
    for (int off = 128; off > 0; off >>= 1) {
        if (threadIdx.x < off) {
            float v = svals[threadIdx.x + off]; int i2 = sidx[threadIdx.x + off];
            if (v < svals[threadIdx.x] || (v == svals[threadIdx.x] && i2 < sidx[threadIdx.x])) {
                svals[threadIdx.x] = v; sidx[threadIdx.x] = i2;
            }
        }
        __syncthreads();
    }
    const int kmin = sidx[0];
    if (threadIdx.x == 0) inds[bn] = kmin;
    __syncthreads();
    const float* ck = cbn + (size_t)kmin * D_;
    float part = 0.f;
    for (int d = threadIdx.x; d < D_; d += 256) {
        float qv = ck[d], lv = lat[d];
        float diff = qv - lv;
        q[(size_t)bn * D_ + d] = lv + diff;
        part += diff * diff;
    }
    svals[threadIdx.x] = part;
    __syncthreads();
    for (int off = 128; off > 0; off >>= 1) {
        if (threadIdx.x < off) svals[threadIdx.x] += svals[threadIdx.x + off];
        __syncthreads();
    }
    if (threadIdx.x == 0) vqp[bn] = svals[0] / (float)D_;
}

__global__ void vq_finish(const float* __restrict__ vqp, const int* __restrict__ inds,
                          float* __restrict__ out_vq, float* __restrict__ out_inds)
{
    int b = threadIdx.x;
    if (b >= B_) return;
    float s = 0.f;
#pragma unroll
    for (int n = 0; n < ND_; n++) s += vqp[b * ND_ + n];
    out_vq[b] = 1.25f * s;
#pragma unroll
    for (int n = 0; n < ND_; n++)
        out_inds[b * ND_ + n] = (float)inds[b * ND_ + n];
}

// ---------------- launch helpers ----------------
static inline void gemm_big(const float* A, int lda, const float* W, int ldw,
                            const float* bias, float* C, int ldc, int M, int N, int K)
{
    dim3 grid((N + 127) / 128, M / 128);
    gemm_k<128, 128, 16, 8, 8><<<grid, 256>>>(A, lda, W, ldw, bias, C, ldc, N, K);
}
static inline void gemm_small(const float* A, int lda, const float* W, int ldw,
                              const float* bias, float* C, int ldc, int M, int N, int K)
{
    dim3 grid((N + 63) / 64, M / 32);
    gemm_k<32, 64, 16, 4, 4><<<grid, 128>>>(A, lda, W, ldw, bias, C, ldc, N, K);
}
static inline void gemm_tc(const float* A, int lda, const float* W, int ldw,
                           const float* bias, float* C, int ldc, int M, int N, int K)
{
    dim3 grid((N + 127) / 128, M / 128);
    hgemm_split<<<grid, 256>>>(A, lda, W, ldw, bias, C, ldc, N, K);
}

extern "C" void kernel_launch(void* const* d_in, const int* in_sizes, int n_in,
                              void* d_out, int out_size)
{
    (void)in_sizes; (void)n_in; (void)out_size;
    const int*   x         = (const int*)  d_in[0];
    const float* enc_embed = (const float*)d_in[1];
    const float* enc_Wih_f = (const float*)d_in[2];
    const float* enc_Whh_f = (const float*)d_in[3];
    const float* enc_b_f   = (const float*)d_in[4];
    const float* enc_Wih_b = (const float*)d_in[5];
    const float* enc_Whh_b = (const float*)d_in[6];
    const float* enc_b_b   = (const float*)d_in[7];
    const float* enc_lin   = (const float*)d_in[8];
    const float* z2dec_W   = (const float*)d_in[9];
    const float* z2dec_b   = (const float*)d_in[10];
    const float* codebooks = (const float*)d_in[11];
    const float* suffix_W  = (const float*)d_in[12];
    const float* dec_embed = (const float*)d_in[13];
    const float* dec_Wih   = (const float*)d_in[14];
    const float* dec_Whh   = (const float*)d_in[15];
    const float* dec_b     = (const float*)d_in[16];
    const float* pred_W    = (const float*)d_in[17];

    float* out      = (float*)d_out;
    float* out_log  = out;
    float* out_vq   = out + (size_t)LOGITS_ELEMS;
    float* out_kl   = out_vq + B_;
    float* out_inds = out_kl + B_;

    float *we,*xgf,*xgb,*encA,*hfB,*hbB,*fhs,*muvar,*root,*q,*vqp,*suffix;
    float *demb,*xgd,*hd0,*cd,*decout;
    float *WfP,*WbP,*WhfP,*WhbP,*WdP,*WhdP,*bfP,*bbP,*bdP;
    int* inds;
    cudaGetSymbolAddress((void**)&we,    g_we);
    cudaGetSymbolAddress((void**)&xgf,   g_xgf);
    cudaGetSymbolAddress((void**)&xgb,   g_xgb);
    cudaGetSymbolAddress((void**)&encA,  g_encA);
    cudaGetSymbolAddress((void**)&hfB,   g_hfB);
    cudaGetSymbolAddress((void**)&hbB,   g_hbB);
    cudaGetSymbolAddress((void**)&fhs,   g_fhs);
    cudaGetSymbolAddress((void**)&muvar, g_muvar);
    cudaGetSymbolAddress((void**)&root,  g_root);
    cudaGetSymbolAddress((void**)&inds,  g_inds);
    cudaGetSymbolAddress((void**)&q,     g_q);
    cudaGetSymbolAddress((void**)&vqp,   g_vqp);
    cudaGetSymbolAddress((void**)&suffix,g_suffix);
    cudaGetSymbolAddress((void**)&demb,  g_demb);
    cudaGetSymbolAddress((void**)&xgd,   g_xgd);
    cudaGetSymbolAddress((void**)&hd0,   g_hd0);
    cudaGetSymbolAddress((void**)&cd,    g_cd);
    cudaGetSymbolAddress((void**)&decout,g_decout);
    cudaGetSymbolAddress((void**)&WfP,   g_WfP);
    cudaGetSymbolAddress((void**)&WbP,   g_WbP);
    cudaGetSymbolAddress((void**)&WhfP,  g_WhfP);
    cudaGetSymbolAddress((void**)&WhbP,  g_WhbP);
    cudaGetSymbolAddress((void**)&WdP,   g_WdP);
    cudaGetSymbolAddress((void**)&WhdP,  g_WhdP);
    cudaGetSymbolAddress((void**)&bfP,   g_bfP);
    cudaGetSymbolAddress((void**)&bbP,   g_bbP);
    cudaGetSymbolAddress((void**)&bdP,   g_bdP);

    float* hfA = encA;
    float* cf  = encA + (size_t)B_ * ENH;
    float* hbA = encA + (size_t)2 * B_ * ENH;
    float* cb  = encA + (size_t)3 * B_ * ENH;

    const int EW = 256;

    // 0) permute weights/biases to gate-interleaved layout
    perm_w<<<(4*ENH*NI_ + EW-1)/EW, EW>>>(enc_Wih_f, WfP,  ENH, NI_);
    perm_w<<<(4*ENH*NI_ + EW-1)/EW, EW>>>(enc_Wih_b, WbP,  ENH, NI_);
    perm_w<<<(4*ENH*ENH + EW-1)/EW, EW>>>(enc_Whh_f, WhfP, ENH, ENH);
    perm_w<<<(4*ENH*ENH + EW-1)/EW, EW>>>(enc_Whh_b, WhbP, ENH, ENH);
    perm_w<<<(4*DNH*NI_ + EW-1)/EW, EW>>>(dec_Wih,   WdP,  DNH, NI_);
    perm_w<<<(4*DNH*DNH + EW-1)/EW, EW>>>(dec_Whh,   WhdP, DNH, DNH);
    perm_b<<<(4*ENH + EW-1)/EW, EW>>>(enc_b_f, bfP, ENH);
    perm_b<<<(4*ENH + EW-1)/EW, EW>>>(enc_b_b, bbP, ENH);
    perm_b<<<(4*DNH + EW-1)/EW, EW>>>(dec_b,   bdP, DNH);

    // 1) encoder embedding + interleaved input-gate GEMMs (fp32)
    embed_kernel<<<(B_ * T_ * NI_ + EW - 1) / EW, EW>>>(x, enc_embed, we);
    gemm_big(we, NI_, WfP, NI_, bfP, xgf, 4 * ENH, B_ * T_, 4 * ENH, NI_);
    gemm_big(we, NI_, WbP, NI_, bbP, xgb, 4 * ENH, B_ * T_, 4 * ENH, NI_);
    cudaMemsetAsync(encA, 0, sizeof(float) * 4 * B_ * ENH, 0);

    // 2) encoder recurrence: fused gemm+gates, both directions, h double-buffered
    {
        dim3 grid(4 * ENH / 32, 2, 2);
        for (int s = 0; s < T_; s++) {
            const float* hf_in = (s & 1) ? hfB : hfA;
            float*       hf_out= (s & 1) ? hfA : hfB;
            const float* hb_in = (s & 1) ? hbB : hbA;
            float*       hb_out= (s & 1) ? hbA : hbB;
            lstm_step2<ENH><<<grid, 128>>>(
                xgf + (size_t)s * 4 * ENH, xgb + (size_t)(T_ - 1 - s) * 4 * ENH, T_ * 4 * ENH,
                WhfP, WhbP,
                hf_in, hb_in, ENH,
                cf, cb,
                hf_out, hb_out, ENH);
        }
    }
    concat_fhs<<<(B_ * 2 * ENH + EW - 1) / EW, EW>>>(hfA, hbA, fhs);

    gemm_small(fhs, 2 * ENH, enc_lin, 2 * ENH, nullptr, muvar, 2 * NZ_, B_, 2 * NZ_, 2 * ENH);
    kl_kernel<<<1, B_>>>(muvar, out_kl);
    gemm_small(muvar, 2 * NZ_, z2dec_W, NZ_, z2dec_b, root, DNH, B_, DNH, NZ_);

    vq_kernel<<<B_ * ND_, 256>>>(fhs, codebooks, inds, q, vqp);
    vq_finish<<<1, B_>>>(vqp, inds, out_vq, out_inds);

    gemm_small(q, ND_ * D_, suffix_W, ND_ * D_, nullptr, suffix, NI_, B_, NI_, ND_ * D_);
    demb_kernel<<<(B_ * T_ * NI_ + EW - 1) / EW, EW>>>(x, dec_embed, suffix, demb);

    // decoder input gates (interleaved via permuted W): tensor-core split-bf16
    gemm_tc(demb, NI_, WdP, NI_, bdP, xgd, 4 * DNH, B_ * T_, 4 * DNH, NI_);

    dec_init<<<(B_ * DNH + EW - 1) / EW, EW>>>(root, hd0, cd);

    // decoder recurrence: fused step, h straight into decout slices
    {
        dim3 grid(4 * DNH / 32, 2, 1);
        for (int s = 0; s < T_; s++) {
            const float* hin = (s == 0) ? hd0 : (decout + (size_t)(s - 1) * DNH);
            int rsHin        = (s == 0) ? DNH : (T_ * DNH);
            const float* xgs = xgd + (size_t)s * 4 * DNH;
            float* ho        = decout + (size_t)s * DNH;
            lstm_step2<DNH><<<grid, 128>>>(
                xgs, xgs, T_ * 4 * DNH,
                WhdP, WhdP,
                hin, hin, rsHin,
                cd, cd,
                ho, ho, T_ * DNH);
        }
    }

    // logits: tensor-core split-bf16
    gemm_tc(decout, DNH, pred_W, DNH, nullptr, out_log, V_, B_ * T_, V_, DNH);
}

// round 13
// speedup vs baseline: 1.4759x; 1.0324x over previous
#include <cuda_runtime.h>
#include <cuda_bf16.h>
#include <math.h>
#include <stdint.h>

#define B_    128
#define T_    64
#define V_    10000
#define NI_   512
#define ENH   640
#define DNH   1024
#define NZ_   128
#define ND_   8
#define K_    1024
#define D_    160
#define LOGITS_ELEMS (B_ * T_ * V_)
#define VPAD  10112   // 79 * 128

// ---------------- scratch ----------------
__device__ __align__(256) float g_we   [B_ * T_ * NI_];
__device__ __align__(256) float g_xgf  [B_ * T_ * 4 * ENH];
__device__ __align__(256) float g_xgb  [B_ * T_ * 4 * ENH];
__device__ __align__(256) float g_encA [4 * B_ * ENH];   // hfA, cf, hbA, cb
__device__ __align__(256) float g_hfB  [B_ * ENH];
__device__ __align__(256) float g_hbB  [B_ * ENH];
__device__ __align__(256) float g_fhs  [B_ * 2 * ENH];
__device__ __align__(256) float g_muvar[B_ * 2 * NZ_];
__device__ __align__(256) float g_root [B_ * DNH];
__device__ __align__(256) int   g_inds [B_ * ND_];
__device__ __align__(256) float g_q    [B_ * ND_ * D_];
__device__ __align__(256) float g_vqp  [B_ * ND_];
__device__ __align__(256) float g_suffix[B_ * NI_];
__device__ __align__(256) float g_xgd  [B_ * T_ * 4 * DNH];
__device__ __align__(256) float g_hd0  [B_ * DNH];
__device__ __align__(256) float g_cd   [B_ * DNH];
__device__ __align__(256) float g_decout[B_ * T_ * DNH];
// permuted (gate-interleaved) fp32 weights/biases (encoder + dec Whh)
__device__ __align__(256) float g_WfP  [4 * ENH * NI_];
__device__ __align__(256) float g_WbP  [4 * ENH * NI_];
__device__ __align__(256) float g_WhfP [4 * ENH * ENH];
__device__ __align__(256) float g_WhbP [4 * ENH * ENH];
__device__ __align__(256) float g_WhdP [4 * DNH * DNH];
__device__ __align__(256) float g_bfP  [4 * ENH];
__device__ __align__(256) float g_bbP  [4 * ENH];
__device__ __align__(256) float g_bdP  [4 * DNH];
// preconverted bf16 hi/lo operands (decoder-side tensor path)
__device__ __align__(256) __nv_bfloat16 g_dembH[B_ * T_ * NI_];
__device__ __align__(256) __nv_bfloat16 g_dembL[B_ * T_ * NI_];
__device__ __align__(256) __nv_bfloat16 g_WdH  [4 * DNH * NI_];
__device__ __align__(256) __nv_bfloat16 g_WdL  [4 * DNH * NI_];
__device__ __align__(256) __nv_bfloat16 g_doH  [B_ * T_ * DNH];
__device__ __align__(256) __nv_bfloat16 g_doL  [B_ * T_ * DNH];
__device__ __align__(256) __nv_bfloat16 g_pwH  [VPAD * DNH];
__device__ __align__(256) __nv_bfloat16 g_pwL  [VPAD * DNH];

// ---------------- helpers ----------------
__device__ __forceinline__ uint32_t smem_u32(const void* p) {
    uint32_t a;
    asm("{ .reg .u64 t; cvta.to.shared.u64 t, %1; cvt.u32.u64 %0, t; }" : "=r"(a) : "l"(p));
    return a;
}
__device__ __forceinline__ void cpa16(uint32_t dst, const void* src) {
    asm volatile("cp.async.ca.shared.global [%0], [%1], 16;" :: "r"(dst), "l"(src));
}

// ---------------- weight permute: row g*H+j -> j*4+g ----------------
__global__ void perm_w(const float* __restrict__ W, float* __restrict__ Wp, int H, int K)
{
    size_t idx = (size_t)blockIdx.x * blockDim.x + threadIdx.x;
    if (idx >= (size_t)4 * H * K) return;
    int k = (int)(idx % K);
    int r = (int)(idx / K);
    int g = r / H, j = r % H;
    Wp[((size_t)j * 4 + g) * K + k] = W[idx];
}
__global__ void perm_w_split(const float* __restrict__ W,
                             __nv_bfloat16* __restrict__ WH, __nv_bfloat16* __restrict__ WL,
                             int H, int K)
{
    size_t idx = (size_t)blockIdx.x * blockDim.x + threadIdx.x;
    if (idx >= (size_t)4 * H * K) return;
    int k = (int)(idx % K);
    int r = (int)(idx / K);
    int g = r / H, j = r % H;
    float v = W[idx];
    __nv_bfloat16 h = __float2bfloat16_rn(v);
    size_t o = ((size_t)j * 4 + g) * K + k;
    WH[o] = h;
    WL[o] = __float2bfloat16_rn(v - __bfloat162float(h));
}
__global__ void perm_b(const float* __restrict__ b, float* __restrict__ bp, int H)
{
    int idx = blockIdx.x * blockDim.x + threadIdx.x;
    if (idx >= 4 * H) return;
    int g = idx / H, j = idx % H;
    bp[j * 4 + g] = b[idx];
}
// split fp32 [rows_total x cols] (rows >= rows_valid zero-filled)
__global__ void split_pad(const float* __restrict__ X,
                          __nv_bfloat16* __restrict__ H, __nv_bfloat16* __restrict__ L,
                          int rows_valid, int rows_total, int cols)
{
    size_t idx = (size_t)blockIdx.x * blockDim.x + threadIdx.x;
    if (idx >= (size_t)rows_total * cols) return;
    int r = (int)(idx / cols);
    float v = (r < rows_valid) ? X[idx] : 0.f;
    __nv_bfloat16 h = __float2bfloat16_rn(v);
    H[idx] = h;
    L[idx] = __float2bfloat16_rn(v - __bfloat162float(h));
}

// ---------------- fp32 SGEMM (encoder path; exact numerics) ----------------
template<int BM, int BN, int BK, int TM, int TN>
__global__ __launch_bounds__((BM/TM)*(BN/TN))
void gemm_k(const float* __restrict__ A, int lda,
            const float* __restrict__ W, int ldw,
            const float* __restrict__ bias,
            float* __restrict__ C, int ldc,
            int N, int K)
{
    constexpr int NT = (BM/TM)*(BN/TN);
    __shared__ __align__(16) float As[BK][BM + 4];
    __shared__ __align__(16) float Ws[BK][BN + 4];
    const int tid  = threadIdx.x;
    const int row0 = blockIdx.y * BM;
    const int col0 = blockIdx.x * BN;
    const int tr   = tid / (BN / TN);
    const int tc   = tid % (BN / TN);
    float acc[TM][TN];
#pragma unroll
    for (int i = 0; i < TM; i++)
#pragma unroll
        for (int j = 0; j < TN; j++) acc[i][j] = 0.f;
    for (int k0 = 0; k0 < K; k0 += BK) {
#pragma unroll
        for (int idx = tid * 4; idx < BM * BK; idx += NT * 4) {
            int m = idx / BK, kk = idx % BK;
            float4 v = *reinterpret_cast<const float4*>(A + (size_t)(row0 + m) * lda + (k0 + kk));
            As[kk+0][m]=v.x; As[kk+1][m]=v.y; As[kk+2][m]=v.z; As[kk+3][m]=v.w;
        }
#pragma unroll
        for (int idx = tid * 4; idx < BN * BK; idx += NT * 4) {
            int n = idx / BK, kk = idx % BK;
            float4 v = make_float4(0.f,0.f,0.f,0.f);
            if (col0 + n < N)
                v = *reinterpret_cast<const float4*>(W + (size_t)(col0 + n) * ldw + (k0 + kk));
            Ws[kk+0][n]=v.x; Ws[kk+1][n]=v.y; Ws[kk+2][n]=v.z; Ws[kk+3][n]=v.w;
        }
        __syncthreads();
#pragma unroll
        for (int kk = 0; kk < BK; kk++) {
            float ra[TM], rb[TN];
#pragma unroll
            for (int i = 0; i < TM; i += 4) {
                float4 v = *reinterpret_cast<const float4*>(&As[kk][tr*TM+i]);
                ra[i]=v.x; ra[i+1]=v.y; ra[i+2]=v.z; ra[i+3]=v.w;
            }
#pragma unroll
            for (int j = 0; j < TN; j += 4) {
                float4 v = *reinterpret_cast<const float4*>(&Ws[kk][tc*TN+j]);
                rb[j]=v.x; rb[j+1]=v.y; rb[j+2]=v.z; rb[j+3]=v.w;
            }
#pragma unroll
            for (int i = 0; i < TM; i++)
#pragma unroll
                for (int j = 0; j < TN; j++)
                    acc[i][j] = fmaf(ra[i], rb[j], acc[i][j]);
        }
        __syncthreads();
    }
#pragma unroll
    for (int i = 0; i < TM; i++) {
        int m = row0 + tr*TM + i;
#pragma unroll
        for (int j = 0; j < TN; j++) {
            int n = col0 + tc*TN + j;
            if (n < N) {
                float v = acc[i][j];
                if (bias) v += bias[n];
                C[(size_t)m * ldc + n] = v;
            }
        }
    }
}

// ---------------- split-bf16 tensor GEMM, preconverted operands + cp.async ----------------
#define MMA_BF16(CC, AA, BB)                                                     \
    asm volatile("mma.sync.aligned.m16n8k16.row.col.f32.bf16.bf16.f32 "          \
        "{%0,%1,%2,%3}, {%4,%5,%6,%7}, {%8,%9}, {%0,%1,%2,%3};"                  \
        : "+f"(CC[0]), "+f"(CC[1]), "+f"(CC[2]), "+f"(CC[3])                     \
        : "r"(AA[0]), "r"(AA[1]), "r"(AA[2]), "r"(AA[3]), "r"(BB[0]), "r"(BB[1]))

// A [M,K] bf16 hi/lo, W [Npad,K] bf16 hi/lo (pad rows zero). M%128==0, K%32==0.
// SMEM stage: 4 arrays x 128 rows x 40 cols bf16 (10240 B each); 2 stages = 81920 B dynamic.
__global__ __launch_bounds__(256)
void hgemm2(const __nv_bfloat16* __restrict__ AH, const __nv_bfloat16* __restrict__ AL,
            const __nv_bfloat16* __restrict__ WH, const __nv_bfloat16* __restrict__ WL,
            const float* __restrict__ bias,
            float* __restrict__ C, int ldc, int N, int K)
{
    extern __shared__ __align__(16) __nv_bfloat16 dsm[];
    const int tid  = threadIdx.x;
    const int warp = tid >> 5, lane = tid & 31;
    const int wm = warp >> 2, wn = warp & 3;
    const int row0 = blockIdx.y * 128, col0 = blockIdx.x * 128;
    const int g = lane >> 2, q = lane & 3;
    const uint32_t sbase = smem_u32(dsm);
    const int ntiles = K >> 5;

    float acc[4][4][4];
#pragma unroll
    for (int a = 0; a < 4; a++)
#pragma unroll
        for (int b = 0; b < 4; b++)
#pragma unroll
            for (int c = 0; c < 4; c++) acc[a][b][c] = 0.f;

    // stage offsets (bytes): stage*40960; arrays at +0, +10240, +20480, +30720
    auto issue_loads = [&](int stage, int t) {
        uint32_t sb = sbase + stage * 40960u;
        int k0 = t << 5;
        for (int i = tid; i < 512; i += 256) {
            int r = i >> 2, c8 = (i & 3) << 3;
            uint32_t off = (uint32_t)(r * 40 + c8) * 2;
            cpa16(sb + off,          AH + (size_t)(row0 + r) * K + k0 + c8);
            cpa16(sb + 10240 + off,  AL + (size_t)(row0 + r) * K + k0 + c8);
            cpa16(sb + 20480 + off,  WH + (size_t)(col0 + r) * K + k0 + c8);
            cpa16(sb + 30720 + off,  WL + (size_t)(col0 + r) * K + k0 + c8);
        }
    };

    issue_loads(0, 0);
    asm volatile("cp.async.commit_group;" ::: "memory");

    for (int t = 0; t < ntiles; t++) {
        if (t + 1 < ntiles) {
            issue_loads((t + 1) & 1, t + 1);
            asm volatile("cp.async.commit_group;" ::: "memory");
            asm volatile("cp.async.wait_group 1;" ::: "memory");
        } else {
            asm volatile("cp.async.wait_group 0;" ::: "memory");
        }
        __syncthreads();
        const __nv_bfloat16* Ah = dsm + (size_t)(t & 1) * 20480;
        const __nv_bfloat16* Al = Ah + 5120;
        const __nv_bfloat16* Wh = Ah + 10240;
        const __nv_bfloat16* Wl = Ah + 15360;
#pragma unroll
        for (int ks = 0; ks < 32; ks += 16) {
            uint32_t ah[4][4], al[4][4], bh[4][2], bl[4][2];
#pragma unroll
            for (int mi = 0; mi < 4; mi++) {
                int r = wm*64 + mi*16 + g;
                ah[mi][0] = *reinterpret_cast<const uint32_t*>(&Ah[(r  )*40 + ks + 2*q    ]);
                ah[mi][1] = *reinterpret_cast<const uint32_t*>(&Ah[(r+8)*40 + ks + 2*q    ]);
                ah[mi][2] = *reinterpret_cast<const uint32_t*>(&Ah[(r  )*40 + ks + 2*q + 8]);
                ah[mi][3] = *reinterpret_cast<const uint32_t*>(&Ah[(r+8)*40 + ks + 2*q + 8]);
                al[mi][0] = *reinterpret_cast<const uint32_t*>(&Al[(r  )*40 + ks + 2*q    ]);
                al[mi][1] = *reinterpret_cast<const uint32_t*>(&Al[(r+8)*40 + ks + 2*q    ]);
                al[mi][2] = *reinterpret_cast<const uint32_t*>(&Al[(r  )*40 + ks + 2*q + 8]);
                al[mi][3] = *reinterpret_cast<const uint32_t*>(&Al[(r+8)*40 + ks + 2*q + 8]);
            }
#pragma unroll
            for (int ni = 0; ni < 4; ni++) {
                int c = wn*32 + ni*8 + g;
                bh[ni][0] = *reinterpret_cast<const uint32_t*>(&Wh[c*40 + ks + 2*q    ]);
                bh[ni][1] = *reinterpret_cast<const uint32_t*>(&Wh[c*40 + ks + 2*q + 8]);
                bl[ni][0] = *reinterpret_cast<const uint32_t*>(&Wl[c*40 + ks + 2*q    ]);
                bl[ni][1] = *reinterpret_cast<const uint32_t*>(&Wl[c*40 + ks + 2*q + 8]);
            }
#pragma unroll
            for (int mi = 0; mi < 4; mi++)
#pragma unroll
                for (int ni = 0; ni < 4; ni++) {
                    MMA_BF16(acc[mi][ni], ah[mi], bh[ni]);
                    MMA_BF16(acc[mi][ni], ah[mi], bl[ni]);
                    MMA_BF16(acc[mi][ni], al[mi], bh[ni]);
                }
        }
        __syncthreads();
    }

#pragma unroll
    for (int mi = 0; mi < 4; mi++) {
        int r = row0 + wm*64 + mi*16 + g;
#pragma unroll
        for (int ni = 0; ni < 4; ni++) {
            int c = col0 + wn*32 + ni*8 + 2*q;
            float b0 = 0.f, b1 = 0.f;
            if (bias) {
                if (c < N)     b0 = bias[c];
                if (c + 1 < N) b1 = bias[c+1];
            }
            if (c < N) {
                C[(size_t)r * ldc + c]     = acc[mi][ni][0] + b0;
                C[(size_t)(r+8) * ldc + c] = acc[mi][ni][2] + b0;
            }
            if (c + 1 < N) {
                C[(size_t)r * ldc + c + 1]     = acc[mi][ni][1] + b1;
                C[(size_t)(r+8) * ldc + c + 1] = acc[mi][ni][3] + b1;
            }
        }
    }
}

// ---------------- fused LSTM step, gate-interleaved ----------------
__device__ __forceinline__ float sigf(float x) { return 1.f / (1.f + expf(-x)); }

template<int H>
__global__ __launch_bounds__(128)
void lstm_step2(const float* __restrict__ xgA, const float* __restrict__ xgB, int rsXG,
                const float* __restrict__ WA,  const float* __restrict__ WB,
                const float* __restrict__ hinA, const float* __restrict__ hinB, int rsHin,
                float* __restrict__ cA, float* __restrict__ cB,
                float* __restrict__ houtA, float* __restrict__ houtB, int rsHout,
                __nv_bfloat16* __restrict__ hH, __nv_bfloat16* __restrict__ hL)
{
    const float* xg  = blockIdx.z ? xgB  : xgA;
    const float* W   = blockIdx.z ? WB   : WA;
    const float* hin = blockIdx.z ? hinB : hinA;
    float* cp   = blockIdx.z ? cB : cA;
    float* hout = blockIdx.z ? houtB : houtA;

    __shared__ __align__(16) float As[16][68];
    __shared__ __align__(16) float Ws[16][36];
    const int tid = threadIdx.x;
    const int tr = tid >> 3, tc = tid & 7;
    const int row0 = blockIdx.y * 64;
    const int col0 = blockIdx.x * 32;

    float acc[4][4];
#pragma unroll
    for (int i = 0; i < 4; i++)
#pragma unroll
        for (int j = 0; j < 4; j++) acc[i][j] = 0.f;

    for (int k0 = 0; k0 < H; k0 += 16) {
        __syncthreads();
#pragma unroll
        for (int i = tid * 4; i < 64 * 16; i += 128 * 4) {
            int r = i >> 4, kk = i & 15;
            float4 v = *reinterpret_cast<const float4*>(&hin[(size_t)(row0 + r) * rsHin + k0 + kk]);
            As[kk+0][r]=v.x; As[kk+1][r]=v.y; As[kk+2][r]=v.z; As[kk+3][r]=v.w;
        }
        {
            int i = tid * 4;
            int r = i >> 4, kk = i & 15;
            float4 v = *reinterpret_cast<const float4*>(&W[(size_t)(col0 + r) * H + k0 + kk]);
            Ws[kk+0][r]=v.x; Ws[kk+1][r]=v.y; Ws[kk+2][r]=v.z; Ws[kk+3][r]=v.w;
        }
        __syncthreads();
#pragma unroll
        for (int kk = 0; kk < 16; kk++) {
            float4 ra = *reinterpret_cast<const float4*>(&As[kk][tr * 4]);
            float4 rb = *reinterpret_cast<const float4*>(&Ws[kk][tc * 4]);
            acc[0][0]=fmaf(ra.x,rb.x,acc[0][0]); acc[0][1]=fmaf(ra.x,rb.y,acc[0][1]);
            acc[0][2]=fmaf(ra.x,rb.z,acc[0][2]); acc[0][3]=fmaf(ra.x,rb.w,acc[0][3]);
            acc[1][0]=fmaf(ra.y,rb.x,acc[1][0]); acc[1][1]=fmaf(ra.y,rb.y,acc[1][1]);
            acc[1][2]=fmaf(ra.y,rb.z,acc[1][2]); acc[1][3]=fmaf(ra.y,rb.w,acc[1][3]);
            acc[2][0]=fmaf(ra.z,rb.x,acc[2][0]); acc[2][1]=fmaf(ra.z,rb.y,acc[2][1]);
            acc[2][2]=fmaf(ra.z,rb.z,acc[2][2]); acc[2][3]=fmaf(ra.z,rb.w,acc[2][3]);
            acc[3][0]=fmaf(ra.w,rb.x,acc[3][0]); acc[3][1]=fmaf(ra.w,rb.y,acc[3][1]);
            acc[3][2]=fmaf(ra.w,rb.z,acc[3][2]); acc[3][3]=fmaf(ra.w,rb.w,acc[3][3]);
        }
    }

    const int col = col0 + tc * 4;
    const int j   = col >> 2;
#pragma unroll
    for (int i = 0; i < 4; i++) {
        int b = row0 + tr * 4 + i;
        float4 xv = *reinterpret_cast<const float4*>(&xg[(size_t)b * rsXG + col]);
        float gi = acc[i][0] + xv.x;
        float gf = acc[i][1] + xv.y;
        float gg = acc[i][2] + xv.z;
        float go = acc[i][3] + xv.w;
        size_t ci = (size_t)b * H + j;
        float cc = sigf(gf) * cp[ci] + sigf(gi) * tanhf(gg);
        cp[ci] = cc;
        float hv = sigf(go) * tanhf(cc);
        hout[(size_t)b * rsHout + j] = hv;
        if (hH) {
            __nv_bfloat16 hh = __float2bfloat16_rn(hv);
            hH[(size_t)b * rsHout + j] = hh;
            hL[(size_t)b * rsHout + j] = __float2bfloat16_rn(hv - __bfloat162float(hh));
        }
    }
}

// ---------------- elementwise / small kernels ----------------
__global__ void embed_kernel(const int* __restrict__ x, const float* __restrict__ emb,
                             float* __restrict__ out)
{
    size_t idx = (size_t)blockIdx.x * blockDim.x + threadIdx.x;
    if (idx >= (size_t)B_ * T_ * NI_) return;
    int i = (int)(idx % NI_), bt = (int)(idx / NI_);
    out[idx] = emb[(size_t)x[bt] * NI_ + i];
}

__global__ void demb_split(const int* __restrict__ x, const float* __restrict__ emb,
                           const float* __restrict__ suffix,
                           __nv_bfloat16* __restrict__ H, __nv_bfloat16* __restrict__ L)
{
    size_t idx = (size_t)blockIdx.x * blockDim.x + threadIdx.x;
    if (idx >= (size_t)B_ * T_ * NI_) return;
    int i = (int)(idx % NI_), bt = (int)(idx / NI_);
    int b = bt / T_;
    float v = emb[(size_t)x[bt] * NI_ + i] + suffix[(size_t)b * NI_ + i];
    __nv_bfloat16 h = __float2bfloat16_rn(v);
    H[idx] = h;
    L[idx] = __float2bfloat16_rn(v - __bfloat162float(h));
}

__global__ void concat_fhs(const float* __restrict__ hf, const float* __restrict__ hb,
                           float* __restrict__ fhs)
{
    int idx = blockIdx.x * blockDim.x + threadIdx.x;
    if (idx >= B_ * 2 * ENH) return;
    int b = idx / (2 * ENH), j = idx % (2 * ENH);
    fhs[idx] = (j < ENH) ? hf[(size_t)b * ENH + j] : hb[(size_t)b * ENH + (j - ENH)];
}

__global__ void kl_kernel(const float* __restrict__ muvar, float* __restrict__ out_kl)
{
    int b = threadIdx.x;
    if (b >= B_) return;
    float s = 0.f;
    const float* row = muvar + (size_t)b * 2 * NZ_;
    for (int j = 0; j < NZ_; j++) {
        float mu = row[j], lv = row[NZ_ + j];
        s += mu * mu + expf(lv) - lv - 1.f;
    }
    out_kl[b] = 0.5f * s;
}

__global__ void dec_init(const float* __restrict__ root, float* __restrict__ h0,
                         float* __restrict__ c0)
{
    int idx = blockIdx.x * blockDim.x + threadIdx.x;
    if (idx >= B_ * DNH) return;
    float r = root[idx];
    h0[idx] = tanhf(r);
    c0[idx] = r;
}

__global__ void vq_kernel(const float* __restrict__ fhs, const float* __restrict__ cb,
                          int* __restrict__ inds, float* __restrict__ q,
                          float* __restrict__ vqp)
{
    const int bn = blockIdx.x;
    const int b = bn / ND_, n = bn % ND_;
    __shared__ __align__(16) float lat[D_];
    __shared__ float svals[256];
    __shared__ int   sidx[256];
    const float* latg = fhs + (size_t)b * (ND_ * D_) + (size_t)n * D_;
    for (int d = threadIdx.x; d < D_; d += 256) lat[d] = latg[d];
    __syncthreads();
    float best = INFINITY; int bidx = K_;
    const float* cbn = cb + (size_t)n * K_ * D_;
    for (int k = threadIdx.x; k < K_; k += 256) {
        const float4* ck = reinterpret_cast<const float4*>(cbn + (size_t)k * D_);
        float t1 = 0.f, t2 = 0.f;
#pragma unroll
        for (int d4 = 0; d4 < D_ / 4; d4++) {
            float4 cv = ck[d4];
            const float4 lv = *reinterpret_cast<const float4*>(&lat[d4 * 4]);
            t1 = fmaf(cv.x, cv.x, t1); t2 = fmaf(cv.x, lv.x, t2);
            t1 = fmaf(cv.y, cv.y, t1); t2 = fmaf(cv.y, lv.y, t2);
            t1 = fmaf(cv.z, cv.z, t1); t2 = fmaf(cv.z, lv.z, t2);
            t1 = fmaf(cv.w, cv.w, t1); t2 = fmaf(cv.w, lv.w, t2);
        }
        float dist = t1 - 2.f * t2;
        if (dist < best || (dist == best && k < bidx)) { best = dist; bidx = k; }
    }
    svals[threadIdx.x] = best; sidx[threadIdx.x] = bidx;
    __syncthreads();
    for (int off = 128; off > 0; off >>= 1) {
        if (threadIdx.x < off) {
            float v = svals[threadIdx.x + off]; int i2 = sidx[threadIdx.x + off];
            if (v < svals[threadIdx.x] || (v == svals[threadIdx.x] && i2 < sidx[threadIdx.x])) {
                svals[threadIdx.x] = v; sidx[threadIdx.x] = i2;
            }
        }
        __syncthreads();
    }
    const int kmin = sidx[0];
    if (threadIdx.x == 0) inds[bn] = kmin;
    __syncthreads();
    const float* ck = cbn + (size_t)kmin * D_;
    float part = 0.f;
    for (int d = threadIdx.x; d < D_; d += 256) {
        float qv = ck[d], lv = lat[d];
        float diff = qv - lv;
        q[(size_t)bn * D_ + d] = lv + diff;
        part += diff * diff;
    }
    svals[threadIdx.x] = part;
    __syncthreads();
    for (int off = 128; off > 0; off >>= 1) {
        if (threadIdx.x < off) svals[threadIdx.x] += svals[threadIdx.x + off];
        __syncthreads();
    }
    if (threadIdx.x == 0) vqp[bn] = svals[0] / (float)D_;
}

__global__ void vq_finish(const float* __restrict__ vqp, const int* __restrict__ inds,
                          float* __restrict__ out_vq, float* __restrict__ out_inds)
{
    int b = threadIdx.x;
    if (b >= B_) return;
    float s = 0.f;
#pragma unroll
    for (int n = 0; n < ND_; n++) s += vqp[b * ND_ + n];
    out_vq[b] = 1.25f * s;
#pragma unroll
    for (int n = 0; n < ND_; n++)
        out_inds[b * ND_ + n] = (float)inds[b * ND_ + n];
}

// ---------------- launch helpers ----------------
static inline void gemm_big(const float* A, int lda, const float* W, int ldw,
                            const float* bias, float* C, int ldc, int M, int N, int K)
{
    dim3 grid((N + 127) / 128, M / 128);
    gemm_k<128, 128, 16, 8, 8><<<grid, 256>>>(A, lda, W, ldw, bias, C, ldc, N, K);
}
static inline void gemm_small(const float* A, int lda, const float* W, int ldw,
                              const float* bias, float* C, int ldc, int M, int N, int K)
{
    dim3 grid((N + 63) / 64, M / 32);
    gemm_k<32, 64, 16, 4, 4><<<grid, 128>>>(A, lda, W, ldw, bias, C, ldc, N, K);
}

extern "C" void kernel_launch(void* const* d_in, const int* in_sizes, int n_in,
                              void* d_out, int out_size)
{
    (void)in_sizes; (void)n_in; (void)out_size;
    const int*   x         = (const int*)  d_in[0];
    const float* enc_embed = (const float*)d_in[1];
    const float* enc_Wih_f = (const float*)d_in[2];
    const float* enc_Whh_f = (const float*)d_in[3];
    const float* enc_b_f   = (const float*)d_in[4];
    const float* enc_Wih_b = (const float*)d_in[5];
    const float* enc_Whh_b = (const float*)d_in[6];
    const float* enc_b_b   = (const float*)d_in[7];
    const float* enc_lin   = (const float*)d_in[8];
    const float* z2dec_W   = (const float*)d_in[9];
    const float* z2dec_b   = (const float*)d_in[10];
    const float* codebooks = (const float*)d_in[11];
    const float* suffix_W  = (const float*)d_in[12];
    const float* dec_embed = (const float*)d_in[13];
    const float* dec_Wih   = (const float*)d_in[14];
    const float* dec_Whh   = (const float*)d_in[15];
    const float* dec_b     = (const float*)d_in[16];
    const float* pred_W    = (const float*)d_in[17];

    float* out      = (float*)d_out;
    float* out_log  = out;
    float* out_vq   = out + (size_t)LOGITS_ELEMS;
    float* out_kl   = out_vq + B_;
    float* out_inds = out_kl + B_;

    float *we,*xgf,*xgb,*encA,*hfB,*hbB,*fhs,*muvar,*root,*q,*vqp,*suffix;
    float *xgd,*hd0,*cd,*decout;
    float *WfP,*WbP,*WhfP,*WhbP,*WhdP,*bfP,*bbP,*bdP;
    __nv_bfloat16 *dembH,*dembL,*WdH,*WdL,*doH,*doL,*pwH,*pwL;
    int* inds;
    cudaGetSymbolAddress((void**)&we,    g_we);
    cudaGetSymbolAddress((void**)&xgf,   g_xgf);
    cudaGetSymbolAddress((void**)&xgb,   g_xgb);
    cudaGetSymbolAddress((void**)&encA,  g_encA);
    cudaGetSymbolAddress((void**)&hfB,   g_hfB);
    cudaGetSymbolAddress((void**)&hbB,   g_hbB);
    cudaGetSymbolAddress((void**)&fhs,   g_fhs);
    cudaGetSymbolAddress((void**)&muvar, g_muvar);
    cudaGetSymbolAddress((void**)&root,  g_root);
    cudaGetSymbolAddress((void**)&inds,  g_inds);
    cudaGetSymbolAddress((void**)&q,     g_q);
    cudaGetSymbolAddress((void**)&vqp,   g_vqp);
    cudaGetSymbolAddress((void**)&suffix,g_suffix);
    cudaGetSymbolAddress((void**)&xgd,   g_xgd);
    cudaGetSymbolAddress((void**)&hd0,   g_hd0);
    cudaGetSymbolAddress((void**)&cd,    g_cd);
    cudaGetSymbolAddress((void**)&decout,g_decout);
    cudaGetSymbolAddress((void**)&WfP,   g_WfP);
    cudaGetSymbolAddress((void**)&WbP,   g_WbP);
    cudaGetSymbolAddress((void**)&WhfP,  g_WhfP);
    cudaGetSymbolAddress((void**)&WhbP,  g_WhbP);
    cudaGetSymbolAddress((void**)&WhdP,  g_WhdP);
    cudaGetSymbolAddress((void**)&bfP,   g_bfP);
    cudaGetSymbolAddress((void**)&bbP,   g_bbP);
    cudaGetSymbolAddress((void**)&bdP,   g_bdP);
    cudaGetSymbolAddress((void**)&dembH, g_dembH);
    cudaGetSymbolAddress((void**)&dembL, g_dembL);
    cudaGetSymbolAddress((void**)&WdH,   g_WdH);
    cudaGetSymbolAddress((void**)&WdL,   g_WdL);
    cudaGetSymbolAddress((void**)&doH,   g_doH);
    cudaGetSymbolAddress((void**)&doL,   g_doL);
    cudaGetSymbolAddress((void**)&pwH,   g_pwH);
    cudaGetSymbolAddress((void**)&pwL,   g_pwL);

    cudaFuncSetAttribute(hgemm2, cudaFuncAttributeMaxDynamicSharedMemorySize, 81920);

    float* hfA = encA;
    float* cf  = encA + (size_t)B_ * ENH;
    float* hbA = encA + (size_t)2 * B_ * ENH;
    float* cb  = encA + (size_t)3 * B_ * ENH;

    const int EW = 256;

    // 0) permute weights/biases; split decoder-side constants to bf16 hi/lo
    perm_w<<<(4*ENH*NI_ + EW-1)/EW, EW>>>(enc_Wih_f, WfP,  ENH, NI_);
    perm_w<<<(4*ENH*NI_ + EW-1)/EW, EW>>>(enc_Wih_b, WbP,  ENH, NI_);
    perm_w<<<(4*ENH*ENH + EW-1)/EW, EW>>>(enc_Whh_f, WhfP, ENH, ENH);
    perm_w<<<(4*ENH*ENH + EW-1)/EW, EW>>>(enc_Whh_b, WhbP, ENH, ENH);
    perm_w<<<(4*DNH*DNH + EW-1)/EW, EW>>>(dec_Whh,   WhdP, DNH, DNH);
    perm_w_split<<<(4*DNH*NI_ + EW-1)/EW, EW>>>(dec_Wih, WdH, WdL, DNH, NI_);
    perm_b<<<(4*ENH + EW-1)/EW, EW>>>(enc_b_f, bfP, ENH);
    perm_b<<<(4*ENH + EW-1)/EW, EW>>>(enc_b_b, bbP, ENH);
    perm_b<<<(4*DNH + EW-1)/EW, EW>>>(dec_b,   bdP, DNH);
    split_pad<<<((size_t)VPAD*DNH + EW-1)/EW, EW>>>(pred_W, pwH, pwL, V_, VPAD, DNH);

    // 1) encoder embedding + interleaved input-gate GEMMs (fp32)
    embed_kernel<<<(B_ * T_ * NI_ + EW - 1) / EW, EW>>>(x, enc_embed, we);
    gemm_big(we, NI_, WfP, NI_, bfP, xgf, 4 * ENH, B_ * T_, 4 * ENH, NI_);
    gemm_big(we, NI_, WbP, NI_, bbP, xgb, 4 * ENH, B_ * T_, 4 * ENH, NI_);
    cudaMemsetAsync(encA, 0, sizeof(float) * 4 * B_ * ENH, 0);

    // 2) encoder recurrence (fp32 exact)
    {
        dim3 grid(4 * ENH / 32, 2, 2);
        for (int s = 0; s < T_; s++) {
            const float* hf_in = (s & 1) ? hfB : hfA;
            float*       hf_out= (s & 1) ? hfA : hfB;
            const float* hb_in = (s & 1) ? hbB : hbA;
            float*       hb_out= (s & 1) ? hbA : hbB;
            lstm_step2<ENH><<<grid, 128>>>(
                xgf + (size_t)s * 4 * ENH, xgb + (size_t)(T_ - 1 - s) * 4 * ENH, T_ * 4 * ENH,
                WhfP, WhbP,
                hf_in, hb_in, ENH,
                cf, cb,
                hf_out, hb_out, ENH,
                nullptr, nullptr);
        }
    }
    concat_fhs<<<(B_ * 2 * ENH + EW - 1) / EW, EW>>>(hfA, hbA, fhs);

    gemm_small(fhs, 2 * ENH, enc_lin, 2 * ENH, nullptr, muvar, 2 * NZ_, B_, 2 * NZ_, 2 * ENH);
    kl_kernel<<<1, B_>>>(muvar, out_kl);
    gemm_small(muvar, 2 * NZ_, z2dec_W, NZ_, z2dec_b, root, DNH, B_, DNH, NZ_);

    vq_kernel<<<B_ * ND_, 256>>>(fhs, codebooks, inds, q, vqp);
    vq_finish<<<1, B_>>>(vqp, inds, out_vq, out_inds);

    gemm_small(q, ND_ * D_, suffix_W, ND_ * D_, nullptr, suffix, NI_, B_, NI_, ND_ * D_);
    demb_split<<<(B_ * T_ * NI_ + EW - 1) / EW, EW>>>(x, dec_embed, suffix, dembH, dembL);

    // decoder input gates: preconverted split-bf16 tensor GEMM
    {
        dim3 grid(4 * DNH / 128, (B_ * T_) / 128);
        hgemm2<<<grid, 256, 81920>>>(dembH, dembL, WdH, WdL, bdP, xgd, 4 * DNH, 4 * DNH, NI_);
    }

    dec_init<<<(B_ * DNH + EW - 1) / EW, EW>>>(root, hd0, cd);

    // decoder recurrence: fused step; h into decout (fp32) + hi/lo bf16 side outputs
    {
        dim3 grid(4 * DNH / 32, 2, 1);
        for (int s = 0; s < T_; s++) {
            const float* hin = (s == 0) ? hd0 : (decout + (size_t)(s - 1) * DNH);
            int rsHin        = (s == 0) ? DNH : (T_ * DNH);
            const float* xgs = xgd + (size_t)s * 4 * DNH;
            float* ho        = decout + (size_t)s * DNH;
            lstm_step2<DNH><<<grid, 128>>>(
                xgs, xgs, T_ * 4 * DNH,
                WhdP, WhdP,
                hin, hin, rsHin,
                cd, cd,
                ho, ho, T_ * DNH,
                doH + (size_t)s * DNH, doL + (size_t)s * DNH);
        }
    }

    // logits: preconverted split-bf16 tensor GEMM (W padded to VPAD rows)
    {
        dim3 grid(VPAD / 128, (B_ * T_) / 128);
        hgemm2<<<grid, 256, 81920>>>(doH, doL, pwH, pwL, nullptr, out_log, V_, V_, DNH);
    }
}

// round 15
// speedup vs baseline: 1.7020x; 1.1532x over previous
#include <cuda_runtime.h>
#include <cuda_bf16.h>
#include <math.h>
#include <stdint.h>

#define B_    128
#define T_    64
#define V_    10000
#define NI_   512
#define ENH   640
#define DNH   1024
#define NZ_   128
#define ND_   8
#define K_    1024
#define D_    160
#define LOGITS_ELEMS (B_ * T_ * V_)
#define VPAD  10112   // 79 * 128

// ---------------- scratch ----------------
__device__ __align__(256) float g_we   [B_ * T_ * NI_];
__device__ __align__(256) float g_xgf  [B_ * T_ * 4 * ENH];
__device__ __align__(256) float g_xgb  [B_ * T_ * 4 * ENH];
__device__ __align__(256) float g_encA [4 * B_ * ENH];   // hfA, cf, hbA, cb
__device__ __align__(256) float g_hfB  [B_ * ENH];
__device__ __align__(256) float g_hbB  [B_ * ENH];
__device__ __align__(256) float g_fhs  [B_ * 2 * ENH];
__device__ __align__(256) float g_muvar[B_ * 2 * NZ_];
__device__ __align__(256) float g_root [B_ * DNH];
__device__ __align__(256) int   g_inds [B_ * ND_];
__device__ __align__(256) float g_q    [B_ * ND_ * D_];
__device__ __align__(256) float g_vqp  [B_ * ND_];
__device__ __align__(256) float g_suffix[B_ * NI_];
__device__ __align__(256) float g_xgd  [B_ * T_ * 4 * DNH];
__device__ __align__(256) float g_hd0  [B_ * DNH];
__device__ __align__(256) float g_cd   [B_ * DNH];
__device__ __align__(256) float g_decout[B_ * T_ * DNH];
// permuted (gate-interleaved) fp32 weights/biases (encoder)
__device__ __align__(256) float g_WfP  [4 * ENH * NI_];
__device__ __align__(256) float g_WbP  [4 * ENH * NI_];
__device__ __align__(256) float g_WhfP [4 * ENH * ENH];
__device__ __align__(256) float g_WhbP [4 * ENH * ENH];
__device__ __align__(256) float g_bfP  [4 * ENH];
__device__ __align__(256) float g_bbP  [4 * ENH];
__device__ __align__(256) float g_bdP  [4 * DNH];
// preconverted bf16 hi/lo operands (decoder-side tensor path)
__device__ __align__(256) __nv_bfloat16 g_dembH[B_ * T_ * NI_];
__device__ __align__(256) __nv_bfloat16 g_dembL[B_ * T_ * NI_];
__device__ __align__(256) __nv_bfloat16 g_WdH  [4 * DNH * NI_];
__device__ __align__(256) __nv_bfloat16 g_WdL  [4 * DNH * NI_];
__device__ __align__(256) __nv_bfloat16 g_WhdH [4 * DNH * DNH];
__device__ __align__(256) __nv_bfloat16 g_WhdL [4 * DNH * DNH];
__device__ __align__(256) __nv_bfloat16 g_hd0H [B_ * DNH];
__device__ __align__(256) __nv_bfloat16 g_hd0L [B_ * DNH];
__device__ __align__(256) __nv_bfloat16 g_doH  [B_ * T_ * DNH];
__device__ __align__(256) __nv_bfloat16 g_doL  [B_ * T_ * DNH];
__device__ __align__(256) __nv_bfloat16 g_pwH  [VPAD * DNH];
__device__ __align__(256) __nv_bfloat16 g_pwL  [VPAD * DNH];

// ---------------- helpers ----------------
__device__ __forceinline__ uint32_t smem_u32(const void* p) {
    uint32_t a;
    asm("{ .reg .u64 t; cvta.to.shared.u64 t, %1; cvt.u32.u64 %0, t; }" : "=r"(a) : "l"(p));
    return a;
}
__device__ __forceinline__ void cpa16(uint32_t dst, const void* src) {
    asm volatile("cp.async.ca.shared.global [%0], [%1], 16;" :: "r"(dst), "l"(src));
}
__device__ __forceinline__ float sigf(float x) { return 1.f / (1.f + expf(-x)); }

// ---------------- weight permute: row g*H+j -> j*4+g ----------------
__global__ void perm_w(const float* __restrict__ W, float* __restrict__ Wp, int H, int K)
{
    size_t idx = (size_t)blockIdx.x * blockDim.x + threadIdx.x;
    if (idx >= (size_t)4 * H * K) return;
    int k = (int)(idx % K);
    int r = (int)(idx / K);
    int g = r / H, j = r % H;
    Wp[((size_t)j * 4 + g) * K + k] = W[idx];
}
__global__ void perm_w_split(const float* __restrict__ W,
                             __nv_bfloat16* __restrict__ WH, __nv_bfloat16* __restrict__ WL,
                             int H, int K)
{
    size_t idx = (size_t)blockIdx.x * blockDim.x + threadIdx.x;
    if (idx >= (size_t)4 * H * K) return;
    int k = (int)(idx % K);
    int r = (int)(idx / K);
    int g = r / H, j = r % H;
    float v = W[idx];
    __nv_bfloat16 h = __float2bfloat16_rn(v);
    size_t o = ((size_t)j * 4 + g) * K + k;
    WH[o] = h;
    WL[o] = __float2bfloat16_rn(v - __bfloat162float(h));
}
__global__ void perm_b(const float* __restrict__ b, float* __restrict__ bp, int H)
{
    int idx = blockIdx.x * blockDim.x + threadIdx.x;
    if (idx >= 4 * H) return;
    int g = idx / H, j = idx % H;
    bp[j * 4 + g] = b[idx];
}
__global__ void split_pad(const float* __restrict__ X,
                          __nv_bfloat16* __restrict__ H, __nv_bfloat16* __restrict__ L,
                          int rows_valid, int rows_total, int cols)
{
    size_t idx = (size_t)blockIdx.x * blockDim.x + threadIdx.x;
    if (idx >= (size_t)rows_total * cols) return;
    int r = (int)(idx / cols);
    float v = (r < rows_valid) ? X[idx] : 0.f;
    __nv_bfloat16 h = __float2bfloat16_rn(v);
    H[idx] = h;
    L[idx] = __float2bfloat16_rn(v - __bfloat162float(h));
}

// ---------------- fp32 SGEMM (encoder path; exact numerics) ----------------
template<int BM, int BN, int BK, int TM, int TN>
__global__ __launch_bounds__((BM/TM)*(BN/TN))
void gemm_k(const float* __restrict__ A, int lda,
            const float* __restrict__ W, int ldw,
            const float* __restrict__ bias,
            float* __restrict__ C, int ldc,
            int N, int K)
{
    constexpr int NT = (BM/TM)*(BN/TN);
    __shared__ __align__(16) float As[BK][BM + 4];
    __shared__ __align__(16) float Ws[BK][BN + 4];
    const int tid  = threadIdx.x;
    const int row0 = blockIdx.y * BM;
    const int col0 = blockIdx.x * BN;
    const int tr   = tid / (BN / TN);
    const int tc   = tid % (BN / TN);
    float acc[TM][TN];
#pragma unroll
    for (int i = 0; i < TM; i++)
#pragma unroll
        for (int j = 0; j < TN; j++) acc[i][j] = 0.f;
    for (int k0 = 0; k0 < K; k0 += BK) {
#pragma unroll
        for (int idx = tid * 4; idx < BM * BK; idx += NT * 4) {
            int m = idx / BK, kk = idx % BK;
            float4 v = *reinterpret_cast<const float4*>(A + (size_t)(row0 + m) * lda + (k0 + kk));
            As[kk+0][m]=v.x; As[kk+1][m]=v.y; As[kk+2][m]=v.z; As[kk+3][m]=v.w;
        }
#pragma unroll
        for (int idx = tid * 4; idx < BN * BK; idx += NT * 4) {
            int n = idx / BK, kk = idx % BK;
            float4 v = make_float4(0.f,0.f,0.f,0.f);
            if (col0 + n < N)
                v = *reinterpret_cast<const float4*>(W + (size_t)(col0 + n) * ldw + (k0 + kk));
            Ws[kk+0][n]=v.x; Ws[kk+1][n]=v.y; Ws[kk+2][n]=v.z; Ws[kk+3][n]=v.w;
        }
        __syncthreads();
#pragma unroll
        for (int kk = 0; kk < BK; kk++) {
            float ra[TM], rb[TN];
#pragma unroll
            for (int i = 0; i < TM; i += 4) {
                float4 v = *reinterpret_cast<const float4*>(&As[kk][tr*TM+i]);
                ra[i]=v.x; ra[i+1]=v.y; ra[i+2]=v.z; ra[i+3]=v.w;
            }
#pragma unroll
            for (int j = 0; j < TN; j += 4) {
                float4 v = *reinterpret_cast<const float4*>(&Ws[kk][tc*TN+j]);
                rb[j]=v.x; rb[j+1]=v.y; rb[j+2]=v.z; rb[j+3]=v.w;
            }
#pragma unroll
            for (int i = 0; i < TM; i++)
#pragma unroll
                for (int j = 0; j < TN; j++)
                    acc[i][j] = fmaf(ra[i], rb[j], acc[i][j]);
        }
        __syncthreads();
    }
#pragma unroll
    for (int i = 0; i < TM; i++) {
        int m = row0 + tr*TM + i;
#pragma unroll
        for (int j = 0; j < TN; j++) {
            int n = col0 + tc*TN + j;
            if (n < N) {
                float v = acc[i][j];
                if (bias) v += bias[n];
                C[(size_t)m * ldc + n] = v;
            }
        }
    }
}

// ---------------- split-bf16 tensor GEMM (preconverted + cp.async, 128x128) ----------------
#define MMA_BF16(CC, AA, BB)                                                     \
    asm volatile("mma.sync.aligned.m16n8k16.row.col.f32.bf16.bf16.f32 "          \
        "{%0,%1,%2,%3}, {%4,%5,%6,%7}, {%8,%9}, {%0,%1,%2,%3};"                  \
        : "+f"(CC[0]), "+f"(CC[1]), "+f"(CC[2]), "+f"(CC[3])                     \
        : "r"(AA[0]), "r"(AA[1]), "r"(AA[2]), "r"(AA[3]), "r"(BB[0]), "r"(BB[1]))

__global__ __launch_bounds__(256)
void hgemm2(const __nv_bfloat16* __restrict__ AH, const __nv_bfloat16* __restrict__ AL,
            const __nv_bfloat16* __restrict__ WH, const __nv_bfloat16* __restrict__ WL,
            const float* __restrict__ bias,
            float* __restrict__ C, int ldc, int N, int K)
{
    extern __shared__ __align__(16) __nv_bfloat16 dsm[];
    const int tid  = threadIdx.x;
    const int warp = tid >> 5, lane = tid & 31;
    const int wm = warp >> 2, wn = warp & 3;
    const int row0 = blockIdx.y * 128, col0 = blockIdx.x * 128;
    const int g = lane >> 2, q = lane & 3;
    const uint32_t sbase = smem_u32(dsm);
    const int ntiles = K >> 5;

    float acc[4][4][4];
#pragma unroll
    for (int a = 0; a < 4; a++)
#pragma unroll
        for (int b = 0; b < 4; b++)
#pragma unroll
            for (int c = 0; c < 4; c++) acc[a][b][c] = 0.f;

    auto issue_loads = [&](int stage, int t) {
        uint32_t sb = sbase + stage * 40960u;
        int k0 = t << 5;
        for (int i = tid; i < 512; i += 256) {
            int r = i >> 2, c8 = (i & 3) << 3;
            uint32_t off = (uint32_t)(r * 40 + c8) * 2;
            cpa16(sb + off,          AH + (size_t)(row0 + r) * K + k0 + c8);
            cpa16(sb + 10240 + off,  AL + (size_t)(row0 + r) * K + k0 + c8);
            cpa16(sb + 20480 + off,  WH + (size_t)(col0 + r) * K + k0 + c8);
            cpa16(sb + 30720 + off,  WL + (size_t)(col0 + r) * K + k0 + c8);
        }
    };

    issue_loads(0, 0);
    asm volatile("cp.async.commit_group;" ::: "memory");

    for (int t = 0; t < ntiles; t++) {
        if (t + 1 < ntiles) {
            issue_loads((t + 1) & 1, t + 1);
            asm volatile("cp.async.commit_group;" ::: "memory");
            asm volatile("cp.async.wait_group 1;" ::: "memory");
        } else {
            asm volatile("cp.async.wait_group 0;" ::: "memory");
        }
        __syncthreads();
        const __nv_bfloat16* Ah = dsm + (size_t)(t & 1) * 20480;
        const __nv_bfloat16* Al = Ah + 5120;
        const __nv_bfloat16* Wh = Ah + 10240;
        const __nv_bfloat16* Wl = Ah + 15360;
#pragma unroll
        for (int ks = 0; ks < 32; ks += 16) {
            uint32_t ah[4][4], al[4][4], bh[4][2], bl[4][2];
#pragma unroll
            for (int mi = 0; mi < 4; mi++) {
                int r = wm*64 + mi*16 + g;
                ah[mi][0] = *reinterpret_cast<const uint32_t*>(&Ah[(r  )*40 + ks + 2*q    ]);
                ah[mi][1] = *reinterpret_cast<const uint32_t*>(&Ah[(r+8)*40 + ks + 2*q    ]);
                ah[mi][2] = *reinterpret_cast<const uint32_t*>(&Ah[(r  )*40 + ks + 2*q + 8]);
                ah[mi][3] = *reinterpret_cast<const uint32_t*>(&Ah[(r+8)*40 + ks + 2*q + 8]);
                al[mi][0] = *reinterpret_cast<const uint32_t*>(&Al[(r  )*40 + ks + 2*q    ]);
                al[mi][1] = *reinterpret_cast<const uint32_t*>(&Al[(r+8)*40 + ks + 2*q    ]);
                al[mi][2] = *reinterpret_cast<const uint32_t*>(&Al[(r  )*40 + ks + 2*q + 8]);
                al[mi][3] = *reinterpret_cast<const uint32_t*>(&Al[(r+8)*40 + ks + 2*q + 8]);
            }
#pragma unroll
            for (int ni = 0; ni < 4; ni++) {
                int c = wn*32 + ni*8 + g;
                bh[ni][0] = *reinterpret_cast<const uint32_t*>(&Wh[c*40 + ks + 2*q    ]);
                bh[ni][1] = *reinterpret_cast<const uint32_t*>(&Wh[c*40 + ks + 2*q + 8]);
                bl[ni][0] = *reinterpret_cast<const uint32_t*>(&Wl[c*40 + ks + 2*q    ]);
                bl[ni][1] = *reinterpret_cast<const uint32_t*>(&Wl[c*40 + ks + 2*q + 8]);
            }
#pragma unroll
            for (int mi = 0; mi < 4; mi++)
#pragma unroll
                for (int ni = 0; ni < 4; ni++) {
                    MMA_BF16(acc[mi][ni], ah[mi], bh[ni]);
                    MMA_BF16(acc[mi][ni], ah[mi], bl[ni]);
                    MMA_BF16(acc[mi][ni], al[mi], bh[ni]);
                }
        }
        __syncthreads();
    }

#pragma unroll
    for (int mi = 0; mi < 4; mi++) {
        int r = row0 + wm*64 + mi*16 + g;
#pragma unroll
        for (int ni = 0; ni < 4; ni++) {
            int c = col0 + wn*32 + ni*8 + 2*q;
            float b0 = 0.f, b1 = 0.f;
            if (bias) {
                if (c < N)     b0 = bias[c];
                if (c + 1 < N) b1 = bias[c+1];
            }
            if (c < N) {
                C[(size_t)r * ldc + c]     = acc[mi][ni][0] + b0;
                C[(size_t)(r+8) * ldc + c] = acc[mi][ni][2] + b0;
            }
            if (c + 1 < N) {
                C[(size_t)r * ldc + c + 1]     = acc[mi][ni][1] + b1;
                C[(size_t)(r+8) * ldc + c + 1] = acc[mi][ni][3] + b1;
            }
        }
    }
}

// ---------------- decoder LSTM step on tensor cores (fused epilogue) ----------------
// Tile 64(batch) x 64(gate-interleaved cols); 128 threads = 4 warps (2x2),
// warp tile 32x32 = (2 mi x 16) x (4 ni x 8). K = DNH, 32 per stage, double buffered.
// Gate quad (i,f | g,o) split across lane partners (lane^1); cell update fused via shfl.
__global__ __launch_bounds__(128)
void lstm_tc_step(const __nv_bfloat16* __restrict__ AH, const __nv_bfloat16* __restrict__ AL, int rsA,
                  const __nv_bfloat16* __restrict__ WH, const __nv_bfloat16* __restrict__ WL,
                  const float* __restrict__ xg, int rsXG,
                  float* __restrict__ cp,
                  float* __restrict__ hout, int rsH,
                  __nv_bfloat16* __restrict__ hHo, __nv_bfloat16* __restrict__ hLo)
{
    __shared__ __align__(16) __nv_bfloat16 sm[2 * 4 * 2560];   // 2 stages x 4 arrays x 64*40
    const int tid  = threadIdx.x;
    const int warp = tid >> 5, lane = tid & 31;
    const int wm = warp >> 1, wn = warp & 1;
    const int g = lane >> 2, q = lane & 3;
    const int row0 = blockIdx.y * 64, col0 = blockIdx.x * 64;
    const uint32_t sb0 = smem_u32(sm);
    const int ntiles = DNH >> 5;

    float acc[2][4][4];
#pragma unroll
    for (int a = 0; a < 2; a++)
#pragma unroll
        for (int b = 0; b < 4; b++)
#pragma unroll
            for (int c = 0; c < 4; c++) acc[a][b][c] = 0.f;

    auto issue_loads = [&](int stage, int t) {
        uint32_t sb = sb0 + stage * 20480u;
        int k0 = t << 5;
        for (int i = tid; i < 256; i += 128) {
            int r = i >> 2, c8 = (i & 3) << 3;
            uint32_t off = (uint32_t)(r * 40 + c8) * 2;
            cpa16(sb + off,          AH + (size_t)(row0 + r) * rsA + k0 + c8);
            cpa16(sb + 5120 + off,   AL + (size_t)(row0 + r) * rsA + k0 + c8);
            cpa16(sb + 10240 + off,  WH + (size_t)(col0 + r) * DNH + k0 + c8);
            cpa16(sb + 15360 + off,  WL + (size_t)(col0 + r) * DNH + k0 + c8);
        }
    };

    issue_loads(0, 0);
    asm volatile("cp.async.commit_group;" ::: "memory");

    for (int t = 0; t < ntiles; t++) {
        if (t + 1 < ntiles) {
            issue_loads((t + 1) & 1, t + 1);
            asm volatile("cp.async.commit_group;" ::: "memory");
            asm volatile("cp.async.wait_group 1;" ::: "memory");
        } else {
            asm volatile("cp.async.wait_group 0;" ::: "memory");
        }
        __syncthreads();
        const __nv_bfloat16* Ah = sm + (size_t)(t & 1) * 10240;
        const __nv_bfloat16* Al = Ah + 2560;
        const __nv_bfloat16* Wh = Ah + 5120;
        const __nv_bfloat16* Wl = Ah + 7680;
#pragma unroll
        for (int ks = 0; ks < 32; ks += 16) {
            uint32_t ah[2][4], al[2][4], bh[4][2], bl[4][2];
#pragma unroll
            for (int mi = 0; mi < 2; mi++) {
                int r = wm*32 + mi*16 + g;
                ah[mi][0] = *reinterpret_cast<const uint32_t*>(&Ah[(r  )*40 + ks + 2*q    ]);
                ah[mi][1] = *reinterpret_cast<const uint32_t*>(&Ah[(r+8)*40 + ks + 2*q    ]);
                ah[mi][2] = *reinterpret_cast<const uint32_t*>(&Ah[(r  )*40 + ks + 2*q + 8]);
                ah[mi][3] = *reinterpret_cast<const uint32_t*>(&Ah[(r+8)*40 + ks + 2*q + 8]);
                al[mi][0] = *reinterpret_cast<const uint32_t*>(&Al[(r  )*40 + ks + 2*q    ]);
                al[mi][1] = *reinterpret_cast<const uint32_t*>(&Al[(r+8)*40 + ks + 2*q    ]);
                al[mi][2] = *reinterpret_cast<const uint32_t*>(&Al[(r  )*40 + ks + 2*q + 8]);
                al[mi][3] = *reinterpret_cast<const uint32_t*>(&Al[(r+8)*40 + ks + 2*q + 8]);
            }
#pragma unroll
            for (int ni = 0; ni < 4; ni++) {
                int c = wn*32 + ni*8 + g;
                bh[ni][0] = *reinterpret_cast<const uint32_t*>(&Wh[c*40 + ks + 2*q    ]);
                bh[ni][1] = *reinterpret_cast<const uint32_t*>(&Wh[c*40 + ks + 2*q + 8]);
                bl[ni][0] = *reinterpret_cast<const uint32_t*>(&Wl[c*40 + ks + 2*q    ]);
                bl[ni][1] = *reinterpret_cast<const uint32_t*>(&Wl[c*40 + ks + 2*q + 8]);
            }
#pragma unroll
            for (int mi = 0; mi < 2; mi++)
#pragma unroll
                for (int ni = 0; ni < 4; ni++) {
                    MMA_BF16(acc[mi][ni], ah[mi], bh[ni]);
                    MMA_BF16(acc[mi][ni], ah[mi], bl[ni]);
                    MMA_BF16(acc[mi][ni], al[mi], bh[ni]);
                }
        }
        __syncthreads();
    }

    // fused LSTM cell update. cols gate-interleaved: c=4j+{0,1,2,3} = i,f,g,o.
    // even-q thread holds (i,f) of unit j; lane^1 partner holds (g,o) of same j.
#pragma unroll
    for (int mi = 0; mi < 2; mi++) {
#pragma unroll
        for (int rr = 0; rr < 2; rr++) {
            int b = row0 + wm*32 + mi*16 + g + rr*8;
#pragma unroll
            for (int ni = 0; ni < 4; ni++) {
                int c = col0 + wn*32 + ni*8 + 2*q;
                float v0 = acc[mi][ni][rr*2 + 0] + xg[(size_t)b * rsXG + c];
                float v1 = acc[mi][ni][rr*2 + 1] + xg[(size_t)b * rsXG + c + 1];
                float p0 = __shfl_xor_sync(0xffffffffu, v0, 1);
                float p1 = __shfl_xor_sync(0xffffffffu, v1, 1);
                if (!(lane & 1)) {
                    int j = c >> 2;
                    size_t ci = (size_t)b * DNH + j;
                    float cc = sigf(v1) * cp[ci] + sigf(v0) * tanhf(p0);
                    cp[ci] = cc;
                    float hv = sigf(p1) * tanhf(cc);
                    size_t ho = (size_t)b * rsH + j;
                    hout[ho] = hv;
                    __nv_bfloat16 hh = __float2bfloat16_rn(hv);
                    hHo[ho] = hh;
                    hLo[ho] = __float2bfloat16_rn(hv - __bfloat162float(hh));
                }
            }
        }
    }
}

// ---------------- fused LSTM step, gate-interleaved (fp32, encoder) ----------------
template<int H>
__global__ __launch_bounds__(128)
void lstm_step2(const float* __restrict__ xgA, const float* __restrict__ xgB, int rsXG,
                const float* __restrict__ WA,  const float* __restrict__ WB,
                const float* __restrict__ hinA, const float* __restrict__ hinB, int rsHin,
                float* __restrict__ cA, float* __restrict__ cB,
                float* __restrict__ houtA, float* __restrict__ houtB, int rsHout)
{
    const float* xg  = blockIdx.z ? xgB  : xgA;
    const float* W   = blockIdx.z ? WB   : WA;
    const float* hin = blockIdx.z ? hinB : hinA;
    float* cp   = blockIdx.z ? cB : cA;
    float* hout = blockIdx.z ? houtB : houtA;

    __shared__ __align__(16) float As[16][68];
    __shared__ __align__(16) float Ws[16][36];
    const int tid = threadIdx.x;
    const int tr = tid >> 3, tc = tid & 7;
    const int row0 = blockIdx.y * 64;
    const int col0 = blockIdx.x * 32;

    float acc[4][4];
#pragma unroll
    for (int i = 0; i < 4; i++)
#pragma unroll
        for (int j = 0; j < 4; j++) acc[i][j] = 0.f;

    for (int k0 = 0; k0 < H; k0 += 16) {
        __syncthreads();
#pragma unroll
        for (int i = tid * 4; i < 64 * 16; i += 128 * 4) {
            int r = i >> 4, kk = i & 15;
            float4 v = *reinterpret_cast<const float4*>(&hin[(size_t)(row0 + r) * rsHin + k0 + kk]);
            As[kk+0][r]=v.x; As[kk+1][r]=v.y; As[kk+2][r]=v.z; As[kk+3][r]=v.w;
        }
        {
            int i = tid * 4;
            int r = i >> 4, kk = i & 15;
            float4 v = *reinterpret_cast<const float4*>(&W[(size_t)(col0 + r) * H + k0 + kk]);
            Ws[kk+0][r]=v.x; Ws[kk+1][r]=v.y; Ws[kk+2][r]=v.z; Ws[kk+3][r]=v.w;
        }
        __syncthreads();
#pragma unroll
        for (int kk = 0; kk < 16; kk++) {
            float4 ra = *reinterpret_cast<const float4*>(&As[kk][tr * 4]);
            float4 rb = *reinterpret_cast<const float4*>(&Ws[kk][tc * 4]);
            acc[0][0]=fmaf(ra.x,rb.x,acc[0][0]); acc[0][1]=fmaf(ra.x,rb.y,acc[0][1]);
            acc[0][2]=fmaf(ra.x,rb.z,acc[0][2]); acc[0][3]=fmaf(ra.x,rb.w,acc[0][3]);
            acc[1][0]=fmaf(ra.y,rb.x,acc[1][0]); acc[1][1]=fmaf(ra.y,rb.y,acc[1][1]);
            acc[1][2]=fmaf(ra.y,rb.z,acc[1][2]); acc[1][3]=fmaf(ra.y,rb.w,acc[1][3]);
            acc[2][0]=fmaf(ra.z,rb.x,acc[2][0]); acc[2][1]=fmaf(ra.z,rb.y,acc[2][1]);
            acc[2][2]=fmaf(ra.z,rb.z,acc[2][2]); acc[2][3]=fmaf(ra.z,rb.w,acc[2][3]);
            acc[3][0]=fmaf(ra.w,rb.x,acc[3][0]); acc[3][1]=fmaf(ra.w,rb.y,acc[3][1]);
            acc[3][2]=fmaf(ra.w,rb.z,acc[3][2]); acc[3][3]=fmaf(ra.w,rb.w,acc[3][3]);
        }
    }

    const int col = col0 + tc * 4;
    const int j   = col >> 2;
#pragma unroll
    for (int i = 0; i < 4; i++) {
        int b = row0 + tr * 4 + i;
        float4 xv = *reinterpret_cast<const float4*>(&xg[(size_t)b * rsXG + col]);
        float gi = acc[i][0] + xv.x;
        float gf = acc[i][1] + xv.y;
        float gg = acc[i][2] + xv.z;
        float go = acc[i][3] + xv.w;
        size_t ci = (size_t)b * H + j;
        float cc = sigf(gf) * cp[ci] + sigf(gi) * tanhf(gg);
        cp[ci] = cc;
        hout[(size_t)b * rsHout + j] = sigf(go) * tanhf(cc);
    }
}

// ---------------- elementwise / small kernels ----------------
__global__ void embed_kernel(const int* __restrict__ x, const float* __restrict__ emb,
                             float* __restrict__ out)
{
    size_t idx = (size_t)blockIdx.x * blockDim.x + threadIdx.x;
    if (idx >= (size_t)B_ * T_ * NI_) return;
    int i = (int)(idx % NI_), bt = (int)(idx / NI_);
    out[idx] = emb[(size_t)x[bt] * NI_ + i];
}

__global__ void demb_split(const int* __restrict__ x, const float* __restrict__ emb,
                           const float* __restrict__ suffix,
                           __nv_bfloat16* __restrict__ H, __nv_bfloat16* __restrict__ L)
{
    size_t idx = (size_t)blockIdx.x * blockDim.x + threadIdx.x;
    if (idx >= (size_t)B_ * T_ * NI_) return;
    int i = (int)(idx % NI_), bt = (int)(idx / NI_);
    int b = bt / T_;
    float v = emb[(size_t)x[bt] * NI_ + i] + suffix[(size_t)b * NI_ + i];
    __nv_bfloat16 h = __float2bfloat16_rn(v);
    H[idx] = h;
    L[idx] = __float2bfloat16_rn(v - __bfloat162float(h));
}

__global__ void concat_fhs(const float* __restrict__ hf, const float* __restrict__ hb,
                           float* __restrict__ fhs)
{
    int idx = blockIdx.x * blockDim.x + threadIdx.x;
    if (idx >= B_ * 2 * ENH) return;
    int b = idx / (2 * ENH), j = idx % (2 * ENH);
    fhs[idx] = (j < ENH) ? hf[(size_t)b * ENH + j] : hb[(size_t)b * ENH + (j - ENH)];
}

__global__ void kl_kernel(const float* __restrict__ muvar, float* __restrict__ out_kl)
{
    int b = threadIdx.x;
    if (b >= B_) return;
    float s = 0.f;
    const float* row = muvar + (size_t)b * 2 * NZ_;
    for (int j = 0; j < NZ_; j++) {
        float mu = row[j], lv = row[NZ_ + j];
        s += mu * mu + expf(lv) - lv - 1.f;
    }
    out_kl[b] = 0.5f * s;
}

__global__ void dec_init(const float* __restrict__ root, float* __restrict__ h0,
                         float* __restrict__ c0,
                         __nv_bfloat16* __restrict__ hH, __nv_bfloat16* __restrict__ hL)
{
    int idx = blockIdx.x * blockDim.x + threadIdx.x;
    if (idx >= B_ * DNH) return;
    float r = root[idx];
    float hv = tanhf(r);
    h0[idx] = hv;
    c0[idx] = r;
    __nv_bfloat16 hh = __float2bfloat16_rn(hv);
    hH[idx] = hh;
    hL[idx] = __float2bfloat16_rn(hv - __bfloat162float(hh));
}

__global__ void vq_kernel(const float* __restrict__ fhs, const float* __restrict__ cb,
                          int* __restrict__ inds, float* __restrict__ q,
                          float* __restrict__ vqp)
{
    const int bn = blockIdx.x;
    const int b = bn / ND_, n = bn % ND_;
    __shared__ __align__(16) float lat[D_];
    __shared__ float svals[256];
    __shared__ int   sidx[256];
    const float* latg = fhs + (size_t)b * (ND_ * D_) + (size_t)n * D_;
    for (int d = threadIdx.x; d < D_; d += 256) lat[d] = latg[d];
    __syncthreads();
    float best = INFINITY; int bidx = K_;
    const float* cbn = cb + (size_t)n * K_ * D_;
    for (int k = threadIdx.x; k < K_; k += 256) {
        const float4* ck = reinterpret_cast<const float4*>(cbn + (size_t)k * D_);
        float t1 = 0.f, t2 = 0.f;
#pragma unroll
        for (int d4 = 0; d4 < D_ / 4; d4++) {
            float4 cv = ck[d4];
            const float4 lv = *reinterpret_cast<const float4*>(&lat[d4 * 4]);
            t1 = fmaf(cv.x, cv.x, t1); t2 = fmaf(cv.x, lv.x, t2);
            t1 = fmaf(cv.y, cv.y, t1); t2 = fmaf(cv.y, lv.y, t2);
            t1 = fmaf(cv.z, cv.z, t1); t2 = fmaf(cv.z, lv.z, t2);
            t1 = fmaf(cv.w, cv.w, t1); t2 = fmaf(cv.w, lv.w, t2);
        }
        float dist = t1 - 2.f * t2;
        if (dist < best || (dist == best && k < bidx)) { best = dist; bidx = k; }
    }
    svals[threadIdx.x] = best; sidx[threadIdx.x] = bidx;
    __syncthreads();
    for (int off = 128; off > 0; off >>= 1) {
        if (threadIdx.x < off) {
            float v = svals[threadIdx.x + off]; int i2 = sidx[threadIdx.x + off];
            if (v < svals[threadIdx.x] || (v == svals[threadIdx.x] && i2 < sidx[threadIdx.x])) {
                svals[threadIdx.x] = v; sidx[threadIdx.x] = i2;
            }
        }
        __syncthreads();
    }
    const int kmin = sidx[0];
    if (threadIdx.x == 0) inds[bn] = kmin;
    __syncthreads();
    const float* ck = cbn + (size_t)kmin * D_;
    float part = 0.f;
    for (int d = threadIdx.x; d < D_; d += 256) {
        float qv = ck[d], lv = lat[d];
        float diff = qv - lv;
        q[(size_t)bn * D_ + d] = lv + diff;
        part += diff * diff;
    }
    svals[threadIdx.x] = part;
    __syncthreads();
    for (int off = 128; off > 0; off >>= 1) {
        if (threadIdx.x < off) svals[threadIdx.x] += svals[threadIdx.x + off];
        __syncthreads();
    }
    if (threadIdx.x == 0) vqp[bn] = svals[0] / (float)D_;
}

__global__ void vq_finish(const float* __restrict__ vqp, const int* __restrict__ inds,
                          float* __restrict__ out_vq, float* __restrict__ out_inds)
{
    int b = threadIdx.x;
    if (b >= B_) return;
    float s = 0.f;
#pragma unroll
    for (int n = 0; n < ND_; n++) s += vqp[b * ND_ + n];
    out_vq[b] = 1.25f * s;
#pragma unroll
    for (int n = 0; n < ND_; n++)
        out_inds[b * ND_ + n] = (float)inds[b * ND_ + n];
}

// ---------------- launch helpers ----------------
static inline void gemm_big(const float* A, int lda, const float* W, int ldw,
                            const float* bias, float* C, int ldc, int M, int N, int K)
{
    dim3 grid((N + 127) / 128, M / 128);
    gemm_k<128, 128, 16, 8, 8><<<grid, 256>>>(A, lda, W, ldw, bias, C, ldc, N, K);
}
static inline void gemm_small(const float* A, int lda, const float* W, int ldw,
                              const float* bias, float* C, int ldc, int M, int N, int K)
{
    dim3 grid((N + 63) / 64, M / 32);
    gemm_k<32, 64, 16, 4, 4><<<grid, 128>>>(A, lda, W, ldw, bias, C, ldc, N, K);
}

extern "C" void kernel_launch(void* const* d_in, const int* in_sizes, int n_in,
                              void* d_out, int out_size)
{
    (void)in_sizes; (void)n_in; (void)out_size;
    const int*   x         = (const int*)  d_in[0];
    const float* enc_embed = (const float*)d_in[1];
    const float* enc_Wih_f = (const float*)d_in[2];
    const float* enc_Whh_f = (const float*)d_in[3];
    const float* enc_b_f   = (const float*)d_in[4];
    const float* enc_Wih_b = (const float*)d_in[5];
    const float* enc_Whh_b = (const float*)d_in[6];
    const float* enc_b_b   = (const float*)d_in[7];
    const float* enc_lin   = (const float*)d_in[8];
    const float* z2dec_W   = (const float*)d_in[9];
    const float* z2dec_b   = (const float*)d_in[10];
    const float* codebooks = (const float*)d_in[11];
    const float* suffix_W  = (const float*)d_in[12];
    const float* dec_embed = (const float*)d_in[13];
    const float* dec_Wih   = (const float*)d_in[14];
    const float* dec_Whh   = (const float*)d_in[15];
    const float* dec_b     = (const float*)d_in[16];
    const float* pred_W    = (const float*)d_in[17];

    float* out      = (float*)d_out;
    float* out_log  = out;
    float* out_vq   = out + (size_t)LOGITS_ELEMS;
    float* out_kl   = out_vq + B_;
    float* out_inds = out_kl + B_;

    float *we,*xgf,*xgb,*encA,*hfB,*hbB,*fhs,*muvar,*root,*q,*vqp,*suffix;
    float *xgd,*hd0,*cd,*decout;
    float *WfP,*WbP,*WhfP,*WhbP,*bfP,*bbP,*bdP;
    __nv_bfloat16 *dembH,*dembL,*WdH,*WdL,*WhdH,*WhdL,*hd0H,*hd0L,*doH,*doL,*pwH,*pwL;
    int* inds;
    cudaGetSymbolAddress((void**)&we,    g_we);
    cudaGetSymbolAddress((void**)&xgf,   g_xgf);
    cudaGetSymbolAddress((void**)&xgb,   g_xgb);
    cudaGetSymbolAddress((void**)&encA,  g_encA);
    cudaGetSymbolAddress((void**)&hfB,   g_hfB);
    cudaGetSymbolAddress((void**)&hbB,   g_hbB);
    cudaGetSymbolAddress((void**)&fhs,   g_fhs);
    cudaGetSymbolAddress((void**)&muvar, g_muvar);
    cudaGetSymbolAddress((void**)&root,  g_root);
    cudaGetSymbolAddress((void**)&inds,  g_inds);
    cudaGetSymbolAddress((void**)&q,     g_q);
    cudaGetSymbolAddress((void**)&vqp,   g_vqp);
    cudaGetSymbolAddress((void**)&suffix,g_suffix);
    cudaGetSymbolAddress((void**)&xgd,   g_xgd);
    cudaGetSymbolAddress((void**)&hd0,   g_hd0);
    cudaGetSymbolAddress((void**)&cd,    g_cd);
    cudaGetSymbolAddress((void**)&decout,g_decout);
    cudaGetSymbolAddress((void**)&WfP,   g_WfP);
    cudaGetSymbolAddress((void**)&WbP,   g_WbP);
    cudaGetSymbolAddress((void**)&WhfP,  g_WhfP);
    cudaGetSymbolAddress((void**)&WhbP,  g_WhbP);
    cudaGetSymbolAddress((void**)&bfP,   g_bfP);
    cudaGetSymbolAddress((void**)&bbP,   g_bbP);
    cudaGetSymbolAddress((void**)&bdP,   g_bdP);
    cudaGetSymbolAddress((void**)&dembH, g_dembH);
    cudaGetSymbolAddress((void**)&dembL, g_dembL);
    cudaGetSymbolAddress((void**)&WdH,   g_WdH);
    cudaGetSymbolAddress((void**)&WdL,   g_WdL);
    cudaGetSymbolAddress((void**)&WhdH,  g_WhdH);
    cudaGetSymbolAddress((void**)&WhdL,  g_WhdL);
    cudaGetSymbolAddress((void**)&hd0H,  g_hd0H);
    cudaGetSymbolAddress((void**)&hd0L,  g_hd0L);
    cudaGetSymbolAddress((void**)&doH,   g_doH);
    cudaGetSymbolAddress((void**)&doL,   g_doL);
    cudaGetSymbolAddress((void**)&pwH,   g_pwH);
    cudaGetSymbolAddress((void**)&pwL,   g_pwL);

    cudaFuncSetAttribute(hgemm2, cudaFuncAttributeMaxDynamicSharedMemorySize, 81920);

    float* hfA = encA;
    float* cf  = encA + (size_t)B_ * ENH;
    float* hbA = encA + (size_t)2 * B_ * ENH;
    float* cb  = encA + (size_t)3 * B_ * ENH;

    const int EW = 256;

    // 0) permute weights/biases; split decoder-side constants to bf16 hi/lo
    perm_w<<<(4*ENH*NI_ + EW-1)/EW, EW>>>(enc_Wih_f, WfP,  ENH, NI_);
    perm_w<<<(4*ENH*NI_ + EW-1)/EW, EW>>>(enc_Wih_b, WbP,  ENH, NI_);
    perm_w<<<(4*ENH*ENH + EW-1)/EW, EW>>>(enc_Whh_f, WhfP, ENH, ENH);
    perm_w<<<(4*ENH*ENH + EW-1)/EW, EW>>>(enc_Whh_b, WhbP, ENH, ENH);
    perm_w_split<<<(4*DNH*DNH + EW-1)/EW, EW>>>(dec_Whh, WhdH, WhdL, DNH, DNH);
    perm_w_split<<<(4*DNH*NI_ + EW-1)/EW, EW>>>(dec_Wih, WdH, WdL, DNH, NI_);
    perm_b<<<(4*ENH + EW-1)/EW, EW>>>(enc_b_f, bfP, ENH);
    perm_b<<<(4*ENH + EW-1)/EW, EW>>>(enc_b_b, bbP, ENH);
    perm_b<<<(4*DNH + EW-1)/EW, EW>>>(dec_b,   bdP, DNH);
    split_pad<<<((size_t)VPAD*DNH + EW-1)/EW, EW>>>(pred_W, pwH, pwL, V_, VPAD, DNH);

    // 1) encoder embedding + interleaved input-gate GEMMs (fp32)
    embed_kernel<<<(B_ * T_ * NI_ + EW - 1) / EW, EW>>>(x, enc_embed, we);
    gemm_big(we, NI_, WfP, NI_, bfP, xgf, 4 * ENH, B_ * T_, 4 * ENH, NI_);
    gemm_big(we, NI_, WbP, NI_, bbP, xgb, 4 * ENH, B_ * T_, 4 * ENH, NI_);
    cudaMemsetAsync(encA, 0, sizeof(float) * 4 * B_ * ENH, 0);

    // 2) encoder recurrence (fp32 exact)
    {
        dim3 grid(4 * ENH / 32, 2, 2);
        for (int s = 0; s < T_; s++) {
            const float* hf_in = (s & 1) ? hfB : hfA;
            float*       hf_out= (s & 1) ? hfA : hfB;
            const float* hb_in = (s & 1) ? hbB : hbA;
            float*       hb_out= (s & 1) ? hbA : hbB;
            lstm_step2<ENH><<<grid, 128>>>(
                xgf + (size_t)s * 4 * ENH, xgb + (size_t)(T_ - 1 - s) * 4 * ENH, T_ * 4 * ENH,
                WhfP, WhbP,
                hf_in, hb_in, ENH,
                cf, cb,
                hf_out, hb_out, ENH);
        }
    }
    concat_fhs<<<(B_ * 2 * ENH + EW - 1) / EW, EW>>>(hfA, hbA, fhs);

    gemm_small(fhs, 2 * ENH, enc_lin, 2 * ENH, nullptr, muvar, 2 * NZ_, B_, 2 * NZ_, 2 * ENH);
    kl_kernel<<<1, B_>>>(muvar, out_kl);
    gemm_small(muvar, 2 * NZ_, z2dec_W, NZ_, z2dec_b, root, DNH, B_, DNH, NZ_);

    vq_kernel<<<B_ * ND_, 256>>>(fhs, codebooks, inds, q, vqp);
    vq_finish<<<1, B_>>>(vqp, inds, out_vq, out_inds);

    gemm_small(q, ND_ * D_, suffix_W, ND_ * D_, nullptr, suffix, NI_, B_, NI_, ND_ * D_);
    demb_split<<<(B_ * T_ * NI_ + EW - 1) / EW, EW>>>(x, dec_embed, suffix, dembH, dembL);

    // decoder input gates: preconverted split-bf16 tensor GEMM
    {
        dim3 grid(4 * DNH / 128, (B_ * T_) / 128);
        hgemm2<<<grid, 256, 81920>>>(dembH, dembL, WdH, WdL, bdP, xgd, 4 * DNH, 4 * DNH, NI_);
    }

    dec_init<<<(B_ * DNH + EW - 1) / EW, EW>>>(root, hd0, cd, hd0H, hd0L);

    // decoder recurrence: tensor-core fused step (64x64 tiles, 128 blocks)
    {
        dim3 grid(4 * DNH / 64, B_ / 64);
        for (int s = 0; s < T_; s++) {
            const __nv_bfloat16* aH = (s == 0) ? hd0H : (doH + (size_t)(s - 1) * DNH);
            const __nv_bfloat16* aL = (s == 0) ? hd0L : (doL + (size_t)(s - 1) * DNH);
            int rsA                 = (s == 0) ? DNH : (T_ * DNH);
            lstm_tc_step<<<grid, 128>>>(
                aH, aL, rsA,
                WhdH, WhdL,
                xgd + (size_t)s * 4 * DNH, T_ * 4 * DNH,
                cd,
                decout + (size_t)s * DNH, T_ * DNH,
                doH + (size_t)s * DNH, doL + (size_t)s * DNH);
        }
    }

    // logits: preconverted split-bf16 tensor GEMM (W padded to VPAD rows)
    {
        dim3 grid(VPAD / 128, (B_ * T_) / 128);
        hgemm2<<<grid, 256, 81920>>>(doH, doL, pwH, pwL, nullptr, out_log, V_, V_, DNH);
    }
}

// round 16
// speedup vs baseline: 1.7791x; 1.0453x over previous
#include <cuda_runtime.h>
#include <cuda_bf16.h>
#include <math.h>
#include <stdint.h>

#define B_    128
#define T_    64
#define V_    10000
#define NI_   512
#define ENH   640
#define DNH   1024
#define NZ_   128
#define ND_   8
#define K_    1024
#define D_    160
#define LOGITS_ELEMS (B_ * T_ * V_)
#define VPAD  10112   // 79 * 128

// ---------------- scratch ----------------
__device__ __align__(256) float g_we   [B_ * T_ * NI_];
__device__ __align__(256) float g_xgf  [B_ * T_ * 4 * ENH];
__device__ __align__(256) float g_xgb  [B_ * T_ * 4 * ENH];
__device__ __align__(256) float g_encA [4 * B_ * ENH];   // hfA, cf, hbA, cb
__device__ __align__(256) float g_hfB  [B_ * ENH];
__device__ __align__(256) float g_hbB  [B_ * ENH];
__device__ __align__(256) float g_fhs  [B_ * 2 * ENH];
__device__ __align__(256) float g_muvar[B_ * 2 * NZ_];
__device__ __align__(256) float g_root [B_ * DNH];
__device__ __align__(256) int   g_inds [B_ * ND_];
__device__ __align__(256) float g_q    [B_ * ND_ * D_];
__device__ __align__(256) float g_vqp  [B_ * ND_];
__device__ __align__(256) float g_suffix[B_ * NI_];
__device__ __align__(256) float g_xgd  [B_ * T_ * 4 * DNH];
__device__ __align__(256) float g_hd0  [B_ * DNH];
__device__ __align__(256) float g_cd   [B_ * DNH];
__device__ __align__(256) float g_decout[B_ * T_ * DNH];
// permuted (gate-interleaved) fp32 weights/biases (encoder)
__device__ __align__(256) float g_WfP  [4 * ENH * NI_];
__device__ __align__(256) float g_WbP  [4 * ENH * NI_];
__device__ __align__(256) float g_WhfP [4 * ENH * ENH];
__device__ __align__(256) float g_WhbP [4 * ENH * ENH];
__device__ __align__(256) float g_bfP  [4 * ENH];
__device__ __align__(256) float g_bbP  [4 * ENH];
__device__ __align__(256) float g_bdP  [4 * DNH];
// preconverted bf16 hi/lo operands (decoder-side tensor path)
__device__ __align__(256) __nv_bfloat16 g_dembH[B_ * T_ * NI_];
__device__ __align__(256) __nv_bfloat16 g_dembL[B_ * T_ * NI_];
__device__ __align__(256) __nv_bfloat16 g_WdH  [4 * DNH * NI_];
__device__ __align__(256) __nv_bfloat16 g_WdL  [4 * DNH * NI_];
__device__ __align__(256) __nv_bfloat16 g_WhdH [4 * DNH * DNH];
__device__ __align__(256) __nv_bfloat16 g_WhdL [4 * DNH * DNH];
__device__ __align__(256) __nv_bfloat16 g_hd0H [B_ * DNH];
__device__ __align__(256) __nv_bfloat16 g_hd0L [B_ * DNH];
__device__ __align__(256) __nv_bfloat16 g_doH  [B_ * T_ * DNH];
__device__ __align__(256) __nv_bfloat16 g_doL  [B_ * T_ * DNH];
__device__ __align__(256) __nv_bfloat16 g_pwH  [VPAD * DNH];
__device__ __align__(256) __nv_bfloat16 g_pwL  [VPAD * DNH];

// ---------------- helpers ----------------
__device__ __forceinline__ uint32_t smem_u32(const void* p) {
    uint32_t a;
    asm("{ .reg .u64 t; cvta.to.shared.u64 t, %1; cvt.u32.u64 %0, t; }" : "=r"(a) : "l"(p));
    return a;
}
__device__ __forceinline__ void cpa16(uint32_t dst, const void* src) {
    asm volatile("cp.async.ca.shared.global [%0], [%1], 16;" :: "r"(dst), "l"(src));
}
__device__ __forceinline__ float sigf(float x) { return 1.f / (1.f + expf(-x)); }
__device__ __forceinline__ uint32_t f2tf32(float x) {
    uint32_t r;
    asm("cvt.rna.tf32.f32 %0, %1;" : "=r"(r) : "f"(x));
    return r;
}
__device__ __forceinline__ void tf32split(float x, uint32_t& hi, uint32_t& lo) {
    hi = f2tf32(x);
    lo = f2tf32(x - __uint_as_float(hi));
}

// ---------------- weight permute: row g*H+j -> j*4+g ----------------
__global__ void perm_w(const float* __restrict__ W, float* __restrict__ Wp, int H, int K)
{
    size_t idx = (size_t)blockIdx.x * blockDim.x + threadIdx.x;
    if (idx >= (size_t)4 * H * K) return;
    int k = (int)(idx % K);
    int r = (int)(idx / K);
    int g = r / H, j = r % H;
    Wp[((size_t)j * 4 + g) * K + k] = W[idx];
}
__global__ void perm_w_split(const float* __restrict__ W,
                             __nv_bfloat16* __restrict__ WH, __nv_bfloat16* __restrict__ WL,
                             int H, int K)
{
    size_t idx = (size_t)blockIdx.x * blockDim.x + threadIdx.x;
    if (idx >= (size_t)4 * H * K) return;
    int k = (int)(idx % K);
    int r = (int)(idx / K);
    int g = r / H, j = r % H;
    float v = W[idx];
    __nv_bfloat16 h = __float2bfloat16_rn(v);
    size_t o = ((size_t)j * 4 + g) * K + k;
    WH[o] = h;
    WL[o] = __float2bfloat16_rn(v - __bfloat162float(h));
}
__global__ void perm_b(const float* __restrict__ b, float* __restrict__ bp, int H)
{
    int idx = blockIdx.x * blockDim.x + threadIdx.x;
    if (idx >= 4 * H) return;
    int g = idx / H, j = idx % H;
    bp[j * 4 + g] = b[idx];
}
__global__ void split_pad(const float* __restrict__ X,
                          __nv_bfloat16* __restrict__ H, __nv_bfloat16* __restrict__ L,
                          int rows_valid, int rows_total, int cols)
{
    size_t idx = (size_t)blockIdx.x * blockDim.x + threadIdx.x;
    if (idx >= (size_t)rows_total * cols) return;
    int r = (int)(idx / cols);
    float v = (r < rows_valid) ? X[idx] : 0.f;
    __nv_bfloat16 h = __float2bfloat16_rn(v);
    H[idx] = h;
    L[idx] = __float2bfloat16_rn(v - __bfloat162float(h));
}

// ---------------- fp32 SGEMM (small encoder-side GEMMs; exact numerics) ----------------
template<int BM, int BN, int BK, int TM, int TN>
__global__ __launch_bounds__((BM/TM)*(BN/TN))
void gemm_k(const float* __restrict__ A, int lda,
            const float* __restrict__ W, int ldw,
            const float* __restrict__ bias,
            float* __restrict__ C, int ldc,
            int N, int K)
{
    constexpr int NT = (BM/TM)*(BN/TN);
    __shared__ __align__(16) float As[BK][BM + 4];
    __shared__ __align__(16) float Ws[BK][BN + 4];
    const int tid  = threadIdx.x;
    const int row0 = blockIdx.y * BM;
    const int col0 = blockIdx.x * BN;
    const int tr   = tid / (BN / TN);
    const int tc   = tid % (BN / TN);
    float acc[TM][TN];
#pragma unroll
    for (int i = 0; i < TM; i++)
#pragma unroll
        for (int j = 0; j < TN; j++) acc[i][j] = 0.f;
    for (int k0 = 0; k0 < K; k0 += BK) {
#pragma unroll
        for (int idx = tid * 4; idx < BM * BK; idx += NT * 4) {
            int m = idx / BK, kk = idx % BK;
            float4 v = *reinterpret_cast<const float4*>(A + (size_t)(row0 + m) * lda + (k0 + kk));
            As[kk+0][m]=v.x; As[kk+1][m]=v.y; As[kk+2][m]=v.z; As[kk+3][m]=v.w;
        }
#pragma unroll
        for (int idx = tid * 4; idx < BN * BK; idx += NT * 4) {
            int n = idx / BK, kk = idx % BK;
            float4 v = make_float4(0.f,0.f,0.f,0.f);
            if (col0 + n < N)
                v = *reinterpret_cast<const float4*>(W + (size_t)(col0 + n) * ldw + (k0 + kk));
            Ws[kk+0][n]=v.x; Ws[kk+1][n]=v.y; Ws[kk+2][n]=v.z; Ws[kk+3][n]=v.w;
        }
        __syncthreads();
#pragma unroll
        for (int kk = 0; kk < BK; kk++) {
            float ra[TM], rb[TN];
#pragma unroll
            for (int i = 0; i < TM; i += 4) {
                float4 v = *reinterpret_cast<const float4*>(&As[kk][tr*TM+i]);
                ra[i]=v.x; ra[i+1]=v.y; ra[i+2]=v.z; ra[i+3]=v.w;
            }
#pragma unroll
            for (int j = 0; j < TN; j += 4) {
                float4 v = *reinterpret_cast<const float4*>(&Ws[kk][tc*TN+j]);
                rb[j]=v.x; rb[j+1]=v.y; rb[j+2]=v.z; rb[j+3]=v.w;
            }
#pragma unroll
            for (int i = 0; i < TM; i++)
#pragma unroll
                for (int j = 0; j < TN; j++)
                    acc[i][j] = fmaf(ra[i], rb[j], acc[i][j]);
        }
        __syncthreads();
    }
#pragma unroll
    for (int i = 0; i < TM; i++) {
        int m = row0 + tr*TM + i;
#pragma unroll
        for (int j = 0; j < TN; j++) {
            int n = col0 + tc*TN + j;
            if (n < N) {
                float v = acc[i][j];
                if (bias) v += bias[n];
                C[(size_t)m * ldc + n] = v;
            }
        }
    }
}

// ---------------- MMA macros ----------------
#define MMA_BF16(CC, AA, BB)                                                     \
    asm volatile("mma.sync.aligned.m16n8k16.row.col.f32.bf16.bf16.f32 "          \
        "{%0,%1,%2,%3}, {%4,%5,%6,%7}, {%8,%9}, {%0,%1,%2,%3};"                  \
        : "+f"(CC[0]), "+f"(CC[1]), "+f"(CC[2]), "+f"(CC[3])                     \
        : "r"(AA[0]), "r"(AA[1]), "r"(AA[2]), "r"(AA[3]), "r"(BB[0]), "r"(BB[1]))

#define MMA_TF32(CC, AA, BB)                                                     \
    asm volatile("mma.sync.aligned.m16n8k8.row.col.f32.tf32.tf32.f32 "           \
        "{%0,%1,%2,%3}, {%4,%5,%6,%7}, {%8,%9}, {%0,%1,%2,%3};"                  \
        : "+f"(CC[0]), "+f"(CC[1]), "+f"(CC[2]), "+f"(CC[3])                     \
        : "r"(AA[0]), "r"(AA[1]), "r"(AA[2]), "r"(AA[3]), "r"(BB[0]), "r"(BB[1]))

// ---------------- split-bf16 tensor GEMM (preconverted + cp.async, 128x128) ----------------
__global__ __launch_bounds__(256)
void hgemm2(const __nv_bfloat16* __restrict__ AH, const __nv_bfloat16* __restrict__ AL,
            const __nv_bfloat16* __restrict__ WH, const __nv_bfloat16* __restrict__ WL,
            const float* __restrict__ bias,
            float* __restrict__ C, int ldc, int N, int K)
{
    extern __shared__ __align__(16) __nv_bfloat16 dsm[];
    const int tid  = threadIdx.x;
    const int warp = tid >> 5, lane = tid & 31;
    const int wm = warp >> 2, wn = warp & 3;
    const int row0 = blockIdx.y * 128, col0 = blockIdx.x * 128;
    const int g = lane >> 2, q = lane & 3;
    const uint32_t sbase = smem_u32(dsm);
    const int ntiles = K >> 5;

    float acc[4][4][4];
#pragma unroll
    for (int a = 0; a < 4; a++)
#pragma unroll
        for (int b = 0; b < 4; b++)
#pragma unroll
            for (int c = 0; c < 4; c++) acc[a][b][c] = 0.f;

    auto issue_loads = [&](int stage, int t) {
        uint32_t sb = sbase + stage * 40960u;
        int k0 = t << 5;
        for (int i = tid; i < 512; i += 256) {
            int r = i >> 2, c8 = (i & 3) << 3;
            uint32_t off = (uint32_t)(r * 40 + c8) * 2;
            cpa16(sb + off,          AH + (size_t)(row0 + r) * K + k0 + c8);
            cpa16(sb + 10240 + off,  AL + (size_t)(row0 + r) * K + k0 + c8);
            cpa16(sb + 20480 + off,  WH + (size_t)(col0 + r) * K + k0 + c8);
            cpa16(sb + 30720 + off,  WL + (size_t)(col0 + r) * K + k0 + c8);
        }
    };

    issue_loads(0, 0);
    asm volatile("cp.async.commit_group;" ::: "memory");

    for (int t = 0; t < ntiles; t++) {
        if (t + 1 < ntiles) {
            issue_loads((t + 1) & 1, t + 1);
            asm volatile("cp.async.commit_group;" ::: "memory");
            asm volatile("cp.async.wait_group 1;" ::: "memory");
        } else {
            asm volatile("cp.async.wait_group 0;" ::: "memory");
        }
        __syncthreads();
        const __nv_bfloat16* Ah = dsm + (size_t)(t & 1) * 20480;
        const __nv_bfloat16* Al = Ah + 5120;
        const __nv_bfloat16* Wh = Ah + 10240;
        const __nv_bfloat16* Wl = Ah + 15360;
#pragma unroll
        for (int ks = 0; ks < 32; ks += 16) {
            uint32_t ah[4][4], al[4][4], bh[4][2], bl[4][2];
#pragma unroll
            for (int mi = 0; mi < 4; mi++) {
                int r = wm*64 + mi*16 + g;
                ah[mi][0] = *reinterpret_cast<const uint32_t*>(&Ah[(r  )*40 + ks + 2*q    ]);
                ah[mi][1] = *reinterpret_cast<const uint32_t*>(&Ah[(r+8)*40 + ks + 2*q    ]);
                ah[mi][2] = *reinterpret_cast<const uint32_t*>(&Ah[(r  )*40 + ks + 2*q + 8]);
                ah[mi][3] = *reinterpret_cast<const uint32_t*>(&Ah[(r+8)*40 + ks + 2*q + 8]);
                al[mi][0] = *reinterpret_cast<const uint32_t*>(&Al[(r  )*40 + ks + 2*q    ]);
                al[mi][1] = *reinterpret_cast<const uint32_t*>(&Al[(r+8)*40 + ks + 2*q    ]);
                al[mi][2] = *reinterpret_cast<const uint32_t*>(&Al[(r  )*40 + ks + 2*q + 8]);
                al[mi][3] = *reinterpret_cast<const uint32_t*>(&Al[(r+8)*40 + ks + 2*q + 8]);
            }
#pragma unroll
            for (int ni = 0; ni < 4; ni++) {
                int c = wn*32 + ni*8 + g;
                bh[ni][0] = *reinterpret_cast<const uint32_t*>(&Wh[c*40 + ks + 2*q    ]);
                bh[ni][1] = *reinterpret_cast<const uint32_t*>(&Wh[c*40 + ks + 2*q + 8]);
                bl[ni][0] = *reinterpret_cast<const uint32_t*>(&Wl[c*40 + ks + 2*q    ]);
                bl[ni][1] = *reinterpret_cast<const uint32_t*>(&Wl[c*40 + ks + 2*q + 8]);
            }
#pragma unroll
            for (int mi = 0; mi < 4; mi++)
#pragma unroll
                for (int ni = 0; ni < 4; ni++) {
                    MMA_BF16(acc[mi][ni], ah[mi], bh[ni]);
                    MMA_BF16(acc[mi][ni], ah[mi], bl[ni]);
                    MMA_BF16(acc[mi][ni], al[mi], bh[ni]);
                }
        }
        __syncthreads();
    }

#pragma unroll
    for (int mi = 0; mi < 4; mi++) {
        int r = row0 + wm*64 + mi*16 + g;
#pragma unroll
        for (int ni = 0; ni < 4; ni++) {
            int c = col0 + wn*32 + ni*8 + 2*q;
            float b0 = 0.f, b1 = 0.f;
            if (bias) {
                if (c < N)     b0 = bias[c];
                if (c + 1 < N) b1 = bias[c+1];
            }
            if (c < N) {
                C[(size_t)r * ldc + c]     = acc[mi][ni][0] + b0;
                C[(size_t)(r+8) * ldc + c] = acc[mi][ni][2] + b0;
            }
            if (c + 1 < N) {
                C[(size_t)r * ldc + c + 1]     = acc[mi][ni][1] + b1;
                C[(size_t)(r+8) * ldc + c + 1] = acc[mi][ni][3] + b1;
            }
        }
    }
}

// ---------------- 3xTF32 fp32-emulated tensor GEMM (fp32 in/out, 128x128) ----------------
// A [M,K] f32, W [N,K] f32, lda = ldw = K. N % 128 == 0, K % 32 == 0.
// smem: per stage A 128x36 f32 (18432 B) + W 128x36 f32; 2 stages = 73728 B dynamic.
__global__ __launch_bounds__(256)
void hgemm_tf32(const float* __restrict__ A, const float* __restrict__ W,
                const float* __restrict__ bias,
                float* __restrict__ C, int ldc, int N, int K)
{
    extern __shared__ __align__(16) float dsmf[];
    const int tid  = threadIdx.x;
    const int warp = tid >> 5, lane = tid & 31;
    const int wm = warp >> 2, wn = warp & 3;
    const int row0 = blockIdx.y * 128, col0 = blockIdx.x * 128;
    const int g = lane >> 2, q = lane & 3;
    const uint32_t sbase = smem_u32(dsmf);
    const int ntiles = K >> 5;

    float acc[4][4][4];
#pragma unroll
    for (int a = 0; a < 4; a++)
#pragma unroll
        for (int b = 0; b < 4; b++)
#pragma unroll
            for (int c = 0; c < 4; c++) acc[a][b][c] = 0.f;

    auto issue_loads = [&](int stage, int t) {
        uint32_t sb = sbase + stage * 36864u;
        int k0 = t << 5;
        for (int i = tid; i < 1024; i += 256) {
            int r = i >> 3, c4 = (i & 7) << 2;
            uint32_t off = (uint32_t)(r * 36 + c4) * 4;
            cpa16(sb + off,          A + (size_t)(row0 + r) * K + k0 + c4);
            cpa16(sb + 18432 + off,  W + (size_t)(col0 + r) * K + k0 + c4);
        }
    };

    issue_loads(0, 0);
    asm volatile("cp.async.commit_group;" ::: "memory");

    for (int t = 0; t < ntiles; t++) {
        if (t + 1 < ntiles) {
            issue_loads((t + 1) & 1, t + 1);
            asm volatile("cp.async.commit_group;" ::: "memory");
            asm volatile("cp.async.wait_group 1;" ::: "memory");
        } else {
            asm volatile("cp.async.wait_group 0;" ::: "memory");
        }
        __syncthreads();
        const float* As = dsmf + (size_t)(t & 1) * 9216;
        const float* Wsm = As + 4608;
#pragma unroll
        for (int ks = 0; ks < 32; ks += 8) {
            uint32_t ah[4][4], al[4][4], bh[4][2], bl[4][2];
#pragma unroll
            for (int mi = 0; mi < 4; mi++) {
                int r = wm*64 + mi*16 + g;
                tf32split(As[(r  )*36 + ks + q    ], ah[mi][0], al[mi][0]);
                tf32split(As[(r+8)*36 + ks + q    ], ah[mi][1], al[mi][1]);
                tf32split(As[(r  )*36 + ks + q + 4], ah[mi][2], al[mi][2]);
                tf32split(As[(r+8)*36 + ks + q + 4], ah[mi][3], al[mi][3]);
            }
#pragma unroll
            for (int ni = 0; ni < 4; ni++) {
                int c = wn*32 + ni*8 + g;
                tf32split(Wsm[c*36 + ks + q    ], bh[ni][0], bl[ni][0]);
                tf32split(Wsm[c*36 + ks + q + 4], bh[ni][1], bl[ni][1]);
            }
#pragma unroll
            for (int mi = 0; mi < 4; mi++)
#pragma unroll
                for (int ni = 0; ni < 4; ni++) {
                    MMA_TF32(acc[mi][ni], ah[mi], bh[ni]);
                    MMA_TF32(acc[mi][ni], ah[mi], bl[ni]);
                    MMA_TF32(acc[mi][ni], al[mi], bh[ni]);
                }
        }
        __syncthreads();
    }

#pragma unroll
    for (int mi = 0; mi < 4; mi++) {
        int r = row0 + wm*64 + mi*16 + g;
#pragma unroll
        for (int ni = 0; ni < 4; ni++) {
            int c = col0 + wn*32 + ni*8 + 2*q;
            float b0 = bias ? bias[c] : 0.f;
            float b1 = bias ? bias[c+1] : 0.f;
            C[(size_t)r * ldc + c]         = acc[mi][ni][0] + b0;
            C[(size_t)r * ldc + c + 1]     = acc[mi][ni][1] + b1;
            C[(size_t)(r+8) * ldc + c]     = acc[mi][ni][2] + b0;
            C[(size_t)(r+8) * ldc + c + 1] = acc[mi][ni][3] + b1;
        }
    }
}

// ---------------- encoder LSTM step on tensor cores (3xTF32, fused epilogue) ----------------
// Tile 64(batch) x 64(gate-interleaved cols); 128 threads = 4 warps (2x2).
// blockIdx.z selects direction (fwd/bwd). fp32 operands, tf32 split in registers.
template<int H>
__global__ __launch_bounds__(128)
void lstm_tf32_step(const float* __restrict__ xgA, const float* __restrict__ xgB, int rsXG,
                    const float* __restrict__ WA,  const float* __restrict__ WB,
                    const float* __restrict__ hinA, const float* __restrict__ hinB, int rsHin,
                    float* __restrict__ cA, float* __restrict__ cB,
                    float* __restrict__ houtA, float* __restrict__ houtB)
{
    const float* xg  = blockIdx.z ? xgB  : xgA;
    const float* W   = blockIdx.z ? WB   : WA;
    const float* hin = blockIdx.z ? hinB : hinA;
    float* cp   = blockIdx.z ? cB : cA;
    float* hout = blockIdx.z ? houtB : houtA;

    __shared__ __align__(16) float sm[2 * 2 * 2304];   // 2 stages x (A 64x36 + W 64x36) f32
    const int tid  = threadIdx.x;
    const int warp = tid >> 5, lane = tid & 31;
    const int wm = warp >> 1, wn = warp & 1;
    const int g = lane >> 2, q = lane & 3;
    const int row0 = blockIdx.y * 64, col0 = blockIdx.x * 64;
    const uint32_t sb0 = smem_u32(sm);
    const int ntiles = H >> 5;

    float acc[2][4][4];
#pragma unroll
    for (int a = 0; a < 2; a++)
#pragma unroll
        for (int b = 0; b < 4; b++)
#pragma unroll
            for (int c = 0; c < 4; c++) acc[a][b][c] = 0.f;

    auto issue_loads = [&](int stage, int t) {
        uint32_t sb = sb0 + stage * 18432u;
        int k0 = t << 5;
        for (int i = tid; i < 512; i += 128) {
            int r = i >> 3, c4 = (i & 7) << 2;
            uint32_t off = (uint32_t)(r * 36 + c4) * 4;
            cpa16(sb + off,         hin + (size_t)(row0 + r) * rsHin + k0 + c4);
            cpa16(sb + 9216 + off,  W + (size_t)(col0 + r) * H + k0 + c4);
        }
    };

    issue_loads(0, 0);
    asm volatile("cp.async.commit_group;" ::: "memory");

    for (int t = 0; t < ntiles; t++) {
        if (t + 1 < ntiles) {
            issue_loads((t + 1) & 1, t + 1);
            asm volatile("cp.async.commit_group;" ::: "memory");
            asm volatile("cp.async.wait_group 1;" ::: "memory");
        } else {
            asm volatile("cp.async.wait_group 0;" ::: "memory");
        }
        __syncthreads();
        const float* As = sm + (size_t)(t & 1) * 4608;
        const float* Wsm = As + 2304;
#pragma unroll
        for (int ks = 0; ks < 32; ks += 8) {
            uint32_t ah[2][4], al[2][4], bh[4][2], bl[4][2];
#pragma unroll
            for (int mi = 0; mi < 2; mi++) {
                int r = wm*32 + mi*16 + g;
                tf32split(As[(r  )*36 + ks + q    ], ah[mi][0], al[mi][0]);
                tf32split(As[(r+8)*36 + ks + q    ], ah[mi][1], al[mi][1]);
                tf32split(As[(r  )*36 + ks + q + 4], ah[mi][2], al[mi][2]);
                tf32split(As[(r+8)*36 + ks + q + 4], ah[mi][3], al[mi][3]);
            }
#pragma unroll
            for (int ni = 0; ni < 4; ni++) {
                int c = wn*32 + ni*8 + g;
                tf32split(Wsm[c*36 + ks + q    ], bh[ni][0], bl[ni][0]);
                tf32split(Wsm[c*36 + ks + q + 4], bh[ni][1], bl[ni][1]);
            }
#pragma unroll
            for (int mi = 0; mi < 2; mi++)
#pragma unroll
                for (int ni = 0; ni < 4; ni++) {
                    MMA_TF32(acc[mi][ni], ah[mi], bh[ni]);
                    MMA_TF32(acc[mi][ni], ah[mi], bl[ni]);
                    MMA_TF32(acc[mi][ni], al[mi], bh[ni]);
                }
        }
        __syncthreads();
    }

    // fused LSTM cell update (gate-interleaved cols; lane-partner holds g,o).
#pragma unroll
    for (int mi = 0; mi < 2; mi++) {
#pragma unroll
        for (int rr = 0; rr < 2; rr++) {
            int b = row0 + wm*32 + mi*16 + g + rr*8;
#pragma unroll
            for (int ni = 0; ni < 4; ni++) {
                int c = col0 + wn*32 + ni*8 + 2*q;
                float v0 = acc[mi][ni][rr*2 + 0] + xg[(size_t)b * rsXG + c];
                float v1 = acc[mi][ni][rr*2 + 1] + xg[(size_t)b * rsXG + c + 1];
                float p0 = __shfl_xor_sync(0xffffffffu, v0, 1);
                float p1 = __shfl_xor_sync(0xffffffffu, v1, 1);
                if (!(lane & 1)) {
                    int j = c >> 2;
                    size_t ci = (size_t)b * H + j;
                    float cc = sigf(v1) * cp[ci] + sigf(v0) * tanhf(p0);
                    cp[ci] = cc;
                    hout[(size_t)b * H + j] = sigf(p1) * tanhf(cc);
                }
            }
        }
    }
}

// ---------------- decoder LSTM step on tensor cores (bf16 split, fused epilogue) ----------------
__global__ __launch_bounds__(128)
void lstm_tc_step(const __nv_bfloat16* __restrict__ AH, const __nv_bfloat16* __restrict__ AL, int rsA,
                  const __nv_bfloat16* __restrict__ WH, const __nv_bfloat16* __restrict__ WL,
                  const float* __restrict__ xg, int rsXG,
                  float* __restrict__ cp,
                  float* __restrict__ hout, int rsH,
                  __nv_bfloat16* __restrict__ hHo, __nv_bfloat16* __restrict__ hLo)
{
    __shared__ __align__(16) __nv_bfloat16 sm[2 * 4 * 2560];
    const int tid  = threadIdx.x;
    const int warp = tid >> 5, lane = tid & 31;
    const int wm = warp >> 1, wn = warp & 1;
    const int g = lane >> 2, q = lane & 3;
    const int row0 = blockIdx.y * 64, col0 = blockIdx.x * 64;
    const uint32_t sb0 = smem_u32(sm);
    const int ntiles = DNH >> 5;

    float acc[2][4][4];
#pragma unroll
    for (int a = 0; a < 2; a++)
#pragma unroll
        for (int b = 0; b < 4; b++)
#pragma unroll
            for (int c = 0; c < 4; c++) acc[a][b][c] = 0.f;

    auto issue_loads = [&](int stage, int t) {
        uint32_t sb = sb0 + stage * 20480u;
        int k0 = t << 5;
        for (int i = tid; i < 256; i += 128) {
            int r = i >> 2, c8 = (i & 3) << 3;
            uint32_t off = (uint32_t)(r * 40 + c8) * 2;
            cpa16(sb + off,          AH + (size_t)(row0 + r) * rsA + k0 + c8);
            cpa16(sb + 5120 + off,   AL + (size_t)(row0 + r) * rsA + k0 + c8);
            cpa16(sb + 10240 + off,  WH + (size_t)(col0 + r) * DNH + k0 + c8);
            cpa16(sb + 15360 + off,  WL + (size_t)(col0 + r) * DNH + k0 + c8);
        }
    };

    issue_loads(0, 0);
    asm volatile("cp.async.commit_group;" ::: "memory");

    for (int t = 0; t < ntiles; t++) {
        if (t + 1 < ntiles) {
            issue_loads((t + 1) & 1, t + 1);
            asm volatile("cp.async.commit_group;" ::: "memory");
            asm volatile("cp.async.wait_group 1;" ::: "memory");
        } else {
            asm volatile("cp.async.wait_group 0;" ::: "memory");
        }
        __syncthreads();
        const __nv_bfloat16* Ah = sm + (size_t)(t & 1) * 10240;
        const __nv_bfloat16* Al = Ah + 2560;
        const __nv_bfloat16* Wh = Ah + 5120;
        const __nv_bfloat16* Wl = Ah + 7680;
#pragma unroll
        for (int ks = 0; ks < 32; ks += 16) {
            uint32_t ah[2][4], al[2][4], bh[4][2], bl[4][2];
#pragma unroll
            for (int mi = 0; mi < 2; mi++) {
                int r = wm*32 + mi*16 + g;
                ah[mi][0] = *reinterpret_cast<const uint32_t*>(&Ah[(r  )*40 + ks + 2*q    ]);
                ah[mi][1] = *reinterpret_cast<const uint32_t*>(&Ah[(r+8)*40 + ks + 2*q    ]);
                ah[mi][2] = *reinterpret_cast<const uint32_t*>(&Ah[(r  )*40 + ks + 2*q + 8]);
                ah[mi][3] = *reinterpret_cast<const uint32_t*>(&Ah[(r+8)*40 + ks + 2*q + 8]);
                al[mi][0] = *reinterpret_cast<const uint32_t*>(&Al[(r  )*40 + ks + 2*q    ]);
                al[mi][1] = *reinterpret_cast<const uint32_t*>(&Al[(r+8)*40 + ks + 2*q    ]);
                al[mi][2] = *reinterpret_cast<const uint32_t*>(&Al[(r  )*40 + ks + 2*q + 8]);
                al[mi][3] = *reinterpret_cast<const uint32_t*>(&Al[(r+8)*40 + ks + 2*q + 8]);
            }
#pragma unroll
            for (int ni = 0; ni < 4; ni++) {
                int c = wn*32 + ni*8 + g;
                bh[ni][0] = *reinterpret_cast<const uint32_t*>(&Wh[c*40 + ks + 2*q    ]);
                bh[ni][1] = *reinterpret_cast<const uint32_t*>(&Wh[c*40 + ks + 2*q + 8]);
                bl[ni][0] = *reinterpret_cast<const uint32_t*>(&Wl[c*40 + ks + 2*q    ]);
                bl[ni][1] = *reinterpret_cast<const uint32_t*>(&Wl[c*40 + ks + 2*q + 8]);
            }
#pragma unroll
            for (int mi = 0; mi < 2; mi++)
#pragma unroll
                for (int ni = 0; ni < 4; ni++) {
                    MMA_BF16(acc[mi][ni], ah[mi], bh[ni]);
                    MMA_BF16(acc[mi][ni], ah[mi], bl[ni]);
                    MMA_BF16(acc[mi][ni], al[mi], bh[ni]);
                }
        }
        __syncthreads();
    }

#pragma unroll
    for (int mi = 0; mi < 2; mi++) {
#pragma unroll
        for (int rr = 0; rr < 2; rr++) {
            int b = row0 + wm*32 + mi*16 + g + rr*8;
#pragma unroll
            for (int ni = 0; ni < 4; ni++) {
                int c = col0 + wn*32 + ni*8 + 2*q;
                float v0 = acc[mi][ni][rr*2 + 0] + xg[(size_t)b * rsXG + c];
                float v1 = acc[mi][ni][rr*2 + 1] + xg[(size_t)b * rsXG + c + 1];
                float p0 = __shfl_xor_sync(0xffffffffu, v0, 1);
                float p1 = __shfl_xor_sync(0xffffffffu, v1, 1);
                if (!(lane & 1)) {
                    int j = c >> 2;
                    size_t ci = (size_t)b * DNH + j;
                    float cc = sigf(v1) * cp[ci] + sigf(v0) * tanhf(p0);
                    cp[ci] = cc;
                    float hv = sigf(p1) * tanhf(cc);
                    size_t ho = (size_t)b * rsH + j;
                    hout[ho] = hv;
                    __nv_bfloat16 hh = __float2bfloat16_rn(hv);
                    hHo[ho] = hh;
                    hLo[ho] = __float2bfloat16_rn(hv - __bfloat162float(hh));
                }
            }
        }
    }
}

// ---------------- elementwise / small kernels ----------------
__global__ void embed_kernel(const int* __restrict__ x, const float* __restrict__ emb,
                             float* __restrict__ out)
{
    size_t idx = (size_t)blockIdx.x * blockDim.x + threadIdx.x;
    if (idx >= (size_t)B_ * T_ * NI_) return;
    int i = (int)(idx % NI_), bt = (int)(idx / NI_);
    out[idx] = emb[(size_t)x[bt] * NI_ + i];
}

__global__ void demb_split(const int* __restrict__ x, const float* __restrict__ emb,
                           const float* __restrict__ suffix,
                           __nv_bfloat16* __restrict__ H, __nv_bfloat16* __restrict__ L)
{
    size_t idx = (size_t)blockIdx.x * blockDim.x + threadIdx.x;
    if (idx >= (size_t)B_ * T_ * NI_) return;
    int i = (int)(idx % NI_), bt = (int)(idx / NI_);
    int b = bt / T_;
    float v = emb[(size_t)x[bt] * NI_ + i] + suffix[(size_t)b * NI_ + i];
    __nv_bfloat16 h = __float2bfloat16_rn(v);
    H[idx] = h;
    L[idx] = __float2bfloat16_rn(v - __bfloat162float(h));
}

__global__ void concat_fhs(const float* __restrict__ hf, const float* __restrict__ hb,
                           float* __restrict__ fhs)
{
    int idx = blockIdx.x * blockDim.x + threadIdx.x;
    if (idx >= B_ * 2 * ENH) return;
    int b = idx / (2 * ENH), j = idx % (2 * ENH);
    fhs[idx] = (j < ENH) ? hf[(size_t)b * ENH + j] : hb[(size_t)b * ENH + (j - ENH)];
}

__global__ void kl_kernel(const float* __restrict__ muvar, float* __restrict__ out_kl)
{
    int b = threadIdx.x;
    if (b >= B_) return;
    float s = 0.f;
    const float* row = muvar + (size_t)b * 2 * NZ_;
    for (int j = 0; j < NZ_; j++) {
        float mu = row[j], lv = row[NZ_ + j];
        s += mu * mu + expf(lv) - lv - 1.f;
    }
    out_kl[b] = 0.5f * s;
}

__global__ void dec_init(const float* __restrict__ root, float* __restrict__ h0,
                         float* __restrict__ c0,
                         __nv_bfloat16* __restrict__ hH, __nv_bfloat16* __restrict__ hL)
{
    int idx = blockIdx.x * blockDim.x + threadIdx.x;
    if (idx >= B_ * DNH) return;
    float r = root[idx];
    float hv = tanhf(r);
    h0[idx] = hv;
    c0[idx] = r;
    __nv_bfloat16 hh = __float2bfloat16_rn(hv);
    hH[idx] = hh;
    hL[idx] = __float2bfloat16_rn(hv - __bfloat162float(hh));
}

__global__ void vq_kernel(const float* __restrict__ fhs, const float* __restrict__ cb,
                          int* __restrict__ inds, float* __restrict__ q,
                          float* __restrict__ vqp)
{
    const int bn = blockIdx.x;
    const int b = bn / ND_, n = bn % ND_;
    __shared__ __align__(16) float lat[D_];
    __shared__ float svals[256];
    __shared__ int   sidx[256];
    const float* latg = fhs + (size_t)b * (ND_ * D_) + (size_t)n * D_;
    for (int d = threadIdx.x; d < D_; d += 256) lat[d] = latg[d];
    __syncthreads();
    float best = INFINITY; int bidx = K_;
    const float* cbn = cb + (size_t)n * K_ * D_;
    for (int k = threadIdx.x; k < K_; k += 256) {
        const float4* ck = reinterpret_cast<const float4*>(cbn + (size_t)k * D_);
        float t1 = 0.f, t2 = 0.f;
#pragma unroll
        for (int d4 = 0; d4 < D_ / 4; d4++) {
            float4 cv = ck[d4];
            const float4 lv = *reinterpret_cast<const float4*>(&lat[d4 * 4]);
            t1 = fmaf(cv.x, cv.x, t1); t2 = fmaf(cv.x, lv.x, t2);
            t1 = fmaf(cv.y, cv.y, t1); t2 = fmaf(cv.y, lv.y, t2);
            t1 = fmaf(cv.z, cv.z, t1); t2 = fmaf(cv.z, lv.z, t2);
            t1 = fmaf(cv.w, cv.w, t1); t2 = fmaf(cv.w, lv.w, t2);
        }
        float dist = t1 - 2.f * t2;
        if (dist < best || (dist == best && k < bidx)) { best = dist; bidx = k; }
    }
    svals[threadIdx.x] = best; sidx[threadIdx.x] = bidx;
    __syncthreads();
    for (int off = 128; off > 0; off >>= 1) {
        if (threadIdx.x < off) {
            float v = svals[threadIdx.x + off]; int i2 = sidx[threadIdx.x + off];
            if (v < svals[threadIdx.x] || (v == svals[threadIdx.x] && i2 < sidx[threadIdx.x])) {
                svals[threadIdx.x] = v; sidx[threadIdx.x] = i2;
            }
        }
        __syncthreads();
    }
    const int kmin = sidx[0];
    if (threadIdx.x == 0) inds[bn] = kmin;
    __syncthreads();
    const float* ck = cbn + (size_t)kmin * D_;
    float part = 0.f;
    for (int d = threadIdx.x; d < D_; d += 256) {
        float qv = ck[d], lv = lat[d];
        float diff = qv - lv;
        q[(size_t)bn * D_ + d] = lv + diff;
        part += diff * diff;
    }
    svals[threadIdx.x] = part;
    __syncthreads();
    for (int off = 128; off > 0; off >>= 1) {
        if (threadIdx.x < off) svals[threadIdx.x] += svals[threadIdx.x + off];
        __syncthreads();
    }
    if (threadIdx.x == 0) vqp[bn] = svals[0] / (float)D_;
}

__global__ void vq_finish(const float* __restrict__ vqp, const int* __restrict__ inds,
                          float* __restrict__ out_vq, float* __restrict__ out_inds)
{
    int b = threadIdx.x;
    if (b >= B_) return;
    float s = 0.f;
#pragma unroll
    for (int n = 0; n < ND_; n++) s += vqp[b * ND_ + n];
    out_vq[b] = 1.25f * s;
#pragma unroll
    for (int n = 0; n < ND_; n++)
        out_inds[b * ND_ + n] = (float)inds[b * ND_ + n];
}

// ---------------- launch helpers ----------------
static inline void gemm_small(const float* A, int lda, const float* W, int ldw,
                              const float* bias, float* C, int ldc, int M, int N, int K)
{
    dim3 grid((N + 63) / 64, M / 32);
    gemm_k<32, 64, 16, 4, 4><<<grid, 128>>>(A, lda, W, ldw, bias, C, ldc, N, K);
}

extern "C" void kernel_launch(void* const* d_in, const int* in_sizes, int n_in,
                              void* d_out, int out_size)
{
    (void)in_sizes; (void)n_in; (void)out_size;
    const int*   x         = (const int*)  d_in[0];
    const float* enc_embed = (const float*)d_in[1];
    const float* enc_Wih_f = (const float*)d_in[2];
    const float* enc_Whh_f = (const float*)d_in[3];
    const float* enc_b_f   = (const float*)d_in[4];
    const float* enc_Wih_b = (const float*)d_in[5];
    const float* enc_Whh_b = (const float*)d_in[6];
    const float* enc_b_b   = (const float*)d_in[7];
    const float* enc_lin   = (const float*)d_in[8];
    const float* z2dec_W   = (const float*)d_in[9];
    const float* z2dec_b   = (const float*)d_in[10];
    const float* codebooks = (const float*)d_in[11];
    const float* suffix_W  = (const float*)d_in[12];
    const float* dec_embed = (const float*)d_in[13];
    const float* dec_Wih   = (const float*)d_in[14];
    const float* dec_Whh   = (const float*)d_in[15];
    const float* dec_b     = (const float*)d_in[16];
    const float* pred_W    = (const float*)d_in[17];

    float* out      = (float*)d_out;
    float* out_log  = out;
    float* out_vq   = out + (size_t)LOGITS_ELEMS;
    float* out_kl   = out_vq + B_;
    float* out_inds = out_kl + B_;

    float *we,*xgf,*xgb,*encA,*hfB,*hbB,*fhs,*muvar,*root,*q,*vqp,*suffix;
    float *xgd,*hd0,*cd,*decout;
    float *WfP,*WbP,*WhfP,*WhbP,*bfP,*bbP,*bdP;
    __nv_bfloat16 *dembH,*dembL,*WdH,*WdL,*WhdH,*WhdL,*hd0H,*hd0L,*doH,*doL,*pwH,*pwL;
    int* inds;
    cudaGetSymbolAddress((void**)&we,    g_we);
    cudaGetSymbolAddress((void**)&xgf,   g_xgf);
    cudaGetSymbolAddress((void**)&xgb,   g_xgb);
    cudaGetSymbolAddress((void**)&encA,  g_encA);
    cudaGetSymbolAddress((void**)&hfB,   g_hfB);
    cudaGetSymbolAddress((void**)&hbB,   g_hbB);
    cudaGetSymbolAddress((void**)&fhs,   g_fhs);
    cudaGetSymbolAddress((void**)&muvar, g_muvar);
    cudaGetSymbolAddress((void**)&root,  g_root);
    cudaGetSymbolAddress((void**)&inds,  g_inds);
    cudaGetSymbolAddress((void**)&q,     g_q);
    cudaGetSymbolAddress((void**)&vqp,   g_vqp);
    cudaGetSymbolAddress((void**)&suffix,g_suffix);
    cudaGetSymbolAddress((void**)&xgd,   g_xgd);
    cudaGetSymbolAddress((void**)&hd0,   g_hd0);
    cudaGetSymbolAddress((void**)&cd,    g_cd);
    cudaGetSymbolAddress((void**)&decout,g_decout);
    cudaGetSymbolAddress((void**)&WfP,   g_WfP);
    cudaGetSymbolAddress((void**)&WbP,   g_WbP);
    cudaGetSymbolAddress((void**)&WhfP,  g_WhfP);
    cudaGetSymbolAddress((void**)&WhbP,  g_WhbP);
    cudaGetSymbolAddress((void**)&bfP,   g_bfP);
    cudaGetSymbolAddress((void**)&bbP,   g_bbP);
    cudaGetSymbolAddress((void**)&bdP,   g_bdP);
    cudaGetSymbolAddress((void**)&dembH, g_dembH);
    cudaGetSymbolAddress((void**)&dembL, g_dembL);
    cudaGetSymbolAddress((void**)&WdH,   g_WdH);
    cudaGetSymbolAddress((void**)&WdL,   g_WdL);
    cudaGetSymbolAddress((void**)&WhdH,  g_WhdH);
    cudaGetSymbolAddress((void**)&WhdL,  g_WhdL);
    cudaGetSymbolAddress((void**)&hd0H,  g_hd0H);
    cudaGetSymbolAddress((void**)&hd0L,  g_hd0L);
    cudaGetSymbolAddress((void**)&doH,   g_doH);
    cudaGetSymbolAddress((void**)&doL,   g_doL);
    cudaGetSymbolAddress((void**)&pwH,   g_pwH);
    cudaGetSymbolAddress((void**)&pwL,   g_pwL);

    cudaFuncSetAttribute(hgemm2, cudaFuncAttributeMaxDynamicSharedMemorySize, 81920);
    cudaFuncSetAttribute(hgemm_tf32, cudaFuncAttributeMaxDynamicSharedMemorySize, 73728);

    float* hfA = encA;
    float* cf  = encA + (size_t)B_ * ENH;
    float* hbA = encA + (size_t)2 * B_ * ENH;
    float* cb  = encA + (size_t)3 * B_ * ENH;

    const int EW = 256;

    // 0) permute weights/biases; split decoder-side constants to bf16 hi/lo
    perm_w<<<(4*ENH*NI_ + EW-1)/EW, EW>>>(enc_Wih_f, WfP,  ENH, NI_);
    perm_w<<<(4*ENH*NI_ + EW-1)/EW, EW>>>(enc_Wih_b, WbP,  ENH, NI_);
    perm_w<<<(4*ENH*ENH + EW-1)/EW, EW>>>(enc_Whh_f, WhfP, ENH, ENH);
    perm_w<<<(4*ENH*ENH + EW-1)/EW, EW>>>(enc_Whh_b, WhbP, ENH, ENH);
    perm_w_split<<<(4*DNH*DNH + EW-1)/EW, EW>>>(dec_Whh, WhdH, WhdL, DNH, DNH);
    perm_w_split<<<(4*DNH*NI_ + EW-1)/EW, EW>>>(dec_Wih, WdH, WdL, DNH, NI_);
    perm_b<<<(4*ENH + EW-1)/EW, EW>>>(enc_b_f, bfP, ENH);
    perm_b<<<(4*ENH + EW-1)/EW, EW>>>(enc_b_b, bbP, ENH);
    perm_b<<<(4*DNH + EW-1)/EW, EW>>>(dec_b,   bdP, DNH);
    split_pad<<<((size_t)VPAD*DNH + EW-1)/EW, EW>>>(pred_W, pwH, pwL, V_, VPAD, DNH);

    // 1) encoder embedding + interleaved input-gate GEMMs (3xTF32 = fp32-class)
    embed_kernel<<<(B_ * T_ * NI_ + EW - 1) / EW, EW>>>(x, enc_embed, we);
    {
        dim3 gx(4 * ENH / 128, (B_ * T_) / 128);
        hgemm_tf32<<<gx, 256, 73728>>>(we, WfP, bfP, xgf, 4 * ENH, 4 * ENH, NI_);
        hgemm_tf32<<<gx, 256, 73728>>>(we, WbP, bbP, xgb, 4 * ENH, 4 * ENH, NI_);
    }
    cudaMemsetAsync(encA, 0, sizeof(float) * 4 * B_ * ENH, 0);

    // 2) encoder recurrence (3xTF32 tensor cores, fused gates; h double-buffered)
    {
        dim3 grid(4 * ENH / 64, B_ / 64, 2);
        for (int s = 0; s < T_; s++) {
            const float* hf_in = (s & 1) ? hfB : hfA;
            float*       hf_out= (s & 1) ? hfA : hfB;
            const float* hb_in = (s & 1) ? hbB : hbA;
            float*       hb_out= (s & 1) ? hbA : hbB;
            lstm_tf32_step<ENH><<<grid, 128>>>(
                xgf + (size_t)s * 4 * ENH, xgb + (size_t)(T_ - 1 - s) * 4 * ENH, T_ * 4 * ENH,
                WhfP, WhbP,
                hf_in, hb_in, ENH,
                cf, cb,
                hf_out, hb_out);
        }
    }
    concat_fhs<<<(B_ * 2 * ENH + EW - 1) / EW, EW>>>(hfA, hbA, fhs);

    gemm_small(fhs, 2 * ENH, enc_lin, 2 * ENH, nullptr, muvar, 2 * NZ_, B_, 2 * NZ_, 2 * ENH);
    kl_kernel<<<1, B_>>>(muvar, out_kl);
    gemm_small(muvar, 2 * NZ_, z2dec_W, NZ_, z2dec_b, root, DNH, B_, DNH, NZ_);

    vq_kernel<<<B_ * ND_, 256>>>(fhs, codebooks, inds, q, vqp);
    vq_finish<<<1, B_>>>(vqp, inds, out_vq, out_inds);

    gemm_small(q, ND_ * D_, suffix_W, ND_ * D_, nullptr, suffix, NI_, B_, NI_, ND_ * D_);
    demb_split<<<(B_ * T_ * NI_ + EW - 1) / EW, EW>>>(x, dec_embed, suffix, dembH, dembL);

    // decoder input gates: preconverted split-bf16 tensor GEMM
    {
        dim3 grid(4 * DNH / 128, (B_ * T_) / 128);
        hgemm2<<<grid, 256, 81920>>>(dembH, dembL, WdH, WdL, bdP, xgd, 4 * DNH, 4 * DNH, NI_);
    }

    dec_init<<<(B_ * DNH + EW - 1) / EW, EW>>>(root, hd0, cd, hd0H, hd0L);

    // decoder recurrence: tensor-core fused step (64x64 tiles, 128 blocks)
    {
        dim3 grid(4 * DNH / 64, B_ / 64);
        for (int s = 0; s < T_; s++) {
            const __nv_bfloat16* aH = (s == 0) ? hd0H : (doH + (size_t)(s - 1) * DNH);
            const __nv_bfloat16* aL = (s == 0) ? hd0L : (doL + (size_t)(s - 1) * DNH);
            int rsA                 = (s == 0) ? DNH : (T_ * DNH);
            lstm_tc_step<<<grid, 128>>>(
                aH, aL, rsA,
                WhdH, WhdL,
                xgd + (size_t)s * 4 * DNH, T_ * 4 * DNH,
                cd,
                decout + (size_t)s * DNH, T_ * DNH,
                doH + (size_t)s * DNH, doL + (size_t)s * DNH);
        }
    }

    // logits: preconverted split-bf16 tensor GEMM (W padded to VPAD rows)
    {
        dim3 grid(VPAD / 128, (B_ * T_) / 128);
        hgemm2<<<grid, 256, 81920>>>(doH, doL, pwH, pwL, nullptr, out_log, V_, V_, DNH);
    }
}

// round 17
// speedup vs baseline: 1.8011x; 1.0124x over previous
#include <cuda_runtime.h>
#include <cuda_bf16.h>
#include <math.h>
#include <stdint.h>

#define B_    128
#define T_    64
#define V_    10000
#define NI_   512
#define ENH   640
#define DNH   1024
#define NZ_   128
#define ND_   8
#define K_    1024
#define D_    160
#define LOGITS_ELEMS (B_ * T_ * V_)
#define VPAD  10112   // 79 * 128

// ---------------- scratch ----------------
__device__ __align__(256) float g_we   [B_ * T_ * NI_];
__device__ __align__(256) float g_weH  [B_ * T_ * NI_];
__device__ __align__(256) float g_weL  [B_ * T_ * NI_];
__device__ __align__(256) float g_xgf  [B_ * T_ * 4 * ENH];
__device__ __align__(256) float g_xgb  [B_ * T_ * 4 * ENH];
__device__ __align__(256) float g_encA [4 * B_ * ENH];   // (cf, cb in middle slots kept for layout compat)
__device__ __align__(256) float g_ehH  [2 * 2 * B_ * ENH]; // [buf][dir][B*ENH] tf32-hi of h
__device__ __align__(256) float g_ehL  [2 * 2 * B_ * ENH];
__device__ __align__(256) float g_ehX  [2 * B_ * ENH];     // exact h, [dir][B*ENH]
__device__ __align__(256) float g_fhs  [B_ * 2 * ENH];
__device__ __align__(256) float g_muvar[B_ * 2 * NZ_];
__device__ __align__(256) float g_root [B_ * DNH];
__device__ __align__(256) int   g_inds [B_ * ND_];
__device__ __align__(256) float g_q    [B_ * ND_ * D_];
__device__ __align__(256) float g_vqp  [B_ * ND_];
__device__ __align__(256) float g_suffix[B_ * NI_];
__device__ __align__(256) float g_xgd  [B_ * T_ * 4 * DNH];
__device__ __align__(256) float g_hd0  [B_ * DNH];
__device__ __align__(256) float g_cd   [B_ * DNH];
__device__ __align__(256) float g_decout[B_ * T_ * DNH];
// tf32 hi/lo pre-split encoder weights (gate-interleaved)
__device__ __align__(256) float g_WfH  [4 * ENH * NI_];
__device__ __align__(256) float g_WfL  [4 * ENH * NI_];
__device__ __align__(256) float g_WbH  [4 * ENH * NI_];
__device__ __align__(256) float g_WbL  [4 * ENH * NI_];
__device__ __align__(256) float g_WhfH [4 * ENH * ENH];
__device__ __align__(256) float g_WhfL [4 * ENH * ENH];
__device__ __align__(256) float g_WhbH [4 * ENH * ENH];
__device__ __align__(256) float g_WhbL [4 * ENH * ENH];
__device__ __align__(256) float g_bfP  [4 * ENH];
__device__ __align__(256) float g_bbP  [4 * ENH];
__device__ __align__(256) float g_bdP  [4 * DNH];
// preconverted bf16 hi/lo operands (decoder-side tensor path)
__device__ __align__(256) __nv_bfloat16 g_dembH[B_ * T_ * NI_];
__device__ __align__(256) __nv_bfloat16 g_dembL[B_ * T_ * NI_];
__device__ __align__(256) __nv_bfloat16 g_WdH  [4 * DNH * NI_];
__device__ __align__(256) __nv_bfloat16 g_WdL  [4 * DNH * NI_];
__device__ __align__(256) __nv_bfloat16 g_WhdH [4 * DNH * DNH];
__device__ __align__(256) __nv_bfloat16 g_WhdL [4 * DNH * DNH];
__device__ __align__(256) __nv_bfloat16 g_hd0H [B_ * DNH];
__device__ __align__(256) __nv_bfloat16 g_hd0L [B_ * DNH];
__device__ __align__(256) __nv_bfloat16 g_doH  [B_ * T_ * DNH];
__device__ __align__(256) __nv_bfloat16 g_doL  [B_ * T_ * DNH];
__device__ __align__(256) __nv_bfloat16 g_pwH  [VPAD * DNH];
__device__ __align__(256) __nv_bfloat16 g_pwL  [VPAD * DNH];

// ---------------- helpers ----------------
__device__ __forceinline__ uint32_t smem_u32(const void* p) {
    uint32_t a;
    asm("{ .reg .u64 t; cvta.to.shared.u64 t, %1; cvt.u32.u64 %0, t; }" : "=r"(a) : "l"(p));
    return a;
}
__device__ __forceinline__ void cpa16(uint32_t dst, const void* src) {
    asm volatile("cp.async.ca.shared.global [%0], [%1], 16;" :: "r"(dst), "l"(src));
}
__device__ __forceinline__ float sigf(float x) { return 1.f / (1.f + expf(-x)); }
__device__ __forceinline__ uint32_t f2tf32(float x) {
    uint32_t r;
    asm("cvt.rna.tf32.f32 %0, %1;" : "=r"(r) : "f"(x));
    return r;
}

// ---------------- prep kernels ----------------
__global__ void perm_w_split_tf32(const float* __restrict__ W,
                                  float* __restrict__ WH, float* __restrict__ WL,
                                  int H, int K)
{
    size_t idx = (size_t)blockIdx.x * blockDim.x + threadIdx.x;
    if (idx >= (size_t)4 * H * K) return;
    int k = (int)(idx % K);
    int r = (int)(idx / K);
    int g = r / H, j = r % H;
    float v = W[idx];
    uint32_t hi = f2tf32(v);
    size_t o = ((size_t)j * 4 + g) * K + k;
    WH[o] = __uint_as_float(hi);
    WL[o] = __uint_as_float(f2tf32(v - __uint_as_float(hi)));
}
__global__ void split_tf32(const float* __restrict__ X,
                           float* __restrict__ H, float* __restrict__ L, size_t n)
{
    size_t idx = (size_t)blockIdx.x * blockDim.x + threadIdx.x;
    if (idx >= n) return;
    float v = X[idx];
    uint32_t hi = f2tf32(v);
    H[idx] = __uint_as_float(hi);
    L[idx] = __uint_as_float(f2tf32(v - __uint_as_float(hi)));
}
__global__ void perm_w_split(const float* __restrict__ W,
                             __nv_bfloat16* __restrict__ WH, __nv_bfloat16* __restrict__ WL,
                             int H, int K)
{
    size_t idx = (size_t)blockIdx.x * blockDim.x + threadIdx.x;
    if (idx >= (size_t)4 * H * K) return;
    int k = (int)(idx % K);
    int r = (int)(idx / K);
    int g = r / H, j = r % H;
    float v = W[idx];
    __nv_bfloat16 h = __float2bfloat16_rn(v);
    size_t o = ((size_t)j * 4 + g) * K + k;
    WH[o] = h;
    WL[o] = __float2bfloat16_rn(v - __bfloat162float(h));
}
__global__ void perm_b(const float* __restrict__ b, float* __restrict__ bp, int H)
{
    int idx = blockIdx.x * blockDim.x + threadIdx.x;
    if (idx >= 4 * H) return;
    int g = idx / H, j = idx % H;
    bp[j * 4 + g] = b[idx];
}
__global__ void split_pad(const float* __restrict__ X,
                          __nv_bfloat16* __restrict__ H, __nv_bfloat16* __restrict__ L,
                          int rows_valid, int rows_total, int cols)
{
    size_t idx = (size_t)blockIdx.x * blockDim.x + threadIdx.x;
    if (idx >= (size_t)rows_total * cols) return;
    int r = (int)(idx / cols);
    float v = (r < rows_valid) ? X[idx] : 0.f;
    __nv_bfloat16 h = __float2bfloat16_rn(v);
    H[idx] = h;
    L[idx] = __float2bfloat16_rn(v - __bfloat162float(h));
}

// ---------------- fp32 SGEMM (small encoder-side GEMMs; exact numerics) ----------------
template<int BM, int BN, int BK, int TM, int TN>
__global__ __launch_bounds__((BM/TM)*(BN/TN))
void gemm_k(const float* __restrict__ A, int lda,
            const float* __restrict__ W, int ldw,
            const float* __restrict__ bias,
            float* __restrict__ C, int ldc,
            int N, int K)
{
    constexpr int NT = (BM/TM)*(BN/TN);
    __shared__ __align__(16) float As[BK][BM + 4];
    __shared__ __align__(16) float Ws[BK][BN + 4];
    const int tid  = threadIdx.x;
    const int row0 = blockIdx.y * BM;
    const int col0 = blockIdx.x * BN;
    const int tr   = tid / (BN / TN);
    const int tc   = tid % (BN / TN);
    float acc[TM][TN];
#pragma unroll
    for (int i = 0; i < TM; i++)
#pragma unroll
        for (int j = 0; j < TN; j++) acc[i][j] = 0.f;
    for (int k0 = 0; k0 < K; k0 += BK) {
#pragma unroll
        for (int idx = tid * 4; idx < BM * BK; idx += NT * 4) {
            int m = idx / BK, kk = idx % BK;
            float4 v = *reinterpret_cast<const float4*>(A + (size_t)(row0 + m) * lda + (k0 + kk));
            As[kk+0][m]=v.x; As[kk+1][m]=v.y; As[kk+2][m]=v.z; As[kk+3][m]=v.w;
        }
#pragma unroll
        for (int idx = tid * 4; idx < BN * BK; idx += NT * 4) {
            int n = idx / BK, kk = idx % BK;
            float4 v = make_float4(0.f,0.f,0.f,0.f);
            if (col0 + n < N)
                v = *reinterpret_cast<const float4*>(W + (size_t)(col0 + n) * ldw + (k0 + kk));
            Ws[kk+0][n]=v.x; Ws[kk+1][n]=v.y; Ws[kk+2][n]=v.z; Ws[kk+3][n]=v.w;
        }
        __syncthreads();
#pragma unroll
        for (int kk = 0; kk < BK; kk++) {
            float ra[TM], rb[TN];
#pragma unroll
            for (int i = 0; i < TM; i += 4) {
                float4 v = *reinterpret_cast<const float4*>(&As[kk][tr*TM+i]);
                ra[i]=v.x; ra[i+1]=v.y; ra[i+2]=v.z; ra[i+3]=v.w;
            }
#pragma unroll
            for (int j = 0; j < TN; j += 4) {
                float4 v = *reinterpret_cast<const float4*>(&Ws[kk][tc*TN+j]);
                rb[j]=v.x; rb[j+1]=v.y; rb[j+2]=v.z; rb[j+3]=v.w;
            }
#pragma unroll
            for (int i = 0; i < TM; i++)
#pragma unroll
                for (int j = 0; j < TN; j++)
                    acc[i][j] = fmaf(ra[i], rb[j], acc[i][j]);
        }
        __syncthreads();
    }
#pragma unroll
    for (int i = 0; i < TM; i++) {
        int m = row0 + tr*TM + i;
#pragma unroll
        for (int j = 0; j < TN; j++) {
            int n = col0 + tc*TN + j;
            if (n < N) {
                float v = acc[i][j];
                if (bias) v += bias[n];
                C[(size_t)m * ldc + n] = v;
            }
        }
    }
}

// ---------------- MMA macros ----------------
#define MMA_BF16(CC, AA, BB)                                                     \
    asm volatile("mma.sync.aligned.m16n8k16.row.col.f32.bf16.bf16.f32 "          \
        "{%0,%1,%2,%3}, {%4,%5,%6,%7}, {%8,%9}, {%0,%1,%2,%3};"                  \
        : "+f"(CC[0]), "+f"(CC[1]), "+f"(CC[2]), "+f"(CC[3])                     \
        : "r"(AA[0]), "r"(AA[1]), "r"(AA[2]), "r"(AA[3]), "r"(BB[0]), "r"(BB[1]))

#define MMA_TF32(CC, AA, BB)                                                     \
    asm volatile("mma.sync.aligned.m16n8k8.row.col.f32.tf32.tf32.f32 "           \
        "{%0,%1,%2,%3}, {%4,%5,%6,%7}, {%8,%9}, {%0,%1,%2,%3};"                  \
        : "+f"(CC[0]), "+f"(CC[1]), "+f"(CC[2]), "+f"(CC[3])                     \
        : "r"(AA[0]), "r"(AA[1]), "r"(AA[2]), "r"(AA[3]), "r"(BB[0]), "r"(BB[1]))

// ---------------- split-bf16 tensor GEMM (preconverted + cp.async, 128x128) ----------------
__global__ __launch_bounds__(256)
void hgemm2(const __nv_bfloat16* __restrict__ AH, const __nv_bfloat16* __restrict__ AL,
            const __nv_bfloat16* __restrict__ WH, const __nv_bfloat16* __restrict__ WL,
            const float* __restrict__ bias,
            float* __restrict__ C, int ldc, int N, int K)
{
    extern __shared__ __align__(16) __nv_bfloat16 dsm[];
    const int tid  = threadIdx.x;
    const int warp = tid >> 5, lane = tid & 31;
    const int wm = warp >> 2, wn = warp & 3;
    const int row0 = blockIdx.y * 128, col0 = blockIdx.x * 128;
    const int g = lane >> 2, q = lane & 3;
    const uint32_t sbase = smem_u32(dsm);
    const int ntiles = K >> 5;

    float acc[4][4][4];
#pragma unroll
    for (int a = 0; a < 4; a++)
#pragma unroll
        for (int b = 0; b < 4; b++)
#pragma unroll
            for (int c = 0; c < 4; c++) acc[a][b][c] = 0.f;

    auto issue_loads = [&](int stage, int t) {
        uint32_t sb = sbase + stage * 40960u;
        int k0 = t << 5;
        for (int i = tid; i < 512; i += 256) {
            int r = i >> 2, c8 = (i & 3) << 3;
            uint32_t off = (uint32_t)(r * 40 + c8) * 2;
            cpa16(sb + off,          AH + (size_t)(row0 + r) * K + k0 + c8);
            cpa16(sb + 10240 + off,  AL + (size_t)(row0 + r) * K + k0 + c8);
            cpa16(sb + 20480 + off,  WH + (size_t)(col0 + r) * K + k0 + c8);
            cpa16(sb + 30720 + off,  WL + (size_t)(col0 + r) * K + k0 + c8);
        }
    };

    issue_loads(0, 0);
    asm volatile("cp.async.commit_group;" ::: "memory");

    for (int t = 0; t < ntiles; t++) {
        if (t + 1 < ntiles) {
            issue_loads((t + 1) & 1, t + 1);
            asm volatile("cp.async.commit_group;" ::: "memory");
            asm volatile("cp.async.wait_group 1;" ::: "memory");
        } else {
            asm volatile("cp.async.wait_group 0;" ::: "memory");
        }
        __syncthreads();
        const __nv_bfloat16* Ah = dsm + (size_t)(t & 1) * 20480;
        const __nv_bfloat16* Al = Ah + 5120;
        const __nv_bfloat16* Wh = Ah + 10240;
        const __nv_bfloat16* Wl = Ah + 15360;
#pragma unroll
        for (int ks = 0; ks < 32; ks += 16) {
            uint32_t ah[4][4], al[4][4], bh[4][2], bl[4][2];
#pragma unroll
            for (int mi = 0; mi < 4; mi++) {
                int r = wm*64 + mi*16 + g;
                ah[mi][0] = *reinterpret_cast<const uint32_t*>(&Ah[(r  )*40 + ks + 2*q    ]);
                ah[mi][1] = *reinterpret_cast<const uint32_t*>(&Ah[(r+8)*40 + ks + 2*q    ]);
                ah[mi][2] = *reinterpret_cast<const uint32_t*>(&Ah[(r  )*40 + ks + 2*q + 8]);
                ah[mi][3] = *reinterpret_cast<const uint32_t*>(&Ah[(r+8)*40 + ks + 2*q + 8]);
                al[mi][0] = *reinterpret_cast<const uint32_t*>(&Al[(r  )*40 + ks + 2*q    ]);
                al[mi][1] = *reinterpret_cast<const uint32_t*>(&Al[(r+8)*40 + ks + 2*q    ]);
                al[mi][2] = *reinterpret_cast<const uint32_t*>(&Al[(r  )*40 + ks + 2*q + 8]);
                al[mi][3] = *reinterpret_cast<const uint32_t*>(&Al[(r+8)*40 + ks + 2*q + 8]);
            }
#pragma unroll
            for (int ni = 0; ni < 4; ni++) {
                int c = wn*32 + ni*8 + g;
                bh[ni][0] = *reinterpret_cast<const uint32_t*>(&Wh[c*40 + ks + 2*q    ]);
                bh[ni][1] = *reinterpret_cast<const uint32_t*>(&Wh[c*40 + ks + 2*q + 8]);
                bl[ni][0] = *reinterpret_cast<const uint32_t*>(&Wl[c*40 + ks + 2*q    ]);
                bl[ni][1] = *reinterpret_cast<const uint32_t*>(&Wl[c*40 + ks + 2*q + 8]);
            }
#pragma unroll
            for (int mi = 0; mi < 4; mi++)
#pragma unroll
                for (int ni = 0; ni < 4; ni++) {
                    MMA_BF16(acc[mi][ni], ah[mi], bh[ni]);
                    MMA_BF16(acc[mi][ni], ah[mi], bl[ni]);
                    MMA_BF16(acc[mi][ni], al[mi], bh[ni]);
                }
        }
        __syncthreads();
    }

#pragma unroll
    for (int mi = 0; mi < 4; mi++) {
        int r = row0 + wm*64 + mi*16 + g;
#pragma unroll
        for (int ni = 0; ni < 4; ni++) {
            int c = col0 + wn*32 + ni*8 + 2*q;
            float b0 = 0.f, b1 = 0.f;
            if (bias) {
                if (c < N)     b0 = bias[c];
                if (c + 1 < N) b1 = bias[c+1];
            }
            if (c < N) {
                C[(size_t)r * ldc + c]     = acc[mi][ni][0] + b0;
                C[(size_t)(r+8) * ldc + c] = acc[mi][ni][2] + b0;
            }
            if (c + 1 < N) {
                C[(size_t)r * ldc + c + 1]     = acc[mi][ni][1] + b1;
                C[(size_t)(r+8) * ldc + c + 1] = acc[mi][ni][3] + b1;
            }
        }
    }
}

// ---------------- 3xTF32 GEMM v2: preconverted hi/lo, fused dual output (z-dim) ----------------
// A [M,K] tf32-hi/lo f32, W[z] [N,K] tf32-hi/lo f32. N % 128 == 0, K % 32 == 0.
// smem/stage: AH,AL,WH,WL each 128x36 f32 (18432 B) = 73728 B; x2 stages = 147456 B dynamic.
__global__ __launch_bounds__(256)
void hgemm_tf32v2(const float* __restrict__ AH, const float* __restrict__ AL,
                  const float* __restrict__ WH0, const float* __restrict__ WL0,
                  const float* __restrict__ WH1, const float* __restrict__ WL1,
                  const float* __restrict__ b0p, const float* __restrict__ b1p,
                  float* __restrict__ C0, float* __restrict__ C1,
                  int ldc, int N, int K)
{
    extern __shared__ __align__(16) float dsmf[];
    const float* WH = blockIdx.z ? WH1 : WH0;
    const float* WL = blockIdx.z ? WL1 : WL0;
    const float* bias = blockIdx.z ? b1p : b0p;
    float* C = blockIdx.z ? C1 : C0;

    const int tid  = threadIdx.x;
    const int warp = tid >> 5, lane = tid & 31;
    const int wm = warp >> 2, wn = warp & 3;
    const int row0 = blockIdx.y * 128, col0 = blockIdx.x * 128;
    const int g = lane >> 2, q = lane & 3;
    const uint32_t sbase = smem_u32(dsmf);
    const int ntiles = K >> 5;

    float acc[4][4][4];
#pragma unroll
    for (int a = 0; a < 4; a++)
#pragma unroll
        for (int b = 0; b < 4; b++)
#pragma unroll
            for (int c = 0; c < 4; c++) acc[a][b][c] = 0.f;

    auto issue_loads = [&](int stage, int t) {
        uint32_t sb = sbase + stage * 73728u;
        int k0 = t << 5;
        for (int i = tid; i < 1024; i += 256) {
            int r = i >> 3, c4 = (i & 7) << 2;
            uint32_t off = (uint32_t)(r * 36 + c4) * 4;
            cpa16(sb + off,          AH + (size_t)(row0 + r) * K + k0 + c4);
            cpa16(sb + 18432 + off,  AL + (size_t)(row0 + r) * K + k0 + c4);
            cpa16(sb + 36864 + off,  WH + (size_t)(col0 + r) * K + k0 + c4);
            cpa16(sb + 55296 + off,  WL + (size_t)(col0 + r) * K + k0 + c4);
        }
    };

    issue_loads(0, 0);
    asm volatile("cp.async.commit_group;" ::: "memory");

    for (int t = 0; t < ntiles; t++) {
        if (t + 1 < ntiles) {
            issue_loads((t + 1) & 1, t + 1);
            asm volatile("cp.async.commit_group;" ::: "memory");
            asm volatile("cp.async.wait_group 1;" ::: "memory");
        } else {
            asm volatile("cp.async.wait_group 0;" ::: "memory");
        }
        __syncthreads();
        const float* Ah = dsmf + (size_t)(t & 1) * 18432;
        const float* Al = Ah + 4608;
        const float* Wh = Ah + 9216;
        const float* Wl = Ah + 13824;
#pragma unroll
        for (int ks = 0; ks < 32; ks += 8) {
            uint32_t ah[4][4], al[4][4], bh[4][2], bl[4][2];
#pragma unroll
            for (int mi = 0; mi < 4; mi++) {
                int r = wm*64 + mi*16 + g;
                ah[mi][0] = __float_as_uint(Ah[(r  )*36 + ks + q    ]);
                ah[mi][1] = __float_as_uint(Ah[(r+8)*36 + ks + q    ]);
                ah[mi][2] = __float_as_uint(Ah[(r  )*36 + ks + q + 4]);
                ah[mi][3] = __float_as_uint(Ah[(r+8)*36 + ks + q + 4]);
                al[mi][0] = __float_as_uint(Al[(r  )*36 + ks + q    ]);
                al[mi][1] = __float_as_uint(Al[(r+8)*36 + ks + q    ]);
                al[mi][2] = __float_as_uint(Al[(r  )*36 + ks + q + 4]);
                al[mi][3] = __float_as_uint(Al[(r+8)*36 + ks + q + 4]);
            }
#pragma unroll
            for (int ni = 0; ni < 4; ni++) {
                int c = wn*32 + ni*8 + g;
                bh[ni][0] = __float_as_uint(Wh[c*36 + ks + q    ]);
                bh[ni][1] = __float_as_uint(Wh[c*36 + ks + q + 4]);
                bl[ni][0] = __float_as_uint(Wl[c*36 + ks + q    ]);
                bl[ni][1] = __float_as_uint(Wl[c*36 + ks + q + 4]);
            }
#pragma unroll
            for (int mi = 0; mi < 4; mi++)
#pragma unroll
                for (int ni = 0; ni < 4; ni++) {
                    MMA_TF32(acc[mi][ni], ah[mi], bh[ni]);
                    MMA_TF32(acc[mi][ni], ah[mi], bl[ni]);
                    MMA_TF32(acc[mi][ni], al[mi], bh[ni]);
                }
        }
        __syncthreads();
    }

#pragma unroll
    for (int mi = 0; mi < 4; mi++) {
        int r = row0 + wm*64 + mi*16 + g;
#pragma unroll
        for (int ni = 0; ni < 4; ni++) {
            int c = col0 + wn*32 + ni*8 + 2*q;
            float b0 = bias ? bias[c] : 0.f;
            float b1 = bias ? bias[c+1] : 0.f;
            C[(size_t)r * ldc + c]         = acc[mi][ni][0] + b0;
            C[(size_t)r * ldc + c + 1]     = acc[mi][ni][1] + b1;
            C[(size_t)(r+8) * ldc + c]     = acc[mi][ni][2] + b0;
            C[(size_t)(r+8) * ldc + c + 1] = acc[mi][ni][3] + b1;
        }
    }
}

// ---------------- encoder LSTM step v2: preconverted tf32 hi/lo, fused epilogue ----------------
// Tile 64(batch) x 64(cols), 128 threads. blockIdx.z = direction. h ping-pong hi/lo in gmem.
template<int H>
__global__ __launch_bounds__(128)
void lstm_tf32_step2(const float* __restrict__ xgA, const float* __restrict__ xgB, int rsXG,
                     const float* __restrict__ WHa, const float* __restrict__ WLa,
                     const float* __restrict__ WHb, const float* __restrict__ WLb,
                     const float* __restrict__ hinH0, const float* __restrict__ hinL0,
                     float* __restrict__ cA, float* __restrict__ cB,
                     float* __restrict__ houtH0, float* __restrict__ houtL0,
                     float* __restrict__ hexact0)
{
    const int dir = blockIdx.z;
    const float* xg   = dir ? xgB : xgA;
    const float* WHp  = dir ? WHb : WHa;
    const float* WLp  = dir ? WLb : WLa;
    const float* hinH = hinH0 + (size_t)dir * B_ * H;
    const float* hinL = hinL0 + (size_t)dir * B_ * H;
    float* cp     = dir ? cB : cA;
    float* houtH  = houtH0 + (size_t)dir * B_ * H;
    float* houtL  = houtL0 + (size_t)dir * B_ * H;
    float* hexact = hexact0 + (size_t)dir * B_ * H;

    extern __shared__ __align__(16) float esm[];
    const int tid  = threadIdx.x;
    const int warp = tid >> 5, lane = tid & 31;
    const int wm = warp >> 1, wn = warp & 1;
    const int g = lane >> 2, q = lane & 3;
    const int row0 = blockIdx.y * 64, col0 = blockIdx.x * 64;
    const uint32_t sb0 = smem_u32(esm);
    const int ntiles = H >> 5;

    float acc[2][4][4];
#pragma unroll
    for (int a = 0; a < 2; a++)
#pragma unroll
        for (int b = 0; b < 4; b++)
#pragma unroll
            for (int c = 0; c < 4; c++) acc[a][b][c] = 0.f;

    auto issue_loads = [&](int stage, int t) {
        uint32_t sb = sb0 + stage * 36864u;
        int k0 = t << 5;
        for (int i = tid; i < 512; i += 128) {
            int r = i >> 3, c4 = (i & 7) << 2;
            uint32_t off = (uint32_t)(r * 36 + c4) * 4;
            cpa16(sb + off,          hinH + (size_t)(row0 + r) * H + k0 + c4);
            cpa16(sb + 9216 + off,   hinL + (size_t)(row0 + r) * H + k0 + c4);
            cpa16(sb + 18432 + off,  WHp + (size_t)(col0 + r) * H + k0 + c4);
            cpa16(sb + 27648 + off,  WLp + (size_t)(col0 + r) * H + k0 + c4);
        }
    };

    issue_loads(0, 0);
    asm volatile("cp.async.commit_group;" ::: "memory");

    for (int t = 0; t < ntiles; t++) {
        if (t + 1 < ntiles) {
            issue_loads((t + 1) & 1, t + 1);
            asm volatile("cp.async.commit_group;" ::: "memory");
            asm volatile("cp.async.wait_group 1;" ::: "memory");
        } else {
            asm volatile("cp.async.wait_group 0;" ::: "memory");
        }
        __syncthreads();
        const float* Ah = esm + (size_t)(t & 1) * 9216;
        const float* Al = Ah + 2304;
        const float* Wh = Ah + 4608;
        const float* Wl = Ah + 6912;
#pragma unroll
        for (int ks = 0; ks < 32; ks += 8) {
            uint32_t ah[2][4], al[2][4], bh[4][2], bl[4][2];
#pragma unroll
            for (int mi = 0; mi < 2; mi++) {
                int r = wm*32 + mi*16 + g;
                ah[mi][0] = __float_as_uint(Ah[(r  )*36 + ks + q    ]);
                ah[mi][1] = __float_as_uint(Ah[(r+8)*36 + ks + q    ]);
                ah[mi][2] = __float_as_uint(Ah[(r  )*36 + ks + q + 4]);
                ah[mi][3] = __float_as_uint(Ah[(r+8)*36 + ks + q + 4]);
                al[mi][0] = __float_as_uint(Al[(r  )*36 + ks + q    ]);
                al[mi][1] = __float_as_uint(Al[(r+8)*36 + ks + q    ]);
                al[mi][2] = __float_as_uint(Al[(r  )*36 + ks + q + 4]);
                al[mi][3] = __float_as_uint(Al[(r+8)*36 + ks + q + 4]);
            }
#pragma unroll
            for (int ni = 0; ni < 4; ni++) {
                int c = wn*32 + ni*8 + g;
                bh[ni][0] = __float_as_uint(Wh[c*36 + ks + q    ]);
                bh[ni][1] = __float_as_uint(Wh[c*36 + ks + q + 4]);
                bl[ni][0] = __float_as_uint(Wl[c*36 + ks + q    ]);
                bl[ni][1] = __float_as_uint(Wl[c*36 + ks + q + 4]);
            }
#pragma unroll
            for (int mi = 0; mi < 2; mi++)
#pragma unroll
                for (int ni = 0; ni < 4; ni++) {
                    MMA_TF32(acc[mi][ni], ah[mi], bh[ni]);
                    MMA_TF32(acc[mi][ni], ah[mi], bl[ni]);
                    MMA_TF32(acc[mi][ni], al[mi], bh[ni]);
                }
        }
        __syncthreads();
    }

#pragma unroll
    for (int mi = 0; mi < 2; mi++) {
#pragma unroll
        for (int rr = 0; rr < 2; rr++) {
            int b = row0 + wm*32 + mi*16 + g + rr*8;
#pragma unroll
            for (int ni = 0; ni < 4; ni++) {
                int c = col0 + wn*32 + ni*8 + 2*q;
                float v0 = acc[mi][ni][rr*2 + 0] + xg[(size_t)b * rsXG + c];
                float v1 = acc[mi][ni][rr*2 + 1] + xg[(size_t)b * rsXG + c + 1];
                float p0 = __shfl_xor_sync(0xffffffffu, v0, 1);
                float p1 = __shfl_xor_sync(0xffffffffu, v1, 1);
                if (!(lane & 1)) {
                    int j = c >> 2;
                    size_t ci = (size_t)b * H + j;
                    float cc = sigf(v1) * cp[ci] + sigf(v0) * tanhf(p0);
                    cp[ci] = cc;
                    float hv = sigf(p1) * tanhf(cc);
                    hexact[ci] = hv;
                    uint32_t hh = f2tf32(hv);
                    houtH[ci] = __uint_as_float(hh);
                    houtL[ci] = __uint_as_float(f2tf32(hv - __uint_as_float(hh)));
                }
            }
        }
    }
}

// ---------------- decoder LSTM step on tensor cores (bf16 split, fused epilogue) ----------------
__global__ __launch_bounds__(128)
void lstm_tc_step(const __nv_bfloat16* __restrict__ AH, const __nv_bfloat16* __restrict__ AL, int rsA,
                  const __nv_bfloat16* __restrict__ WH, const __nv_bfloat16* __restrict__ WL,
                  const float* __restrict__ xg, int rsXG,
                  float* __restrict__ cp,
                  float* __restrict__ hout, int rsH,
                  __nv_bfloat16* __restrict__ hHo, __nv_bfloat16* __restrict__ hLo)
{
    __shared__ __align__(16) __nv_bfloat16 sm[2 * 4 * 2560];
    const int tid  = threadIdx.x;
    const int warp = tid >> 5, lane = tid & 31;
    const int wm = warp >> 1, wn = warp & 1;
    const int g = lane >> 2, q = lane & 3;
    const int row0 = blockIdx.y * 64, col0 = blockIdx.x * 64;
    const uint32_t sb0 = smem_u32(sm);
    const int ntiles = DNH >> 5;

    float acc[2][4][4];
#pragma unroll
    for (int a = 0; a < 2; a++)
#pragma unroll
        for (int b = 0; b < 4; b++)
#pragma unroll
            for (int c = 0; c < 4; c++) acc[a][b][c] = 0.f;

    auto issue_loads = [&](int stage, int t) {
        uint32_t sb = sb0 + stage * 20480u;
        int k0 = t << 5;
        for (int i = tid; i < 256; i += 128) {
            int r = i >> 2, c8 = (i & 3) << 3;
            uint32_t off = (uint32_t)(r * 40 + c8) * 2;
            cpa16(sb + off,          AH + (size_t)(row0 + r) * rsA + k0 + c8);
            cpa16(sb + 5120 + off,   AL + (size_t)(row0 + r) * rsA + k0 + c8);
            cpa16(sb + 10240 + off,  WH + (size_t)(col0 + r) * DNH + k0 + c8);
            cpa16(sb + 15360 + off,  WL + (size_t)(col0 + r) * DNH + k0 + c8);
        }
    };

    issue_loads(0, 0);
    asm volatile("cp.async.commit_group;" ::: "memory");

    for (int t = 0; t < ntiles; t++) {
        if (t + 1 < ntiles) {
            issue_loads((t + 1) & 1, t + 1);
            asm volatile("cp.async.commit_group;" ::: "memory");
            asm volatile("cp.async.wait_group 1;" ::: "memory");
        } else {
            asm volatile("cp.async.wait_group 0;" ::: "memory");
        }
        __syncthreads();
        const __nv_bfloat16* Ah = sm + (size_t)(t & 1) * 10240;
        const __nv_bfloat16* Al = Ah + 2560;
        const __nv_bfloat16* Wh = Ah + 5120;
        const __nv_bfloat16* Wl = Ah + 7680;
#pragma unroll
        for (int ks = 0; ks < 32; ks += 16) {
            uint32_t ah[2][4], al[2][4], bh[4][2], bl[4][2];
#pragma unroll
            for (int mi = 0; mi < 2; mi++) {
                int r = wm*32 + mi*16 + g;
                ah[mi][0] = *reinterpret_cast<const uint32_t*>(&Ah[(r  )*40 + ks + 2*q    ]);
                ah[mi][1] = *reinterpret_cast<const uint32_t*>(&Ah[(r+8)*40 + ks + 2*q    ]);
                ah[mi][2] = *reinterpret_cast<const uint32_t*>(&Ah[(r  )*40 + ks + 2*q + 8]);
                ah[mi][3] = *reinterpret_cast<const uint32_t*>(&Ah[(r+8)*40 + ks + 2*q + 8]);
                al[mi][0] = *reinterpret_cast<const uint32_t*>(&Al[(r  )*40 + ks + 2*q    ]);
                al[mi][1] = *reinterpret_cast<const uint32_t*>(&Al[(r+8)*40 + ks + 2*q    ]);
                al[mi][2] = *reinterpret_cast<const uint32_t*>(&Al[(r  )*40 + ks + 2*q + 8]);
                al[mi][3] = *reinterpret_cast<const uint32_t*>(&Al[(r+8)*40 + ks + 2*q + 8]);
            }
#pragma unroll
            for (int ni = 0; ni < 4; ni++) {
                int c = wn*32 + ni*8 + g;
                bh[ni][0] = *reinterpret_cast<const uint32_t*>(&Wh[c*40 + ks + 2*q    ]);
                bh[ni][1] = *reinterpret_cast<const uint32_t*>(&Wh[c*40 + ks + 2*q + 8]);
                bl[ni][0] = *reinterpret_cast<const uint32_t*>(&Wl[c*40 + ks + 2*q    ]);
                bl[ni][1] = *reinterpret_cast<const uint32_t*>(&Wl[c*40 + ks + 2*q + 8]);
            }
#pragma unroll
            for (int mi = 0; mi < 2; mi++)
#pragma unroll
                for (int ni = 0; ni < 4; ni++) {
                    MMA_BF16(acc[mi][ni], ah[mi], bh[ni]);
                    MMA_BF16(acc[mi][ni], ah[mi], bl[ni]);
                    MMA_BF16(acc[mi][ni], al[mi], bh[ni]);
                }
        }
        __syncthreads();
    }

#pragma unroll
    for (int mi = 0; mi < 2; mi++) {
#pragma unroll
        for (int rr = 0; rr < 2; rr++) {
            int b = row0 + wm*32 + mi*16 + g + rr*8;
#pragma unroll
            for (int ni = 0; ni < 4; ni++) {
                int c = col0 + wn*32 + ni*8 + 2*q;
                float v0 = acc[mi][ni][rr*2 + 0] + xg[(size_t)b * rsXG + c];
                float v1 = acc[mi][ni][rr*2 + 1] + xg[(size_t)b * rsXG + c + 1];
                float p0 = __shfl_xor_sync(0xffffffffu, v0, 1);
                float p1 = __shfl_xor_sync(0xffffffffu, v1, 1);
                if (!(lane & 1)) {
                    int j = c >> 2;
                    size_t ci = (size_t)b * DNH + j;
                    float cc = sigf(v1) * cp[ci] + sigf(v0) * tanhf(p0);
                    cp[ci] = cc;
                    float hv = sigf(p1) * tanhf(cc);
                    size_t ho = (size_t)b * rsH + j;
                    hout[ho] = hv;
                    __nv_bfloat16 hh = __float2bfloat16_rn(hv);
                    hHo[ho] = hh;
                    hLo[ho] = __float2bfloat16_rn(hv - __bfloat162float(hh));
                }
            }
        }
    }
}

// ---------------- elementwise / small kernels ----------------
__global__ void embed_kernel(const int* __restrict__ x, const float* __restrict__ emb,
                             float* __restrict__ out)
{
    size_t idx = (size_t)blockIdx.x * blockDim.x + threadIdx.x;
    if (idx >= (size_t)B_ * T_ * NI_) return;
    int i = (int)(idx % NI_), bt = (int)(idx / NI_);
    out[idx] = emb[(size_t)x[bt] * NI_ + i];
}

__global__ void demb_split(const int* __restrict__ x, const float* __restrict__ emb,
                           const float* __restrict__ suffix,
                           __nv_bfloat16* __restrict__ H, __nv_bfloat16* __restrict__ L)
{
    size_t idx = (size_t)blockIdx.x * blockDim.x + threadIdx.x;
    if (idx >= (size_t)B_ * T_ * NI_) return;
    int i = (int)(idx % NI_), bt = (int)(idx / NI_);
    int b = bt / T_;
    float v = emb[(size_t)x[bt] * NI_ + i] + suffix[(size_t)b * NI_ + i];
    __nv_bfloat16 h = __float2bfloat16_rn(v);
    H[idx] = h;
    L[idx] = __float2bfloat16_rn(v - __bfloat162float(h));
}

__global__ void concat_fhs(const float* __restrict__ hf, const float* __restrict__ hb,
                           float* __restrict__ fhs)
{
    int idx = blockIdx.x * blockDim.x + threadIdx.x;
    if (idx >= B_ * 2 * ENH) return;
    int b = idx / (2 * ENH), j = idx % (2 * ENH);
    fhs[idx] = (j < ENH) ? hf[(size_t)b * ENH + j] : hb[(size_t)b * ENH + (j - ENH)];
}

__global__ void kl_kernel(const float* __restrict__ muvar, float* __restrict__ out_kl)
{
    int b = threadIdx.x;
    if (b >= B_) return;
    float s = 0.f;
    const float* row = muvar + (size_t)b * 2 * NZ_;
    for (int j = 0; j < NZ_; j++) {
        float mu = row[j], lv = row[NZ_ + j];
        s += mu * mu + expf(lv) - lv - 1.f;
    }
    out_kl[b] = 0.5f * s;
}

__global__ void dec_init(const float* __restrict__ root, float* __restrict__ h0,
                         float* __restrict__ c0,
                         __nv_bfloat16* __restrict__ hH, __nv_bfloat16* __restrict__ hL)
{
    int idx = blockIdx.x * blockDim.x + threadIdx.x;
    if (idx >= B_ * DNH) return;
    float r = root[idx];
    float hv = tanhf(r);
    h0[idx] = hv;
    c0[idx] = r;
    __nv_bfloat16 hh = __float2bfloat16_rn(hv);
    hH[idx] = hh;
    hL[idx] = __float2bfloat16_rn(hv - __bfloat162float(hh));
}

__global__ void vq_kernel(const float* __restrict__ fhs, const float* __restrict__ cb,
                          int* __restrict__ inds, float* __restrict__ q,
                          float* __restrict__ vqp)
{
    const int bn = blockIdx.x;
    const int b = bn / ND_, n = bn % ND_;
    __shared__ __align__(16) float lat[D_];
    __shared__ float svals[256];
    __shared__ int   sidx[256];
    const float* latg = fhs + (size_t)b * (ND_ * D_) + (size_t)n * D_;
    for (int d = threadIdx.x; d < D_; d += 256) lat[d] = latg[d];
    __syncthreads();
    float best = INFINITY; int bidx = K_;
    const float* cbn = cb + (size_t)n * K_ * D_;
    for (int k = threadIdx.x; k < K_; k += 256) {
        const float4* ck = reinterpret_cast<const float4*>(cbn + (size_t)k * D_);
        float t1 = 0.f, t2 = 0.f;
#pragma unroll
        for (int d4 = 0; d4 < D_ / 4; d4++) {
            float4 cv = ck[d4];
            const float4 lv = *reinterpret_cast<const float4*>(&lat[d4 * 4]);
            t1 = fmaf(cv.x, cv.x, t1); t2 = fmaf(cv.x, lv.x, t2);
            t1 = fmaf(cv.y, cv.y, t1); t2 = fmaf(cv.y, lv.y, t2);
            t1 = fmaf(cv.z, cv.z, t1); t2 = fmaf(cv.z, lv.z, t2);
            t1 = fmaf(cv.w, cv.w, t1); t2 = fmaf(cv.w, lv.w, t2);
        }
        float dist = t1 - 2.f * t2;
        if (dist < best || (dist == best && k < bidx)) { best = dist; bidx = k; }
    }
    svals[threadIdx.x] = best; sidx[threadIdx.x] = bidx;
    __syncthreads();
    for (int off = 128; off > 0; off >>= 1) {
        if (threadIdx.x < off) {
            float v = svals[threadIdx.x + off]; int i2 = sidx[threadIdx.x + off];
            if (v < svals[threadIdx.x] || (v == svals[threadIdx.x] && i2 < sidx[threadIdx.x])) {
                svals[threadIdx.x] = v; sidx[threadIdx.x] = i2;
            }
        }
        __syncthreads();
    }
    const int kmin = sidx[0];
    if (threadIdx.x == 0) inds[bn] = kmin;
    __syncthreads();
    const float* ck = cbn + (size_t)kmin * D_;
    float part = 0.f;
    for (int d = threadIdx.x; d < D_; d += 256) {
        float qv = ck[d], lv = lat[d];
        float diff = qv - lv;
        q[(size_t)bn * D_ + d] = lv + diff;
        part += diff * diff;
    }
    svals[threadIdx.x] = part;
    __syncthreads();
    for (int off = 128; off > 0; off >>= 1) {
        if (threadIdx.x < off) svals[threadIdx.x] += svals[threadIdx.x + off];
        __syncthreads();
    }
    if (threadIdx.x == 0) vqp[bn] = svals[0] / (float)D_;
}

__global__ void vq_finish(const float* __restrict__ vqp, const int* __restrict__ inds,
                          float* __restrict__ out_vq, float* __restrict__ out_inds)
{
    int b = threadIdx.x;
    if (b >= B_) return;
    float s = 0.f;
#pragma unroll
    for (int n = 0; n < ND_; n++) s += vqp[b * ND_ + n];
    out_vq[b] = 1.25f * s;
#pragma unroll
    for (int n = 0; n < ND_; n++)
        out_inds[b * ND_ + n] = (float)inds[b * ND_ + n];
}

// ---------------- launch helpers ----------------
static inline void gemm_small(const float* A, int lda, const float* W, int ldw,
                              const float* bias, float* C, int ldc, int M, int N, int K)
{
    dim3 grid((N + 63) / 64, M / 32);
    gemm_k<32, 64, 16, 4, 4><<<grid, 128>>>(A, lda, W, ldw, bias, C, ldc, N, K);
}

extern "C" void kernel_launch(void* const* d_in, const int* in_sizes, int n_in,
                              void* d_out, int out_size)
{
    (void)in_sizes; (void)n_in; (void)out_size;
    const int*   x         = (const int*)  d_in[0];
    const float* enc_embed = (const float*)d_in[1];
    const float* enc_Wih_f = (const float*)d_in[2];
    const float* enc_Whh_f = (const float*)d_in[3];
    const float* enc_b_f   = (const float*)d_in[4];
    const float* enc_Wih_b = (const float*)d_in[5];
    const float* enc_Whh_b = (const float*)d_in[6];
    const float* enc_b_b   = (const float*)d_in[7];
    const float* enc_lin   = (const float*)d_in[8];
    const float* z2dec_W   = (const float*)d_in[9];
    const float* z2dec_b   = (const float*)d_in[10];
    const float* codebooks = (const float*)d_in[11];
    const float* suffix_W  = (const float*)d_in[12];
    const float* dec_embed = (const float*)d_in[13];
    const float* dec_Wih   = (const float*)d_in[14];
    const float* dec_Whh   = (const float*)d_in[15];
    const float* dec_b     = (const float*)d_in[16];
    const float* pred_W    = (const float*)d_in[17];

    float* out      = (float*)d_out;
    float* out_log  = out;
    float* out_vq   = out + (size_t)LOGITS_ELEMS;
    float* out_kl   = out_vq + B_;
    float* out_inds = out_kl + B_;

    float *we,*weH,*weL,*xgf,*xgb,*encA,*ehH,*ehL,*ehX,*fhs,*muvar,*root,*q,*vqp,*suffix;
    float *xgd,*hd0,*cd,*decout;
    float *WfH,*WfL,*WbH,*WbL,*WhfH,*WhfL,*WhbH,*WhbL,*bfP,*bbP,*bdP;
    __nv_bfloat16 *dembH,*dembL,*WdH,*WdL,*WhdH,*WhdL,*hd0H,*hd0L,*doH,*doL,*pwH,*pwL;
    int* inds;
    cudaGetSymbolAddress((void**)&we,    g_we);
    cudaGetSymbolAddress((void**)&weH,   g_weH);
    cudaGetSymbolAddress((void**)&weL,   g_weL);
    cudaGetSymbolAddress((void**)&xgf,   g_xgf);
    cudaGetSymbolAddress((void**)&xgb,   g_xgb);
    cudaGetSymbolAddress((void**)&encA,  g_encA);
    cudaGetSymbolAddress((void**)&ehH,   g_ehH);
    cudaGetSymbolAddress((void**)&ehL,   g_ehL);
    cudaGetSymbolAddress((void**)&ehX,   g_ehX);
    cudaGetSymbolAddress((void**)&fhs,   g_fhs);
    cudaGetSymbolAddress((void**)&muvar, g_muvar);
    cudaGetSymbolAddress((void**)&root,  g_root);
    cudaGetSymbolAddress((void**)&inds,  g_inds);
    cudaGetSymbolAddress((void**)&q,     g_q);
    cudaGetSymbolAddress((void**)&vqp,   g_vqp);
    cudaGetSymbolAddress((void**)&suffix,g_suffix);
    cudaGetSymbolAddress((void**)&xgd,   g_xgd);
    cudaGetSymbolAddress((void**)&hd0,   g_hd0);
    cudaGetSymbolAddress((void**)&cd,    g_cd);
    cudaGetSymbolAddress((void**)&decout,g_decout);
    cudaGetSymbolAddress((void**)&WfH,   g_WfH);
    cudaGetSymbolAddress((void**)&WfL,   g_WfL);
    cudaGetSymbolAddress((void**)&WbH,   g_WbH);
    cudaGetSymbolAddress((void**)&WbL,   g_WbL);
    cudaGetSymbolAddress((void**)&WhfH,  g_WhfH);
    cudaGetSymbolAddress((void**)&WhfL,  g_WhfL);
    cudaGetSymbolAddress((void**)&WhbH,  g_WhbH);
    cudaGetSymbolAddress((void**)&WhbL,  g_WhbL);
    cudaGetSymbolAddress((void**)&bfP,   g_bfP);
    cudaGetSymbolAddress((void**)&bbP,   g_bbP);
    cudaGetSymbolAddress((void**)&bdP,   g_bdP);
    cudaGetSymbolAddress((void**)&dembH, g_dembH);
    cudaGetSymbolAddress((void**)&dembL, g_dembL);
    cudaGetSymbolAddress((void**)&WdH,   g_WdH);
    cudaGetSymbolAddress((void**)&WdL,   g_WdL);
    cudaGetSymbolAddress((void**)&WhdH,  g_WhdH);
    cudaGetSymbolAddress((void**)&WhdL,  g_WhdL);
    cudaGetSymbolAddress((void**)&hd0H,  g_hd0H);
    cudaGetSymbolAddress((void**)&hd0L,  g_hd0L);
    cudaGetSymbolAddress((void**)&doH,   g_doH);
    cudaGetSymbolAddress((void**)&doL,   g_doL);
    cudaGetSymbolAddress((void**)&pwH,   g_pwH);
    cudaGetSymbolAddress((void**)&pwL,   g_pwL);

    cudaFuncSetAttribute(hgemm2, cudaFuncAttributeMaxDynamicSharedMemorySize, 81920);
    cudaFuncSetAttribute(hgemm_tf32v2, cudaFuncAttributeMaxDynamicSharedMemorySize, 147456);
    cudaFuncSetAttribute(lstm_tf32_step2<ENH>, cudaFuncAttributeMaxDynamicSharedMemorySize, 73728);

    float* cf = encA + (size_t)B_ * ENH;
    float* cb = encA + (size_t)2 * B_ * ENH;

    const int EW = 256;

    // 0) prep: permutes + splits
    perm_w_split_tf32<<<(4*ENH*NI_ + EW-1)/EW, EW>>>(enc_Wih_f, WfH, WfL, ENH, NI_);
    perm_w_split_tf32<<<(4*ENH*NI_ + EW-1)/EW, EW>>>(enc_Wih_b, WbH, WbL, ENH, NI_);
    perm_w_split_tf32<<<(4*ENH*ENH + EW-1)/EW, EW>>>(enc_Whh_f, WhfH, WhfL, ENH, ENH);
    perm_w_split_tf32<<<(4*ENH*ENH + EW-1)/EW, EW>>>(enc_Whh_b, WhbH, WhbL, ENH, ENH);
    perm_w_split<<<(4*DNH*DNH + EW-1)/EW, EW>>>(dec_Whh, WhdH, WhdL, DNH, DNH);
    perm_w_split<<<(4*DNH*NI_ + EW-1)/EW, EW>>>(dec_Wih, WdH, WdL, DNH, NI_);
    perm_b<<<(4*ENH + EW-1)/EW, EW>>>(enc_b_f, bfP, ENH);
    perm_b<<<(4*ENH + EW-1)/EW, EW>>>(enc_b_b, bbP, ENH);
    perm_b<<<(4*DNH + EW-1)/EW, EW>>>(dec_b,   bdP, DNH);
    split_pad<<<((size_t)VPAD*DNH + EW-1)/EW, EW>>>(pred_W, pwH, pwL, V_, VPAD, DNH);

    // 1) encoder embedding + tf32 split of we + fused xgf/xgb GEMM
    embed_kernel<<<(B_ * T_ * NI_ + EW - 1) / EW, EW>>>(x, enc_embed, we);
    split_tf32<<<((size_t)B_*T_*NI_ + EW-1)/EW, EW>>>(we, weH, weL, (size_t)B_*T_*NI_);
    {
        dim3 gx(4 * ENH / 128, (B_ * T_) / 128, 2);
        hgemm_tf32v2<<<gx, 256, 147456>>>(weH, weL, WfH, WfL, WbH, WbL,
                                          bfP, bbP, xgf, xgb, 4 * ENH, 4 * ENH, NI_);
    }
    cudaMemsetAsync(encA, 0, sizeof(float) * 4 * B_ * ENH, 0);
    cudaMemsetAsync(ehH, 0, sizeof(float) * 2 * 2 * B_ * ENH, 0);
    cudaMemsetAsync(ehL, 0, sizeof(float) * 2 * 2 * B_ * ENH, 0);

    // 2) encoder recurrence (tf32 preconverted hi/lo, fused gates; h ping-pong)
    {
        dim3 grid(4 * ENH / 64, B_ / 64, 2);
        const size_t bufStride = (size_t)2 * B_ * ENH;
        for (int s = 0; s < T_; s++) {
            int bi = s & 1, bo = bi ^ 1;
            lstm_tf32_step2<ENH><<<grid, 128, 73728>>>(
                xgf + (size_t)s * 4 * ENH, xgb + (size_t)(T_ - 1 - s) * 4 * ENH, T_ * 4 * ENH,
                WhfH, WhfL, WhbH, WhbL,
                ehH + bi * bufStride, ehL + bi * bufStride,
                cf, cb,
                ehH + bo * bufStride, ehL + bo * bufStride,
                ehX);
        }
    }
    concat_fhs<<<(B_ * 2 * ENH + EW - 1) / EW, EW>>>(ehX, ehX + (size_t)B_ * ENH, fhs);

    gemm_small(fhs, 2 * ENH, enc_lin, 2 * ENH, nullptr, muvar, 2 * NZ_, B_, 2 * NZ_, 2 * ENH);
    kl_kernel<<<1, B_>>>(muvar, out_kl);
    gemm_small(muvar, 2 * NZ_, z2dec_W, NZ_, z2dec_b, root, DNH, B_, DNH, NZ_);

    vq_kernel<<<B_ * ND_, 256>>>(fhs, codebooks, inds, q, vqp);
    vq_finish<<<1, B_>>>(vqp, inds, out_vq, out_inds);

    gemm_small(q, ND_ * D_, suffix_W, ND_ * D_, nullptr, suffix, NI_, B_, NI_, ND_ * D_);
    demb_split<<<(B_ * T_ * NI_ + EW - 1) / EW, EW>>>(x, dec_embed, suffix, dembH, dembL);

    // decoder input gates: preconverted split-bf16 tensor GEMM
    {
        dim3 grid(4 * DNH / 128, (B_ * T_) / 128);
        hgemm2<<<grid, 256, 81920>>>(dembH, dembL, WdH, WdL, bdP, xgd, 4 * DNH, 4 * DNH, NI_);
    }

    dec_init<<<(B_ * DNH + EW - 1) / EW, EW>>>(root, hd0, cd, hd0H, hd0L);

    // decoder recurrence: tensor-core fused step (64x64 tiles, 128 blocks)
    {
        dim3 grid(4 * DNH / 64, B_ / 64);
        for (int s = 0; s < T_; s++) {
            const __nv_bfloat16* aH = (s == 0) ? hd0H : (doH + (size_t)(s - 1) * DNH);
            const __nv_bfloat16* aL = (s == 0) ? hd0L : (doL + (size_t)(s - 1) * DNH);
            int rsA                 = (s == 0) ? DNH : (T_ * DNH);
            lstm_tc_step<<<grid, 128>>>(
                aH, aL, rsA,
                WhdH, WhdL,
                xgd + (size_t)s * 4 * DNH, T_ * 4 * DNH,
                cd,
                decout + (size_t)s * DNH, T_ * DNH,
                doH + (size_t)s * DNH, doL + (size_t)s * DNH);
        }
    }

    // logits: preconverted split-bf16 tensor GEMM (W padded to VPAD rows)
    {
        dim3 grid(VPAD / 128, (B_ * T_) / 128);
        hgemm2<<<grid, 256, 81920>>>(doH, doL, pwH, pwL, nullptr, out_log, V_, V_, DNH);
    }
}